// round 10
// baseline (speedup 1.0000x reference)
#include <cuda_runtime.h>
#include <math.h>

#define T_ 64
#define M_ 256
#define K_ 6
#define B_ 256
#define H_ 256
#define L_ 128
#define V_ 780
#define E_ 16384
#define DC_ 383          // wcls cols = H+L-1
#define DS_ 638          // ucls cols = 2H+L-2
#define NROWS (E_ + B_)  // msg rows + root rows
#define NB_ 64           // scan blocks (all resident)

// ------------------------- device scratch --------------------------------
__device__ __align__(16) float  g_hbuf [(E_ + 1) * H_];
__device__ __align__(16) float  g_h1buf[(E_ + 1) * H_];
__device__ __align__(16) float  g_W1T  [512 * H_];      // for embW1 prep
__device__ __align__(16) float  g_W1P  [H_ * H_];       // packed: [(k>>2)*256+col]*4+(k&3)
__device__ __align__(16) float  g_W0P  [H_ * H_];       // packed W0^T
__device__ __align__(16) float  g_embW1[V_ * H_];       // emb_spatial @ W1^T_spatial
__device__ __align__(16) float  g_GtP  [256 * V_];      // packed rows 0..255
__device__ __align__(16) float  g_GtC  [128 * V_];      // packed ctx rows 256..383
__device__ __align__(16) float  g_ctxG [B_ * V_];       // ctx_spatial(b) . Gt[256..382]
__device__ double g_acc[6];
__device__ volatile int g_bar[T_];

// ------------------------- helpers ---------------------------------------
__device__ __forceinline__ float blockReduceSum(float v, float* sh) {
    __syncthreads();
    #pragma unroll
    for (int o = 16; o > 0; o >>= 1) v += __shfl_down_sync(0xffffffffu, v, o);
    int tid = threadIdx.x;
    if ((tid & 31) == 0) sh[tid >> 5] = v;
    __syncthreads();
    if (tid < 32) {
        int nw = (blockDim.x + 31) >> 5;
        v = (tid < nw) ? sh[tid] : 0.f;
        #pragma unroll
        for (int o = 16; o > 0; o >>= 1) v += __shfl_down_sync(0xffffffffu, v, o);
        if (tid == 0) sh[0] = v;
    }
    __syncthreads();
    return sh[0];
}

__device__ __forceinline__ float gt_val(int i, int v, const float* wcls) {
    if (i == 0)  return -wcls[v * DC_];
    if (i < DC_) return wcls[v * DC_ + i];
    return 0.f;
}

// ------------------------- prep -------------------------------------------
__global__ void prep_misc(const float* __restrict__ W0,
                          const float* __restrict__ W1,
                          const float* __restrict__ wcls) {
    if (blockIdx.x == 0 && threadIdx.x < T_) g_bar[threadIdx.x] = 0;
    const int n1 = 512 * H_;        // W1T
    const int n2 = H_ * H_;         // W1P
    const int n3 = H_ * H_;         // W0P
    const int n4 = 256 * V_;        // GtP
    const int n5 = 128 * V_;        // GtC
    for (int idx = blockIdx.x * blockDim.x + threadIdx.x;
         idx < n1 + n2 + n3 + n4 + n5; idx += gridDim.x * blockDim.x) {
        if (idx < n1) {
            int i = idx >> 8, j = idx & 255;
            g_W1T[idx] = (i < 511) ? W1[j * 511 + i] : 0.f;
        } else if (idx < n1 + n2) {
            int k = idx - n1;
            int i = k >> 8, j = k & 255;
            float val = (i == 0) ? W1[j * 511] : W1[j * 511 + 255 + i];
            g_W1P[((i >> 2) << 10) + (j << 2) + (i & 3)] = val;
        } else if (idx < n1 + n2 + n3) {
            int k = idx - n1 - n2;
            int i = k >> 8, j = k & 255;
            g_W0P[((i >> 2) << 10) + (j << 2) + (i & 3)] = W0[j * H_ + i];
        } else if (idx < n1 + n2 + n3 + n4) {
            int k = idx - n1 - n2 - n3;
            int i = k / V_, v = k % V_;
            g_GtP[(((i >> 2) * V_ + v) << 2) + (i & 3)] = gt_val(i, v, wcls);
        } else {
            int k = idx - n1 - n2 - n3 - n4;
            int j = k / V_, v = k % V_;
            g_GtC[(((j >> 2) * V_ + v) << 2) + (j & 3)] = gt_val(256 + j, v, wcls);
        }
    }
}

__global__ void prep_pad(const float* __restrict__ W0,
                         const float* __restrict__ b0,
                         const float* __restrict__ s0p) {
    __shared__ float red[32];
    __shared__ float ybc;
    int tid = threadIdx.x;
    if (tid < 6) g_acc[tid] = 0.0;
    g_hbuf[E_ * H_ + tid] = (tid == 0) ? 1.f : 0.f;
    float y = W0[tid * H_] + b0[tid];
    if (tid == 0) ybc = y;
    float ss = blockReduceSum((tid == 0) ? 0.f : y * y, red);
    float time = expf(s0p[0]) / (1.f + expf(-ybc)) + 1.1f;
    float sc = sqrtf((time * time - 1.f) / fmaxf(ss, 1e-8f));
    g_h1buf[E_ * H_ + tid] = (tid == 0) ? time : y * sc;
}

// embW1[v][j] = sum_{i=1..255} emb[v][i] * W1T[i][j]
__global__ void prep_embW1(const float* __restrict__ emb) {
    __shared__ float es[16][256];
    int v0 = blockIdx.x * 16, tid = threadIdx.x;
    for (int i = tid; i < 16 * 256; i += 256) {
        int r = i >> 8, c = i & 255;
        es[r][c] = (v0 + r < V_) ? emb[(v0 + r) * H_ + c] : 0.f;
    }
    __syncthreads();
    float acc[16];
    #pragma unroll
    for (int r = 0; r < 16; r++) acc[r] = 0.f;
    for (int i = 1; i < 256; i++) {
        float w = g_W1T[i * H_ + tid];
        #pragma unroll
        for (int r = 0; r < 16; r++) acc[r] += es[r][i] * w;
    }
    #pragma unroll
    for (int r = 0; r < 16; r++)
        if (v0 + r < V_) g_embW1[(v0 + r) * H_ + tid] = acc[r];
}

// ctxG: 8 b-rows per block, GtC shared across them
__global__ void prep_ctxG(const float* __restrict__ xtv) {
    __shared__ float4 cs[8][32];
    int b0 = blockIdx.x * 8, tid = threadIdx.x;
    for (int i = tid; i < 8 * 128; i += 256) {
        int bb = i >> 7, j = i & 127;
        ((float*)cs)[i] = (j < 127) ? xtv[(b0 + bb) * L_ + 1 + j] : 0.f;
    }
    __syncthreads();
    const float4* gc = (const float4*)g_GtC;
    for (int v = tid; v < V_; v += 256) {
        float acc[8];
        #pragma unroll
        for (int bb = 0; bb < 8; bb++) acc[bb] = 0.f;
        #pragma unroll 4
        for (int j4 = 0; j4 < 32; j4++) {
            float4 g = gc[j4 * V_ + v];
            #pragma unroll
            for (int bb = 0; bb < 8; bb++) {
                float4 c = cs[bb][j4];
                acc[bb] += g.x * c.x + g.y * c.y + g.z * c.z + g.w * c.w;
            }
        }
        #pragma unroll
        for (int bb = 0; bb < 8; bb++) g_ctxG[(b0 + bb) * V_ + v] = acc[bb];
    }
}

// ------------------------- persistent scan kernel -------------------------
// 64 blocks x 1024 threads. col = tid&255, q = tid>>8 (4-way K split,
// 4 rows/block, row q owned by quarter q in phase1/epilogues).
__global__ void __launch_bounds__(1024, 1) scan_kernel(
    const int*   __restrict__ wid,
    const int*   __restrict__ nhi,
    const float* __restrict__ nhw,
    const float* __restrict__ emb,
    const float* __restrict__ b0,
    const float* __restrict__ s0p,
    const float* __restrict__ b1,
    const float* __restrict__ s1p) {
    __shared__ float svec[4][256];
    __shared__ float shv [4][256];
    __shared__ float part[4][1024];
    __shared__ float redsh[4][8];
    __shared__ float ybc[4];

    int tid  = threadIdx.x;
    int col  = tid & 255;
    int q    = tid >> 8;         // 0..3
    int wq   = (tid >> 5) & 7;   // warp within quarter
    int lane = tid & 31;
    int bx   = blockIdx.x;
    float e_s0 = expf(s0p[0]);
    float e_s1 = expf(s1p[0]);
    float bias1 = b1[col];
    float bias0 = b0[col];

    const float4* w1p = (const float4*)g_W1P + (q * 16) * 256 + col;
    const float4* w0p = (const float4*)g_W0P + (q * 16) * 256 + col;

    for (int t = 0; t < T_; t++) {
        int e = t * M_ + bx * 4 + q;   // this quarter's row

        // ---- phase 1: gathered midpoint on h1buf, build svec[q] ----------
        {
            float wsum = 0.f, a = 0.f;
            #pragma unroll
            for (int k = 0; k < K_; k++) {
                int   id = nhi[e * K_ + k];
                float w  = nhw[e * K_ + k];
                wsum += w;
                a += w * g_h1buf[id * H_ + col];
            }
            a /= fmaxf(wsum, 1e-8f);
            float v = (col == 0) ? a * a : -a * a;
            #pragma unroll
            for (int o = 16; o > 0; o >>= 1) v += __shfl_down_sync(0xffffffffu, v, o);
            if (lane == 0) redsh[q][wq] = v;
            __syncthreads();
            float inn = 0.f;
            #pragma unroll
            for (int w8 = 0; w8 < 8; w8++) inn += redsh[q][w8];
            float h1m = a / sqrtf(fmaxf(inn, 1e-8f));
            if (col == 0) {
                float cx0 = emb[wid[e] * H_];
                svec[q][0] = sqrtf(fmaxf(cx0 * cx0 + h1m * h1m - 1.0f, 1e-8f));
            } else {
                svec[q][col] = h1m;
            }
        }
        __syncthreads();

        // ---- phase 2: Y = svec @ W1 (K quarter, 4 rows) -------------------
        float a0 = 0.f, a1 = 0.f, a2 = 0.f, a3 = 0.f;
        {
            const float4* s0v = (const float4*)&svec[0][q * 64];
            const float4* s1v = (const float4*)&svec[1][q * 64];
            const float4* s2v = (const float4*)&svec[2][q * 64];
            const float4* s3v = (const float4*)&svec[3][q * 64];
            #pragma unroll 4
            for (int i4 = 0; i4 < 16; i4++) {
                float4 w = w1p[i4 * 256];
                float4 x0 = s0v[i4], x1 = s1v[i4], x2 = s2v[i4], x3 = s3v[i4];
                a0 += w.x * x0.x + w.y * x0.y + w.z * x0.z + w.w * x0.w;
                a1 += w.x * x1.x + w.y * x1.y + w.z * x1.z + w.w * x1.w;
                a2 += w.x * x2.x + w.y * x2.y + w.z * x2.z + w.w * x2.w;
                a3 += w.x * x3.x + w.y * x3.y + w.z * x3.z + w.w * x3.w;
            }
        }
        part[0][tid] = a0; part[1][tid] = a1; part[2][tid] = a2; part[3][tid] = a3;
        __syncthreads();

        // epilogue: quarter q finishes row q
        {
            float y = part[q][col] + part[q][256 + col] + part[q][512 + col]
                    + part[q][768 + col] + bias1 + g_embW1[wid[e] * H_ + col];
            float v = (col == 0) ? 0.f : y * y;
            #pragma unroll
            for (int o = 16; o > 0; o >>= 1) v += __shfl_down_sync(0xffffffffu, v, o);
            if (lane == 0) redsh[q][wq] = v;
            if (col == 0) ybc[q] = y;
            __syncthreads();
            float ss = 0.f;
            #pragma unroll
            for (int w8 = 0; w8 < 8; w8++) ss += redsh[q][w8];
            float time = e_s1 / (1.f + expf(-ybc[q])) + 1.1f;
            float sc = sqrtf((time * time - 1.f) / fmaxf(ss, 1e-8f));
            float outv = (col == 0) ? time : y * sc;
            g_hbuf[e * H_ + col] = outv;
            shv[q][col] = outv;
        }
        __syncthreads();

        // ---- phase 3: h1 = new_h @ W0T ------------------------------------
        float c0 = 0.f, c1 = 0.f, c2 = 0.f, c3 = 0.f;
        {
            const float4* s0v = (const float4*)&shv[0][q * 64];
            const float4* s1v = (const float4*)&shv[1][q * 64];
            const float4* s2v = (const float4*)&shv[2][q * 64];
            const float4* s3v = (const float4*)&shv[3][q * 64];
            #pragma unroll 4
            for (int i4 = 0; i4 < 16; i4++) {
                float4 w = w0p[i4 * 256];
                float4 x0 = s0v[i4], x1 = s1v[i4], x2 = s2v[i4], x3 = s3v[i4];
                c0 += w.x * x0.x + w.y * x0.y + w.z * x0.z + w.w * x0.w;
                c1 += w.x * x1.x + w.y * x1.y + w.z * x1.z + w.w * x1.w;
                c2 += w.x * x2.x + w.y * x2.y + w.z * x2.z + w.w * x2.w;
                c3 += w.x * x3.x + w.y * x3.y + w.z * x3.z + w.w * x3.w;
            }
        }
        part[0][tid] = c0; part[1][tid] = c1; part[2][tid] = c2; part[3][tid] = c3;
        __syncthreads();

        {
            float y = part[q][col] + part[q][256 + col] + part[q][512 + col]
                    + part[q][768 + col] + bias0;
            float v = (col == 0) ? 0.f : y * y;
            #pragma unroll
            for (int o = 16; o > 0; o >>= 1) v += __shfl_down_sync(0xffffffffu, v, o);
            if (lane == 0) redsh[q][wq] = v;
            if (col == 0) ybc[q] = y;
            __syncthreads();
            float ss = 0.f;
            #pragma unroll
            for (int w8 = 0; w8 < 8; w8++) ss += redsh[q][w8];
            float time = e_s0 / (1.f + expf(-ybc[q])) + 1.1f;
            float sc = sqrtf((time * time - 1.f) / fmaxf(ss, 1e-8f));
            g_h1buf[e * H_ + col] = (col == 0) ? time : y * sc;
        }

        // ---- grid barrier -------------------------------------------------
        __threadfence();
        __syncthreads();
        if (tid == 0) {
            atomicAdd((int*)&g_bar[t], 1);
            while (g_bar[t] < NB_) __nanosleep(64);
        }
        __syncthreads();
    }
}

// -------- fused X-build + centroid scores GEMM (K=256) + CE + argmax ------
__global__ void __launch_bounds__(256) scores_ce_kernel(
    const float* __restrict__ wbias,
    const int*   __restrict__ bidx,
    const int*   __restrict__ dir,
    const int*   __restrict__ ptg,
    const int*   __restrict__ rwid,
    const float* __restrict__ xtv) {
    extern __shared__ float dsm[];
    float* xs  = dsm;                // [16][256]
    float* scr = dsm + 16 * 256;     // [16][788]
    __shared__ int sbid[16];
    __shared__ float sh_loss, sh_hit, sh_mask;
    int rb = blockIdx.x * 16, tid = threadIdx.x;
    if (tid == 0) { sh_loss = 0.f; sh_hit = 0.f; sh_mask = 0.f; }
    for (int idx = tid; idx < 16 * 256; idx += 256) {
        int row = rb + (idx >> 8);
        xs[idx] = (row < E_) ? g_hbuf[row * H_ + (idx & 255)] : 0.f;
    }
    if (tid < 16) {
        int row = rb + tid;
        sbid[tid] = (row < E_) ? bidx[row] : (row - E_);
    }
    __syncthreads();
    if (tid < 16) {   // fix col 0 (concat time component)
        int row = rb + tid;
        float c0 = xtv[sbid[tid] * L_];
        float n0 = (row < E_) ? xs[tid * 256] : 1.f;
        xs[tid * 256] = sqrtf(fmaxf(n0 * n0 + c0 * c0 - 1.f, 1e-8f));
    }
    __syncthreads();

    const float4* gp = (const float4*)g_GtP;
    for (int cc = 0; cc < 4; cc++) {
        int colv = cc * 256 + tid;
        if (colv < V_) {
            float acc[16];
            #pragma unroll
            for (int r = 0; r < 16; r++) acc[r] = 0.f;
            #pragma unroll 4
            for (int i4 = 0; i4 < 64; i4++) {
                float4 g = gp[i4 * V_ + colv];
                #pragma unroll
                for (int r = 0; r < 16; r++) {
                    float4 xv = *(const float4*)&xs[r * 256 + i4 * 4];
                    acc[r] += g.x * xv.x + g.y * xv.y + g.z * xv.z + g.w * xv.w;
                }
            }
            float bb = wbias[colv];
            #pragma unroll
            for (int r = 0; r < 16; r++) {
                float cg = g_ctxG[sbid[r] * V_ + colv];
                scr[r * 788 + colv] = 2.f + 2.f * (acc[r] + cg) + bb;
            }
        }
    }
    __syncthreads();

    int w = tid >> 5, lane = tid & 31;
    #pragma unroll
    for (int rr = 0; rr < 2; rr++) {
        int r = w * 2 + rr;
        int row = rb + r;
        const float* s = scr + r * 788;
        float mx = -1e30f; int mi = 0x7fffffff;
        for (int j = lane; j < V_; j += 32) {
            float v = s[j];
            if (v > mx) { mx = v; mi = j; }
        }
        #pragma unroll
        for (int o = 16; o > 0; o >>= 1) {
            float om = __shfl_down_sync(0xffffffffu, mx, o);
            int   oi = __shfl_down_sync(0xffffffffu, mi, o);
            if (om > mx || (om == mx && oi < mi)) { mx = om; mi = oi; }
        }
        mx = __shfl_sync(0xffffffffu, mx, 0);
        mi = __shfl_sync(0xffffffffu, mi, 0);
        float p = 0.f;
        for (int j = lane; j < V_; j += 32) p += __expf(s[j] - mx);
        #pragma unroll
        for (int o = 16; o > 0; o >>= 1) p += __shfl_down_sync(0xffffffffu, p, o);
        if (lane == 0) {
            float lse = mx + logf(p);
            float pm_l = (row < E_) ? (float)dir[row] : 1.f;
            float pm_m = (row < E_) ? pm_l : 0.f;
            int tgt = (row < E_) ? ptg[row] : rwid[row - E_];
            float ce = lse - s[tgt];
            atomicAdd(&sh_loss, pm_l * ce);
            atomicAdd(&sh_hit,  pm_l * ((mi == tgt) ? 1.f : 0.f));
            atomicAdd(&sh_mask, pm_m);
        }
    }
    __syncthreads();
    if (tid == 0) {
        atomicAdd(&g_acc[0], (double)sh_loss);
        atomicAdd(&g_acc[1], (double)sh_hit);
        atomicAdd(&g_acc[2], (double)sh_mask);
    }
}

// ------------------------- stop head (4 rows/block) ------------------------
__global__ void stop_kernel(const int*   __restrict__ wid,
                            const int*   __restrict__ noi,
                            const float* __restrict__ now,
                            const int*   __restrict__ bidx,
                            const int*   __restrict__ dir,
                            const int*   __restrict__ rwid,
                            const int*   __restrict__ roi,
                            const float* __restrict__ row_w,
                            const float* __restrict__ xtv,
                            const float* __restrict__ emb,
                            const float* __restrict__ ucls,
                            const float* __restrict__ ubias) {
    __shared__ float red[32];
    __shared__ float s_ce, s_hit;
    int tid = threadIdx.x;
    if (tid == 0) { s_ce = 0.f; s_hit = 0.f; }
    float u0a = ucls[tid];
    float u0b = ucls[255 + tid];
    float u1a = ucls[DS_ + tid];
    float u1b = ucls[DS_ + 255 + tid];
    float u0c = (tid > 0 && tid < L_) ? ucls[510 + tid] : 0.f;
    float u1c = (tid > 0 && tid < L_) ? ucls[DS_ + 510 + tid] : 0.f;
    float ub0 = ubias[0], ub1 = ubias[1];

    for (int rr = 0; rr < 4; rr++) {
        int row = blockIdx.x * 4 + rr;
        int widx, tgt;
        const int* oidx; const float* ow; const float* ctx;
        if (row < E_) {
            widx = wid[row]; tgt = dir[row];
            oidx = noi + row * K_; ow = now + row * K_;
            ctx = xtv + bidx[row] * L_;
        } else {
            int b = row - E_;
            widx = rwid[b]; tgt = 0;
            oidx = roi + b * K_; ow = row_w + b * K_;
            ctx = xtv + b * L_;
        }
        float wsum = 0.f, a = 0.f;
        #pragma unroll
        for (int k = 0; k < K_; k++) {
            int id = oidx[k]; float w = ow[k];
            wsum += w;
            a += w * g_hbuf[id * H_ + tid];
        }
        a /= fmaxf(wsum, 1e-8f);
        float inner = blockReduceSum((tid == 0) ? -a * a : a * a, red);
        float co = a / sqrtf(fmaxf(-inner, 1e-8f));
        float cx = emb[widx * H_ + tid];
        float d0, d1;
        if (tid == 0) {
            float t2s = fmaxf(cx * cx + co * co - 1.f, 1e-8f);
            float c0 = ctx[0];
            float x0 = sqrtf(fmaxf(t2s + c0 * c0 - 1.f, 1e-8f));
            d0 = -x0 * u0a;
            d1 = -x0 * u1a;
        } else {
            d0 = cx * u0a + co * u0b;
            d1 = cx * u1a + co * u1b;
            if (tid < L_) {
                float cv = ctx[tid];
                d0 += cv * u0c;
                d1 += cv * u1c;
            }
        }
        float sc0 = blockReduceSum(d0, red);
        float sc1 = blockReduceSum(d1, red);
        if (tid == 0) {
            sc0 = 2.f + 2.f * sc0 + ub0;
            sc1 = 2.f + 2.f * sc1 + ub1;
            float mxv = fmaxf(sc0, sc1);
            float lse = mxv + logf(expf(sc0 - mxv) + expf(sc1 - mxv));
            s_ce += lse - ((tgt == 0) ? sc0 : sc1);
            int am = (sc1 > sc0) ? 1 : 0;
            s_hit += (am == tgt) ? 1.f : 0.f;
        }
    }
    __syncthreads();
    if (tid == 0) {
        atomicAdd(&g_acc[3], (double)s_ce);
        atomicAdd(&g_acc[4], (double)s_hit);
    }
}

// ------------------------- finalize ---------------------------------------
__global__ void finalize(float* __restrict__ out) {
    out[0] = (float)(g_acc[0] / (double)B_);
    out[1] = (float)(g_acc[3] / (double)B_);
    out[2] = (float)(g_acc[1] / ((double)B_ + g_acc[2]));
    out[3] = (float)(g_acc[4] / (double)(E_ + B_));
}

// ------------------------- launch ------------------------------------------
extern "C" void kernel_launch(void* const* d_in, const int* in_sizes, int n_in,
                              void* d_out, int out_size) {
    const int*   wid   = (const int*)  d_in[0];
    const int*   nhi   = (const int*)  d_in[1];
    const float* nhw   = (const float*)d_in[2];
    const int*   noi   = (const int*)  d_in[3];
    const float* now_  = (const float*)d_in[4];
    const int*   bidx  = (const int*)  d_in[5];
    const int*   dir   = (const int*)  d_in[6];
    const int*   ptg   = (const int*)  d_in[7];
    const int*   rwid  = (const int*)  d_in[8];
    const int*   roi   = (const int*)  d_in[9];
    const float* row_w = (const float*)d_in[10];
    const float* xtv   = (const float*)d_in[11];
    const float* emb   = (const float*)d_in[12];
    const float* W0    = (const float*)d_in[13];
    const float* b0    = (const float*)d_in[14];
    const float* s0    = (const float*)d_in[15];
    const float* W1    = (const float*)d_in[16];
    const float* b1    = (const float*)d_in[17];
    const float* s1    = (const float*)d_in[18];
    const float* wcls  = (const float*)d_in[19];
    const float* wbias = (const float*)d_in[20];
    const float* ucls  = (const float*)d_in[21];
    const float* ubias = (const float*)d_in[22];
    float* out = (float*)d_out;

    const int smem_ce = (16 * 256 + 16 * 788) * sizeof(float);  // ~66 KB
    cudaFuncSetAttribute(scores_ce_kernel,
                         cudaFuncAttributeMaxDynamicSharedMemorySize, smem_ce);

    prep_misc<<<1024, 256>>>(W0, W1, wcls);
    prep_pad<<<1, 256>>>(W0, b0, s0);
    prep_embW1<<<(V_ + 15) / 16, 256>>>(emb);
    prep_ctxG<<<B_ / 8, 256>>>(xtv);
    scan_kernel<<<NB_, 1024>>>(wid, nhi, nhw, emb, b0, s0, b1, s1);
    scores_ce_kernel<<<NROWS / 16, 256, smem_ce>>>(wbias, bidx, dir, ptg, rwid, xtv);
    stop_kernel<<<NROWS / 4, 256>>>(wid, noi, now_, bidx, dir, rwid, roi, row_w,
                                    xtv, emb, ucls, ubias);
    finalize<<<1, 1>>>(out);
}

// round 11
// speedup vs baseline: 1.1572x; 1.1572x over previous
#include <cuda_runtime.h>
#include <math.h>

#define T_ 64
#define M_ 256
#define K_ 6
#define B_ 256
#define H_ 256
#define L_ 128
#define V_ 780
#define E_ 16384
#define DC_ 383          // wcls cols = H+L-1
#define DS_ 638          // ucls cols = 2H+L-2
#define NROWS (E_ + B_)  // msg rows + root rows
#define NB_ 128          // scan blocks (all resident; 128 <= 148 SMs)

// ------------------------- device scratch --------------------------------
__device__ __align__(16) float  g_hbuf [(E_ + 1) * H_];
__device__ __align__(16) float  g_h1buf[(E_ + 1) * H_];
__device__ __align__(16) float  g_W1T  [512 * H_];      // for embW1 prep
__device__ __align__(16) float  g_W1P  [H_ * H_];       // packed: [(k>>2)*256+col]*4+(k&3)
__device__ __align__(16) float  g_W0P  [H_ * H_];       // packed W0^T
__device__ __align__(16) float  g_embW1[V_ * H_];       // emb_spatial @ W1^T_spatial
__device__ __align__(16) float  g_GtP  [256 * V_];      // packed rows 0..255
__device__ __align__(16) float  g_GtC  [128 * V_];      // packed ctx rows 256..383
__device__ __align__(16) float  g_ctxG [B_ * V_];       // ctx_spatial(b) . Gt[256..382]
__device__ double g_acc[6];
__device__ volatile int g_bar[T_];

// ------------------------- helpers ---------------------------------------
__device__ __forceinline__ void ffma2(unsigned long long& d,
                                      unsigned long long a,
                                      unsigned long long b) {
    asm("fma.rn.f32x2 %0, %1, %2, %0;" : "+l"(d) : "l"(a), "l"(b));
}
__device__ __forceinline__ float unpack_sum(unsigned long long v) {
    float lo, hi;
    asm("mov.b64 {%0,%1}, %2;" : "=f"(lo), "=f"(hi) : "l"(v));
    return lo + hi;
}

__device__ __forceinline__ float blockReduceSum(float v, float* sh) {
    __syncthreads();
    #pragma unroll
    for (int o = 16; o > 0; o >>= 1) v += __shfl_down_sync(0xffffffffu, v, o);
    int tid = threadIdx.x;
    if ((tid & 31) == 0) sh[tid >> 5] = v;
    __syncthreads();
    if (tid < 32) {
        int nw = (blockDim.x + 31) >> 5;
        v = (tid < nw) ? sh[tid] : 0.f;
        #pragma unroll
        for (int o = 16; o > 0; o >>= 1) v += __shfl_down_sync(0xffffffffu, v, o);
        if (tid == 0) sh[0] = v;
    }
    __syncthreads();
    return sh[0];
}

__device__ __forceinline__ float gt_val(int i, int v, const float* wcls) {
    if (i == 0)  return -wcls[v * DC_];
    if (i < DC_) return wcls[v * DC_ + i];
    return 0.f;
}

// ------------------------- prep -------------------------------------------
__global__ void prep_misc(const float* __restrict__ W0,
                          const float* __restrict__ W1,
                          const float* __restrict__ wcls) {
    if (blockIdx.x == 0 && threadIdx.x < T_) g_bar[threadIdx.x] = 0;
    const int n1 = 512 * H_;        // W1T
    const int n2 = H_ * H_;         // W1P
    const int n3 = H_ * H_;         // W0P
    const int n4 = 256 * V_;        // GtP
    const int n5 = 128 * V_;        // GtC
    for (int idx = blockIdx.x * blockDim.x + threadIdx.x;
         idx < n1 + n2 + n3 + n4 + n5; idx += gridDim.x * blockDim.x) {
        if (idx < n1) {
            int i = idx >> 8, j = idx & 255;
            g_W1T[idx] = (i < 511) ? W1[j * 511 + i] : 0.f;
        } else if (idx < n1 + n2) {
            int k = idx - n1;
            int i = k >> 8, j = k & 255;
            float val = (i == 0) ? W1[j * 511] : W1[j * 511 + 255 + i];
            g_W1P[((i >> 2) << 10) + (j << 2) + (i & 3)] = val;
        } else if (idx < n1 + n2 + n3) {
            int k = idx - n1 - n2;
            int i = k >> 8, j = k & 255;
            g_W0P[((i >> 2) << 10) + (j << 2) + (i & 3)] = W0[j * H_ + i];
        } else if (idx < n1 + n2 + n3 + n4) {
            int k = idx - n1 - n2 - n3;
            int i = k / V_, v = k % V_;
            g_GtP[(((i >> 2) * V_ + v) << 2) + (i & 3)] = gt_val(i, v, wcls);
        } else {
            int k = idx - n1 - n2 - n3 - n4;
            int j = k / V_, v = k % V_;
            g_GtC[(((j >> 2) * V_ + v) << 2) + (j & 3)] = gt_val(256 + j, v, wcls);
        }
    }
}

__global__ void prep_pad(const float* __restrict__ W0,
                         const float* __restrict__ b0,
                         const float* __restrict__ s0p) {
    __shared__ float red[32];
    __shared__ float ybc;
    int tid = threadIdx.x;
    if (tid < 6) g_acc[tid] = 0.0;
    g_hbuf[E_ * H_ + tid] = (tid == 0) ? 1.f : 0.f;
    float y = W0[tid * H_] + b0[tid];
    if (tid == 0) ybc = y;
    float ss = blockReduceSum((tid == 0) ? 0.f : y * y, red);
    float time = expf(s0p[0]) / (1.f + expf(-ybc)) + 1.1f;
    float sc = sqrtf((time * time - 1.f) / fmaxf(ss, 1e-8f));
    g_h1buf[E_ * H_ + tid] = (tid == 0) ? time : y * sc;
}

// embW1[v][j] = sum_{i=1..255} emb[v][i] * W1T[i][j]
__global__ void prep_embW1(const float* __restrict__ emb) {
    __shared__ float es[16][256];
    int v0 = blockIdx.x * 16, tid = threadIdx.x;
    for (int i = tid; i < 16 * 256; i += 256) {
        int r = i >> 8, c = i & 255;
        es[r][c] = (v0 + r < V_) ? emb[(v0 + r) * H_ + c] : 0.f;
    }
    __syncthreads();
    float acc[16];
    #pragma unroll
    for (int r = 0; r < 16; r++) acc[r] = 0.f;
    for (int i = 1; i < 256; i++) {
        float w = g_W1T[i * H_ + tid];
        #pragma unroll
        for (int r = 0; r < 16; r++) acc[r] += es[r][i] * w;
    }
    #pragma unroll
    for (int r = 0; r < 16; r++)
        if (v0 + r < V_) g_embW1[(v0 + r) * H_ + tid] = acc[r];
}

// ctxG[b][v] = sum_{j=0..126} xtv[b][1+j] * Gt[256+j][v]  (one b per block)
__global__ void prep_ctxG(const float* __restrict__ xtv) {
    __shared__ __align__(16) float cs[128];
    int b = blockIdx.x, tid = threadIdx.x;
    if (tid < 128) cs[tid] = (tid < 127) ? xtv[b * L_ + 1 + tid] : 0.f;
    __syncthreads();
    const float4* gc = (const float4*)g_GtC;
    const float4* cv = (const float4*)cs;
    for (int v = tid; v < V_; v += 256) {
        float acc = 0.f;
        #pragma unroll 8
        for (int j4 = 0; j4 < 32; j4++) {
            float4 g = gc[j4 * V_ + v];
            float4 c = cv[j4];
            acc += g.x * c.x + g.y * c.y + g.z * c.z + g.w * c.w;
        }
        g_ctxG[b * V_ + v] = acc;
    }
}

// ------------------------- persistent scan kernel -------------------------
// 128 blocks x 512 threads, 2 rows/block (row = half). GEMM K split across
// halves with part[] reduce; packed float4 weights via FFMA2 (f32x2).
__global__ void __launch_bounds__(512, 1) scan_kernel(
    const int*   __restrict__ wid,
    const int*   __restrict__ nhi,
    const float* __restrict__ nhw,
    const float* __restrict__ emb,
    const float* __restrict__ b0,
    const float* __restrict__ s0p,
    const float* __restrict__ b1,
    const float* __restrict__ s1p) {
    __shared__ __align__(16) float svec[2][256];
    __shared__ __align__(16) float shv [2][256];
    __shared__ float part[2][512];
    __shared__ float redsh[2][8];
    __shared__ float ybc[2];

    int tid  = threadIdx.x;
    int col  = tid & 255;
    int half = tid >> 8;
    int warp = tid >> 5;
    int lane = tid & 31;
    int bx   = blockIdx.x;
    float e_s0 = expf(s0p[0]);
    float e_s1 = expf(s1p[0]);
    float bias1 = b1[col];
    float bias0 = b0[col];

    const ulonglong2* w1p = (const ulonglong2*)g_W1P + half * 32 * 256 + col;
    const ulonglong2* w0p = (const ulonglong2*)g_W0P + half * 32 * 256 + col;

    for (int t = 0; t < T_; t++) {
        int e = t * M_ + bx * 2 + half;   // this half's row

        // ---- phase 1: gathered midpoint on h1buf, build svec[half] -------
        {
            float wsum = 0.f, a = 0.f;
            #pragma unroll
            for (int k = 0; k < K_; k++) {
                int   id = nhi[e * K_ + k];
                float w  = nhw[e * K_ + k];
                wsum += w;
                a += w * g_h1buf[id * H_ + col];
            }
            a /= fmaxf(wsum, 1e-8f);
            float v = (col == 0) ? a * a : -a * a;
            #pragma unroll
            for (int o = 16; o > 0; o >>= 1) v += __shfl_down_sync(0xffffffffu, v, o);
            if (lane == 0) redsh[half][warp & 7] = v;
            __syncthreads();
            float inn = 0.f;
            #pragma unroll
            for (int w8 = 0; w8 < 8; w8++) inn += redsh[half][w8];
            float h1m = a / sqrtf(fmaxf(inn, 1e-8f));
            if (col == 0) {
                float cx0 = emb[wid[e] * H_];
                svec[half][0] = sqrtf(fmaxf(cx0 * cx0 + h1m * h1m - 1.0f, 1e-8f));
            } else {
                svec[half][col] = h1m;
            }
        }
        __syncthreads();

        // ---- phase 2: Y = svec @ W1 (K split across halves, FFMA2) -------
        unsigned long long acc0 = 0ull, acc1 = 0ull;
        {
            const ulonglong2* s0v = (const ulonglong2*)&svec[0][half * 128];
            const ulonglong2* s1v = (const ulonglong2*)&svec[1][half * 128];
            #pragma unroll 8
            for (int i4 = 0; i4 < 32; i4++) {
                ulonglong2 w = w1p[i4 * 256];
                ulonglong2 x0 = s0v[i4], x1 = s1v[i4];
                ffma2(acc0, w.x, x0.x); ffma2(acc0, w.y, x0.y);
                ffma2(acc1, w.x, x1.x); ffma2(acc1, w.y, x1.y);
            }
        }
        part[0][tid] = unpack_sum(acc0);
        part[1][tid] = unpack_sum(acc1);
        __syncthreads();

        // epilogue: each half finishes its own row
        {
            float y = part[half][col] + part[half][256 + col] + bias1
                    + g_embW1[wid[e] * H_ + col];
            float v = (col == 0) ? 0.f : y * y;
            #pragma unroll
            for (int o = 16; o > 0; o >>= 1) v += __shfl_down_sync(0xffffffffu, v, o);
            if (lane == 0) redsh[half][warp & 7] = v;
            if (col == 0) ybc[half] = y;
            __syncthreads();
            float ss = 0.f;
            #pragma unroll
            for (int w8 = 0; w8 < 8; w8++) ss += redsh[half][w8];
            float time = e_s1 / (1.f + expf(-ybc[half])) + 1.1f;
            float sc = sqrtf((time * time - 1.f) / fmaxf(ss, 1e-8f));
            float outv = (col == 0) ? time : y * sc;
            g_hbuf[e * H_ + col] = outv;
            shv[half][col] = outv;
        }
        __syncthreads();

        // ---- phase 3: h1 = new_h @ W0T (FFMA2) ----------------------------
        unsigned long long acc2 = 0ull, acc3 = 0ull;
        {
            const ulonglong2* s0v = (const ulonglong2*)&shv[0][half * 128];
            const ulonglong2* s1v = (const ulonglong2*)&shv[1][half * 128];
            #pragma unroll 8
            for (int i4 = 0; i4 < 32; i4++) {
                ulonglong2 w = w0p[i4 * 256];
                ulonglong2 x0 = s0v[i4], x1 = s1v[i4];
                ffma2(acc2, w.x, x0.x); ffma2(acc2, w.y, x0.y);
                ffma2(acc3, w.x, x1.x); ffma2(acc3, w.y, x1.y);
            }
        }
        part[0][tid] = unpack_sum(acc2);
        part[1][tid] = unpack_sum(acc3);
        __syncthreads();

        {
            float y = part[half][col] + part[half][256 + col] + bias0;
            float v = (col == 0) ? 0.f : y * y;
            #pragma unroll
            for (int o = 16; o > 0; o >>= 1) v += __shfl_down_sync(0xffffffffu, v, o);
            if (lane == 0) redsh[half][warp & 7] = v;
            if (col == 0) ybc[half] = y;
            __syncthreads();
            float ss = 0.f;
            #pragma unroll
            for (int w8 = 0; w8 < 8; w8++) ss += redsh[half][w8];
            float time = e_s0 / (1.f + expf(-ybc[half])) + 1.1f;
            float sc = sqrtf((time * time - 1.f) / fmaxf(ss, 1e-8f));
            g_h1buf[e * H_ + col] = (col == 0) ? time : y * sc;
        }

        // ---- grid barrier -------------------------------------------------
        __threadfence();
        __syncthreads();
        if (tid == 0) {
            atomicAdd((int*)&g_bar[t], 1);
            while (g_bar[t] < NB_) __nanosleep(64);
        }
        __syncthreads();
    }
}

// -------- fused X-build + centroid scores GEMM (K=256, FFMA2) + CE --------
__global__ void __launch_bounds__(256) scores_ce_kernel(
    const float* __restrict__ wbias,
    const int*   __restrict__ bidx,
    const int*   __restrict__ dir,
    const int*   __restrict__ ptg,
    const int*   __restrict__ rwid,
    const float* __restrict__ xtv) {
    extern __shared__ float dsm[];
    float* xs  = dsm;                // [16][256]
    float* scr = dsm + 16 * 256;     // [16][788]
    __shared__ int sbid[16];
    __shared__ float sh_loss, sh_hit, sh_mask;
    int rb = blockIdx.x * 16, tid = threadIdx.x;
    if (tid == 0) { sh_loss = 0.f; sh_hit = 0.f; sh_mask = 0.f; }
    for (int idx = tid; idx < 16 * 256; idx += 256) {
        int row = rb + (idx >> 8);
        xs[idx] = (row < E_) ? g_hbuf[row * H_ + (idx & 255)] : 0.f;
    }
    if (tid < 16) {
        int row = rb + tid;
        sbid[tid] = (row < E_) ? bidx[row] : (row - E_);
    }
    __syncthreads();
    if (tid < 16) {   // fix col 0 (concat time component)
        int row = rb + tid;
        float c0 = xtv[sbid[tid] * L_];
        float n0 = (row < E_) ? xs[tid * 256] : 1.f;
        xs[tid * 256] = sqrtf(fmaxf(n0 * n0 + c0 * c0 - 1.f, 1e-8f));
    }
    __syncthreads();

    const ulonglong2* gp = (const ulonglong2*)g_GtP;
    for (int cc = 0; cc < 4; cc++) {
        int colv = cc * 256 + tid;
        if (colv < V_) {
            unsigned long long acc[16];
            #pragma unroll
            for (int r = 0; r < 16; r++) acc[r] = 0ull;
            #pragma unroll 4
            for (int i4 = 0; i4 < 64; i4++) {
                ulonglong2 g = gp[i4 * V_ + colv];
                #pragma unroll
                for (int r = 0; r < 16; r++) {
                    ulonglong2 xv = *(const ulonglong2*)&xs[r * 256 + i4 * 4];
                    ffma2(acc[r], g.x, xv.x);
                    ffma2(acc[r], g.y, xv.y);
                }
            }
            float bb = wbias[colv];
            #pragma unroll
            for (int r = 0; r < 16; r++) {
                float cg = g_ctxG[sbid[r] * V_ + colv];
                scr[r * 788 + colv] = 2.f + 2.f * (unpack_sum(acc[r]) + cg) + bb;
            }
        }
    }
    __syncthreads();

    int w = tid >> 5, lane = tid & 31;
    #pragma unroll
    for (int rr = 0; rr < 2; rr++) {
        int r = w * 2 + rr;
        int row = rb + r;
        const float* s = scr + r * 788;
        float mx = -1e30f; int mi = 0x7fffffff;
        for (int j = lane; j < V_; j += 32) {
            float v = s[j];
            if (v > mx) { mx = v; mi = j; }
        }
        #pragma unroll
        for (int o = 16; o > 0; o >>= 1) {
            float om = __shfl_down_sync(0xffffffffu, mx, o);
            int   oi = __shfl_down_sync(0xffffffffu, mi, o);
            if (om > mx || (om == mx && oi < mi)) { mx = om; mi = oi; }
        }
        mx = __shfl_sync(0xffffffffu, mx, 0);
        mi = __shfl_sync(0xffffffffu, mi, 0);
        float p = 0.f;
        for (int j = lane; j < V_; j += 32) p += __expf(s[j] - mx);
        #pragma unroll
        for (int o = 16; o > 0; o >>= 1) p += __shfl_down_sync(0xffffffffu, p, o);
        if (lane == 0) {
            float lse = mx + logf(p);
            float pm_l = (row < E_) ? (float)dir[row] : 1.f;
            float pm_m = (row < E_) ? pm_l : 0.f;
            int tgt = (row < E_) ? ptg[row] : rwid[row - E_];
            float ce = lse - s[tgt];
            atomicAdd(&sh_loss, pm_l * ce);
            atomicAdd(&sh_hit,  pm_l * ((mi == tgt) ? 1.f : 0.f));
            atomicAdd(&sh_mask, pm_m);
        }
    }
    __syncthreads();
    if (tid == 0) {
        atomicAdd(&g_acc[0], (double)sh_loss);
        atomicAdd(&g_acc[1], (double)sh_hit);
        atomicAdd(&g_acc[2], (double)sh_mask);
    }
}

// ------------------------- stop head (4 rows/block) ------------------------
__global__ void stop_kernel(const int*   __restrict__ wid,
                            const int*   __restrict__ noi,
                            const float* __restrict__ now,
                            const int*   __restrict__ bidx,
                            const int*   __restrict__ dir,
                            const int*   __restrict__ rwid,
                            const int*   __restrict__ roi,
                            const float* __restrict__ row_w,
                            const float* __restrict__ xtv,
                            const float* __restrict__ emb,
                            const float* __restrict__ ucls,
                            const float* __restrict__ ubias) {
    __shared__ float red[32];
    __shared__ float s_ce, s_hit;
    int tid = threadIdx.x;
    if (tid == 0) { s_ce = 0.f; s_hit = 0.f; }
    float u0a = ucls[tid];
    float u0b = ucls[255 + tid];
    float u1a = ucls[DS_ + tid];
    float u1b = ucls[DS_ + 255 + tid];
    float u0c = (tid > 0 && tid < L_) ? ucls[510 + tid] : 0.f;
    float u1c = (tid > 0 && tid < L_) ? ucls[DS_ + 510 + tid] : 0.f;
    float ub0 = ubias[0], ub1 = ubias[1];

    for (int rr = 0; rr < 4; rr++) {
        int row = blockIdx.x * 4 + rr;
        int widx, tgt;
        const int* oidx; const float* ow; const float* ctx;
        if (row < E_) {
            widx = wid[row]; tgt = dir[row];
            oidx = noi + row * K_; ow = now + row * K_;
            ctx = xtv + bidx[row] * L_;
        } else {
            int b = row - E_;
            widx = rwid[b]; tgt = 0;
            oidx = roi + b * K_; ow = row_w + b * K_;
            ctx = xtv + b * L_;
        }
        float wsum = 0.f, a = 0.f;
        #pragma unroll
        for (int k = 0; k < K_; k++) {
            int id = oidx[k]; float w = ow[k];
            wsum += w;
            a += w * g_hbuf[id * H_ + tid];
        }
        a /= fmaxf(wsum, 1e-8f);
        float inner = blockReduceSum((tid == 0) ? -a * a : a * a, red);
        float co = a / sqrtf(fmaxf(-inner, 1e-8f));
        float cx = emb[widx * H_ + tid];
        float d0, d1;
        if (tid == 0) {
            float t2s = fmaxf(cx * cx + co * co - 1.f, 1e-8f);
            float c0 = ctx[0];
            float x0 = sqrtf(fmaxf(t2s + c0 * c0 - 1.f, 1e-8f));
            d0 = -x0 * u0a;
            d1 = -x0 * u1a;
        } else {
            d0 = cx * u0a + co * u0b;
            d1 = cx * u1a + co * u1b;
            if (tid < L_) {
                float cv = ctx[tid];
                d0 += cv * u0c;
                d1 += cv * u1c;
            }
        }
        float sc0 = blockReduceSum(d0, red);
        float sc1 = blockReduceSum(d1, red);
        if (tid == 0) {
            sc0 = 2.f + 2.f * sc0 + ub0;
            sc1 = 2.f + 2.f * sc1 + ub1;
            float mxv = fmaxf(sc0, sc1);
            float lse = mxv + logf(expf(sc0 - mxv) + expf(sc1 - mxv));
            s_ce += lse - ((tgt == 0) ? sc0 : sc1);
            int am = (sc1 > sc0) ? 1 : 0;
            s_hit += (am == tgt) ? 1.f : 0.f;
        }
    }
    __syncthreads();
    if (tid == 0) {
        atomicAdd(&g_acc[3], (double)s_ce);
        atomicAdd(&g_acc[4], (double)s_hit);
    }
}

// ------------------------- finalize ---------------------------------------
__global__ void finalize(float* __restrict__ out) {
    out[0] = (float)(g_acc[0] / (double)B_);
    out[1] = (float)(g_acc[3] / (double)B_);
    out[2] = (float)(g_acc[1] / ((double)B_ + g_acc[2]));
    out[3] = (float)(g_acc[4] / (double)(E_ + B_));
}

// ------------------------- launch ------------------------------------------
extern "C" void kernel_launch(void* const* d_in, const int* in_sizes, int n_in,
                              void* d_out, int out_size) {
    const int*   wid   = (const int*)  d_in[0];
    const int*   nhi   = (const int*)  d_in[1];
    const float* nhw   = (const float*)d_in[2];
    const int*   noi   = (const int*)  d_in[3];
    const float* now_  = (const float*)d_in[4];
    const int*   bidx  = (const int*)  d_in[5];
    const int*   dir   = (const int*)  d_in[6];
    const int*   ptg   = (const int*)  d_in[7];
    const int*   rwid  = (const int*)  d_in[8];
    const int*   roi   = (const int*)  d_in[9];
    const float* row_w = (const float*)d_in[10];
    const float* xtv   = (const float*)d_in[11];
    const float* emb   = (const float*)d_in[12];
    const float* W0    = (const float*)d_in[13];
    const float* b0    = (const float*)d_in[14];
    const float* s0    = (const float*)d_in[15];
    const float* W1    = (const float*)d_in[16];
    const float* b1    = (const float*)d_in[17];
    const float* s1    = (const float*)d_in[18];
    const float* wcls  = (const float*)d_in[19];
    const float* wbias = (const float*)d_in[20];
    const float* ucls  = (const float*)d_in[21];
    const float* ubias = (const float*)d_in[22];
    float* out = (float*)d_out;

    const int smem_ce = (16 * 256 + 16 * 788) * sizeof(float);  // ~66 KB
    cudaFuncSetAttribute(scores_ce_kernel,
                         cudaFuncAttributeMaxDynamicSharedMemorySize, smem_ce);

    prep_misc<<<1024, 256>>>(W0, W1, wcls);
    prep_pad<<<1, 256>>>(W0, b0, s0);
    prep_embW1<<<(V_ + 15) / 16, 256>>>(emb);
    prep_ctxG<<<B_, 256>>>(xtv);
    scan_kernel<<<NB_, 512>>>(wid, nhi, nhw, emb, b0, s0, b1, s1);
    scores_ce_kernel<<<NROWS / 16, 256, smem_ce>>>(wbias, bidx, dir, ptg, rwid, xtv);
    stop_kernel<<<NROWS / 4, 256>>>(wid, noi, now_, bidx, dir, rwid, roi, row_w,
                                    xtv, emb, ucls, ubias);
    finalize<<<1, 1>>>(out);
}

// round 12
// speedup vs baseline: 1.2303x; 1.0632x over previous
#include <cuda_runtime.h>
#include <math.h>

#define T_ 64
#define M_ 256
#define K_ 6
#define B_ 256
#define H_ 256
#define L_ 128
#define V_ 780
#define E_ 16384
#define DC_ 383          // wcls cols = H+L-1
#define DS_ 638          // ucls cols = 2H+L-2
#define NROWS (E_ + B_)  // msg rows + root rows
#define NB_ 128          // scan worker blocks (barrier count)
#define NH_ 20           // helper blocks (prep work) -> total grid 148
#define NTOT_ (NB_ + NH_)

// ------------------------- device scratch --------------------------------
__device__ __align__(16) float  g_hbuf [(E_ + 1) * H_];
__device__ __align__(16) float  g_h1buf[(E_ + 1) * H_];
__device__ __align__(16) float  g_W1T  [512 * H_];      // for embW1 prep
__device__ __align__(16) float  g_W1P  [H_ * H_];       // packed: [(k>>2)*256+col]*4+(k&3)
__device__ __align__(16) float  g_W0P  [H_ * H_];       // packed W0^T
__device__ __align__(16) float  g_embW1[V_ * H_];       // emb_spatial @ W1^T_spatial
__device__ __align__(16) float  g_GtP  [256 * V_];      // packed rows 0..255
__device__ __align__(16) float  g_GtC  [128 * V_];      // packed ctx rows 256..383
__device__ __align__(16) float  g_ctxG [B_ * V_];       // ctx_spatial(b) . Gt[256..382]
__device__ double g_acc[6];
__device__ volatile int g_bar[T_];
__device__ volatile int g_hbar;

// ------------------------- helpers ---------------------------------------
__device__ __forceinline__ void ffma2(unsigned long long& d,
                                      unsigned long long a,
                                      unsigned long long b) {
    asm("fma.rn.f32x2 %0, %1, %2, %0;" : "+l"(d) : "l"(a), "l"(b));
}
__device__ __forceinline__ float unpack_sum(unsigned long long v) {
    float lo, hi;
    asm("mov.b64 {%0,%1}, %2;" : "=f"(lo), "=f"(hi) : "l"(v));
    return lo + hi;
}

__device__ __forceinline__ float blockReduceSum(float v, float* sh) {
    __syncthreads();
    #pragma unroll
    for (int o = 16; o > 0; o >>= 1) v += __shfl_down_sync(0xffffffffu, v, o);
    int tid = threadIdx.x;
    if ((tid & 31) == 0) sh[tid >> 5] = v;
    __syncthreads();
    if (tid < 32) {
        int nw = (blockDim.x + 31) >> 5;
        v = (tid < nw) ? sh[tid] : 0.f;
        #pragma unroll
        for (int o = 16; o > 0; o >>= 1) v += __shfl_down_sync(0xffffffffu, v, o);
        if (tid == 0) sh[0] = v;
    }
    __syncthreads();
    return sh[0];
}

__device__ __forceinline__ float gt_val(int i, int v, const float* wcls) {
    if (i == 0)  return -wcls[v * DC_];
    if (i < DC_) return wcls[v * DC_ + i];
    return 0.f;
}

// ------------------------- prep (weights only) -----------------------------
__global__ void prep_misc(const float* __restrict__ W0,
                          const float* __restrict__ W1) {
    if (blockIdx.x == 0) {
        if (threadIdx.x < T_) g_bar[threadIdx.x] = 0;
        if (threadIdx.x == 0) g_hbar = 0;
    }
    const int n1 = 512 * H_;        // W1T
    const int n2 = H_ * H_;         // W1P
    const int n3 = H_ * H_;         // W0P
    for (int idx = blockIdx.x * blockDim.x + threadIdx.x;
         idx < n1 + n2 + n3; idx += gridDim.x * blockDim.x) {
        if (idx < n1) {
            int i = idx >> 8, j = idx & 255;
            g_W1T[idx] = (i < 511) ? W1[j * 511 + i] : 0.f;
        } else if (idx < n1 + n2) {
            int k = idx - n1;
            int i = k >> 8, j = k & 255;
            float val = (i == 0) ? W1[j * 511] : W1[j * 511 + 255 + i];
            g_W1P[((i >> 2) << 10) + (j << 2) + (i & 3)] = val;
        } else {
            int k = idx - n1 - n2;
            int i = k >> 8, j = k & 255;
            g_W0P[((i >> 2) << 10) + (j << 2) + (i & 3)] = W0[j * H_ + i];
        }
    }
}

__global__ void prep_pad(const float* __restrict__ W0,
                         const float* __restrict__ b0,
                         const float* __restrict__ s0p) {
    __shared__ float red[32];
    __shared__ float ybc;
    int tid = threadIdx.x;
    if (tid < 6) g_acc[tid] = 0.0;
    g_hbuf[E_ * H_ + tid] = (tid == 0) ? 1.f : 0.f;
    float y = W0[tid * H_] + b0[tid];
    if (tid == 0) ybc = y;
    float ss = blockReduceSum((tid == 0) ? 0.f : y * y, red);
    float time = expf(s0p[0]) / (1.f + expf(-ybc)) + 1.1f;
    float sc = sqrtf((time * time - 1.f) / fmaxf(ss, 1e-8f));
    g_h1buf[E_ * H_ + tid] = (tid == 0) ? time : y * sc;
}

// embW1[v][j] = sum_{i=1..255} emb[v][i] * W1T[i][j]
__global__ void prep_embW1(const float* __restrict__ emb) {
    __shared__ float es[16][256];
    int v0 = blockIdx.x * 16, tid = threadIdx.x;
    for (int i = tid; i < 16 * 256; i += 256) {
        int r = i >> 8, c = i & 255;
        es[r][c] = (v0 + r < V_) ? emb[(v0 + r) * H_ + c] : 0.f;
    }
    __syncthreads();
    float acc[16];
    #pragma unroll
    for (int r = 0; r < 16; r++) acc[r] = 0.f;
    for (int i = 1; i < 256; i++) {
        float w = g_W1T[i * H_ + tid];
        #pragma unroll
        for (int r = 0; r < 16; r++) acc[r] += es[r][i] * w;
    }
    #pragma unroll
    for (int r = 0; r < 16; r++)
        if (v0 + r < V_) g_embW1[(v0 + r) * H_ + tid] = acc[r];
}

// ------------- helper-block work (runs concurrently with the scan) ---------
__device__ void helper_work(const float* __restrict__ wcls,
                            const float* __restrict__ xtv,
                            int hb, float* cs) {
    int tid = threadIdx.x;   // 512 threads
    // 1) GtC (ctx rows of centroid matrix, packed)
    for (int idx = hb * 512 + tid; idx < 128 * V_; idx += NH_ * 512) {
        int j = idx / V_, v = idx - j * V_;
        g_GtC[(((j >> 2) * V_ + v) << 2) + (j & 3)] = gt_val(256 + j, v, wcls);
    }
    // 2) helper barrier (GtC complete before ctxG reads it)
    __threadfence();
    __syncthreads();
    if (tid == 0) {
        atomicAdd((int*)&g_hbar, 1);
        while (g_hbar < NH_) __nanosleep(128);
    }
    __syncthreads();
    // 3) ctxG[b][v] = xtv_spatial(b) . GtC
    const float4* gc = (const float4*)g_GtC;
    for (int b = hb; b < B_; b += NH_) {
        if (tid < 128) cs[tid] = (tid < 127) ? xtv[b * L_ + 1 + tid] : 0.f;
        __syncthreads();
        const float4* cv = (const float4*)cs;
        for (int v = tid; v < V_; v += 512) {
            float acc = 0.f;
            #pragma unroll 8
            for (int j4 = 0; j4 < 32; j4++) {
                float4 g = gc[j4 * V_ + v];
                float4 c = cv[j4];
                acc += g.x * c.x + g.y * c.y + g.z * c.z + g.w * c.w;
            }
            g_ctxG[b * V_ + v] = acc;
        }
        __syncthreads();
    }
    // 4) GtP (h rows of centroid matrix, packed)
    for (int idx = hb * 512 + tid; idx < 256 * V_; idx += NH_ * 512) {
        int i = idx / V_, v = idx - i * V_;
        g_GtP[(((i >> 2) * V_ + v) << 2) + (i & 3)] = gt_val(i, v, wcls);
    }
}

// ------------------------- persistent scan kernel -------------------------
// grid = 148: blocks 0..127 scan (2 rows each, K split across halves, FFMA2);
// blocks 128..147 run helper prep work concurrently.
__global__ void __launch_bounds__(512, 1) scan_kernel(
    const int*   __restrict__ wid,
    const int*   __restrict__ nhi,
    const float* __restrict__ nhw,
    const float* __restrict__ emb,
    const float* __restrict__ b0,
    const float* __restrict__ s0p,
    const float* __restrict__ b1,
    const float* __restrict__ s1p,
    const float* __restrict__ wcls,
    const float* __restrict__ xtv) {
    __shared__ __align__(16) float svec[2][256];
    __shared__ __align__(16) float shv [2][256];
    __shared__ float part[2][512];
    __shared__ float redsh[2][8];
    __shared__ float ybc[2];

    if (blockIdx.x >= NB_) {
        helper_work(wcls, xtv, blockIdx.x - NB_, &svec[0][0]);
        return;
    }

    int tid  = threadIdx.x;
    int col  = tid & 255;
    int half = tid >> 8;
    int warp = tid >> 5;
    int lane = tid & 31;
    int bx   = blockIdx.x;
    float e_s0 = expf(s0p[0]);
    float e_s1 = expf(s1p[0]);
    float bias1 = b1[col];
    float bias0 = b0[col];

    const ulonglong2* w1p = (const ulonglong2*)g_W1P + half * 32 * 256 + col;
    const ulonglong2* w0p = (const ulonglong2*)g_W0P + half * 32 * 256 + col;

    // prefetch step-0 indices
    int   pid[K_]; float pw[K_]; int pwid;
    {
        int e0 = bx * 2 + half;
        #pragma unroll
        for (int k = 0; k < K_; k++) { pid[k] = nhi[e0 * K_ + k]; pw[k] = nhw[e0 * K_ + k]; }
        pwid = wid[e0];
    }

    for (int t = 0; t < T_; t++) {
        int e = t * M_ + bx * 2 + half;   // this half's row

        // issue barrier-independent loads early
        float embv = g_embW1[pwid * H_ + col];
        float cx0  = emb[pwid * H_];

        // ---- phase 1: gathered midpoint on h1buf, build svec[half] -------
        {
            float wsum = 0.f, a = 0.f;
            #pragma unroll
            for (int k = 0; k < K_; k++) {
                wsum += pw[k];
                a += pw[k] * g_h1buf[pid[k] * H_ + col];
            }
            a /= fmaxf(wsum, 1e-8f);
            float v = (col == 0) ? a * a : -a * a;
            #pragma unroll
            for (int o = 16; o > 0; o >>= 1) v += __shfl_down_sync(0xffffffffu, v, o);
            if (lane == 0) redsh[half][warp & 7] = v;
            __syncthreads();
            float inn = 0.f;
            #pragma unroll
            for (int w8 = 0; w8 < 8; w8++) inn += redsh[half][w8];
            float h1m = a / sqrtf(fmaxf(inn, 1e-8f));
            if (col == 0) {
                svec[half][0] = sqrtf(fmaxf(cx0 * cx0 + h1m * h1m - 1.0f, 1e-8f));
            } else {
                svec[half][col] = h1m;
            }
        }
        __syncthreads();

        // ---- phase 2: Y = svec @ W1 (K split across halves, FFMA2) -------
        unsigned long long acc0 = 0ull, acc1 = 0ull;
        {
            const ulonglong2* s0v = (const ulonglong2*)&svec[0][half * 128];
            const ulonglong2* s1v = (const ulonglong2*)&svec[1][half * 128];
            #pragma unroll 8
            for (int i4 = 0; i4 < 32; i4++) {
                ulonglong2 w = w1p[i4 * 256];
                ulonglong2 x0 = s0v[i4], x1 = s1v[i4];
                ffma2(acc0, w.x, x0.x); ffma2(acc0, w.y, x0.y);
                ffma2(acc1, w.x, x1.x); ffma2(acc1, w.y, x1.y);
            }
        }
        part[0][tid] = unpack_sum(acc0);
        part[1][tid] = unpack_sum(acc1);
        __syncthreads();

        // epilogue: each half finishes its own row
        {
            float y = part[half][col] + part[half][256 + col] + bias1 + embv;
            float v = (col == 0) ? 0.f : y * y;
            #pragma unroll
            for (int o = 16; o > 0; o >>= 1) v += __shfl_down_sync(0xffffffffu, v, o);
            if (lane == 0) redsh[half][warp & 7] = v;
            if (col == 0) ybc[half] = y;
            __syncthreads();
            float ss = 0.f;
            #pragma unroll
            for (int w8 = 0; w8 < 8; w8++) ss += redsh[half][w8];
            float time = e_s1 / (1.f + expf(-ybc[half])) + 1.1f;
            float sc = sqrtf((time * time - 1.f) / fmaxf(ss, 1e-8f));
            float outv = (col == 0) ? time : y * sc;
            g_hbuf[e * H_ + col] = outv;
            shv[half][col] = outv;
        }
        __syncthreads();

        // ---- phase 3: h1 = new_h @ W0T (FFMA2) ----------------------------
        unsigned long long acc2 = 0ull, acc3 = 0ull;
        {
            const ulonglong2* s0v = (const ulonglong2*)&shv[0][half * 128];
            const ulonglong2* s1v = (const ulonglong2*)&shv[1][half * 128];
            #pragma unroll 8
            for (int i4 = 0; i4 < 32; i4++) {
                ulonglong2 w = w0p[i4 * 256];
                ulonglong2 x0 = s0v[i4], x1 = s1v[i4];
                ffma2(acc2, w.x, x0.x); ffma2(acc2, w.y, x0.y);
                ffma2(acc3, w.x, x1.x); ffma2(acc3, w.y, x1.y);
            }
        }
        part[0][tid] = unpack_sum(acc2);
        part[1][tid] = unpack_sum(acc3);
        __syncthreads();

        {
            float y = part[half][col] + part[half][256 + col] + bias0;
            float v = (col == 0) ? 0.f : y * y;
            #pragma unroll
            for (int o = 16; o > 0; o >>= 1) v += __shfl_down_sync(0xffffffffu, v, o);
            if (lane == 0) redsh[half][warp & 7] = v;
            if (col == 0) ybc[half] = y;
            __syncthreads();
            float ss = 0.f;
            #pragma unroll
            for (int w8 = 0; w8 < 8; w8++) ss += redsh[half][w8];
            float time = e_s0 / (1.f + expf(-ybc[half])) + 1.1f;
            float sc = sqrtf((time * time - 1.f) / fmaxf(ss, 1e-8f));
            g_h1buf[e * H_ + col] = (col == 0) ? time : y * sc;
        }

        // prefetch next step's indices (input arrays: barrier-independent)
        if (t + 1 < T_) {
            int en = (t + 1) * M_ + bx * 2 + half;
            #pragma unroll
            for (int k = 0; k < K_; k++) { pid[k] = nhi[en * K_ + k]; pw[k] = nhw[en * K_ + k]; }
            pwid = wid[en];
        }

        // ---- grid barrier -------------------------------------------------
        __threadfence();
        __syncthreads();
        if (tid == 0) {
            atomicAdd((int*)&g_bar[t], 1);
            while (g_bar[t] < NB_) __nanosleep(64);
        }
        __syncthreads();
    }
}

// -------- fused X-build + centroid scores GEMM (K=256, FFMA2) + CE --------
__global__ void __launch_bounds__(256) scores_ce_kernel(
    const float* __restrict__ wbias,
    const int*   __restrict__ bidx,
    const int*   __restrict__ dir,
    const int*   __restrict__ ptg,
    const int*   __restrict__ rwid,
    const float* __restrict__ xtv) {
    extern __shared__ float dsm[];
    float* xs  = dsm;                // [16][256]
    float* scr = dsm + 16 * 256;     // [16][788]
    __shared__ int sbid[16];
    __shared__ float sh_loss, sh_hit, sh_mask;
    int rb = blockIdx.x * 16, tid = threadIdx.x;
    if (tid == 0) { sh_loss = 0.f; sh_hit = 0.f; sh_mask = 0.f; }
    for (int idx = tid; idx < 16 * 256; idx += 256) {
        int row = rb + (idx >> 8);
        xs[idx] = (row < E_) ? g_hbuf[row * H_ + (idx & 255)] : 0.f;
    }
    if (tid < 16) {
        int row = rb + tid;
        sbid[tid] = (row < E_) ? bidx[row] : (row - E_);
    }
    __syncthreads();
    if (tid < 16) {   // fix col 0 (concat time component)
        int row = rb + tid;
        float c0 = xtv[sbid[tid] * L_];
        float n0 = (row < E_) ? xs[tid * 256] : 1.f;
        xs[tid * 256] = sqrtf(fmaxf(n0 * n0 + c0 * c0 - 1.f, 1e-8f));
    }
    __syncthreads();

    const ulonglong2* gp = (const ulonglong2*)g_GtP;
    for (int cc = 0; cc < 4; cc++) {
        int colv = cc * 256 + tid;
        if (colv < V_) {
            unsigned long long acc[16];
            #pragma unroll
            for (int r = 0; r < 16; r++) acc[r] = 0ull;
            #pragma unroll 4
            for (int i4 = 0; i4 < 64; i4++) {
                ulonglong2 g = gp[i4 * V_ + colv];
                #pragma unroll
                for (int r = 0; r < 16; r++) {
                    ulonglong2 xv = *(const ulonglong2*)&xs[r * 256 + i4 * 4];
                    ffma2(acc[r], g.x, xv.x);
                    ffma2(acc[r], g.y, xv.y);
                }
            }
            float bb = wbias[colv];
            #pragma unroll
            for (int r = 0; r < 16; r++) {
                float cg = g_ctxG[sbid[r] * V_ + colv];
                scr[r * 788 + colv] = 2.f + 2.f * (unpack_sum(acc[r]) + cg) + bb;
            }
        }
    }
    __syncthreads();

    int w = tid >> 5, lane = tid & 31;
    #pragma unroll
    for (int rr = 0; rr < 2; rr++) {
        int r = w * 2 + rr;
        int row = rb + r;
        const float* s = scr + r * 788;
        float mx = -1e30f; int mi = 0x7fffffff;
        for (int j = lane; j < V_; j += 32) {
            float v = s[j];
            if (v > mx) { mx = v; mi = j; }
        }
        #pragma unroll
        for (int o = 16; o > 0; o >>= 1) {
            float om = __shfl_down_sync(0xffffffffu, mx, o);
            int   oi = __shfl_down_sync(0xffffffffu, mi, o);
            if (om > mx || (om == mx && oi < mi)) { mx = om; mi = oi; }
        }
        mx = __shfl_sync(0xffffffffu, mx, 0);
        mi = __shfl_sync(0xffffffffu, mi, 0);
        float p = 0.f;
        for (int j = lane; j < V_; j += 32) p += __expf(s[j] - mx);
        #pragma unroll
        for (int o = 16; o > 0; o >>= 1) p += __shfl_down_sync(0xffffffffu, p, o);
        if (lane == 0) {
            float lse = mx + logf(p);
            float pm_l = (row < E_) ? (float)dir[row] : 1.f;
            float pm_m = (row < E_) ? pm_l : 0.f;
            int tgt = (row < E_) ? ptg[row] : rwid[row - E_];
            float ce = lse - s[tgt];
            atomicAdd(&sh_loss, pm_l * ce);
            atomicAdd(&sh_hit,  pm_l * ((mi == tgt) ? 1.f : 0.f));
            atomicAdd(&sh_mask, pm_m);
        }
    }
    __syncthreads();
    if (tid == 0) {
        atomicAdd(&g_acc[0], (double)sh_loss);
        atomicAdd(&g_acc[1], (double)sh_hit);
        atomicAdd(&g_acc[2], (double)sh_mask);
    }
}

// ------------------------- stop head (4 rows/block) ------------------------
__global__ void stop_kernel(const int*   __restrict__ wid,
                            const int*   __restrict__ noi,
                            const float* __restrict__ now,
                            const int*   __restrict__ bidx,
                            const int*   __restrict__ dir,
                            const int*   __restrict__ rwid,
                            const int*   __restrict__ roi,
                            const float* __restrict__ row_w,
                            const float* __restrict__ xtv,
                            const float* __restrict__ emb,
                            const float* __restrict__ ucls,
                            const float* __restrict__ ubias) {
    __shared__ float red[32];
    __shared__ float s_ce, s_hit;
    int tid = threadIdx.x;
    if (tid == 0) { s_ce = 0.f; s_hit = 0.f; }
    float u0a = ucls[tid];
    float u0b = ucls[255 + tid];
    float u1a = ucls[DS_ + tid];
    float u1b = ucls[DS_ + 255 + tid];
    float u0c = (tid > 0 && tid < L_) ? ucls[510 + tid] : 0.f;
    float u1c = (tid > 0 && tid < L_) ? ucls[DS_ + 510 + tid] : 0.f;
    float ub0 = ubias[0], ub1 = ubias[1];

    for (int rr = 0; rr < 4; rr++) {
        int row = blockIdx.x * 4 + rr;
        int widx, tgt;
        const int* oidx; const float* ow; const float* ctx;
        if (row < E_) {
            widx = wid[row]; tgt = dir[row];
            oidx = noi + row * K_; ow = now + row * K_;
            ctx = xtv + bidx[row] * L_;
        } else {
            int b = row - E_;
            widx = rwid[b]; tgt = 0;
            oidx = roi + b * K_; ow = row_w + b * K_;
            ctx = xtv + b * L_;
        }
        float wsum = 0.f, a = 0.f;
        #pragma unroll
        for (int k = 0; k < K_; k++) {
            int id = oidx[k]; float w = ow[k];
            wsum += w;
            a += w * g_hbuf[id * H_ + tid];
        }
        a /= fmaxf(wsum, 1e-8f);
        float inner = blockReduceSum((tid == 0) ? -a * a : a * a, red);
        float co = a / sqrtf(fmaxf(-inner, 1e-8f));
        float cx = emb[widx * H_ + tid];
        float d0, d1;
        if (tid == 0) {
            float t2s = fmaxf(cx * cx + co * co - 1.f, 1e-8f);
            float c0 = ctx[0];
            float x0 = sqrtf(fmaxf(t2s + c0 * c0 - 1.f, 1e-8f));
            d0 = -x0 * u0a;
            d1 = -x0 * u1a;
        } else {
            d0 = cx * u0a + co * u0b;
            d1 = cx * u1a + co * u1b;
            if (tid < L_) {
                float cv = ctx[tid];
                d0 += cv * u0c;
                d1 += cv * u1c;
            }
        }
        float sc0 = blockReduceSum(d0, red);
        float sc1 = blockReduceSum(d1, red);
        if (tid == 0) {
            sc0 = 2.f + 2.f * sc0 + ub0;
            sc1 = 2.f + 2.f * sc1 + ub1;
            float mxv = fmaxf(sc0, sc1);
            float lse = mxv + logf(expf(sc0 - mxv) + expf(sc1 - mxv));
            s_ce += lse - ((tgt == 0) ? sc0 : sc1);
            int am = (sc1 > sc0) ? 1 : 0;
            s_hit += (am == tgt) ? 1.f : 0.f;
        }
    }
    __syncthreads();
    if (tid == 0) {
        atomicAdd(&g_acc[3], (double)s_ce);
        atomicAdd(&g_acc[4], (double)s_hit);
    }
}

// ------------------------- finalize ---------------------------------------
__global__ void finalize(float* __restrict__ out) {
    out[0] = (float)(g_acc[0] / (double)B_);
    out[1] = (float)(g_acc[3] / (double)B_);
    out[2] = (float)(g_acc[1] / ((double)B_ + g_acc[2]));
    out[3] = (float)(g_acc[4] / (double)(E_ + B_));
}

// ------------------------- launch ------------------------------------------
extern "C" void kernel_launch(void* const* d_in, const int* in_sizes, int n_in,
                              void* d_out, int out_size) {
    const int*   wid   = (const int*)  d_in[0];
    const int*   nhi   = (const int*)  d_in[1];
    const float* nhw   = (const float*)d_in[2];
    const int*   noi   = (const int*)  d_in[3];
    const float* now_  = (const float*)d_in[4];
    const int*   bidx  = (const int*)  d_in[5];
    const int*   dir   = (const int*)  d_in[6];
    const int*   ptg   = (const int*)  d_in[7];
    const int*   rwid  = (const int*)  d_in[8];
    const int*   roi   = (const int*)  d_in[9];
    const float* row_w = (const float*)d_in[10];
    const float* xtv   = (const float*)d_in[11];
    const float* emb   = (const float*)d_in[12];
    const float* W0    = (const float*)d_in[13];
    const float* b0    = (const float*)d_in[14];
    const float* s0    = (const float*)d_in[15];
    const float* W1    = (const float*)d_in[16];
    const float* b1    = (const float*)d_in[17];
    const float* s1    = (const float*)d_in[18];
    const float* wcls  = (const float*)d_in[19];
    const float* wbias = (const float*)d_in[20];
    const float* ucls  = (const float*)d_in[21];
    const float* ubias = (const float*)d_in[22];
    float* out = (float*)d_out;

    const int smem_ce = (16 * 256 + 16 * 788) * sizeof(float);  // ~66 KB
    cudaFuncSetAttribute(scores_ce_kernel,
                         cudaFuncAttributeMaxDynamicSharedMemorySize, smem_ce);

    prep_misc<<<512, 256>>>(W0, W1);
    prep_pad<<<1, 256>>>(W0, b0, s0);
    prep_embW1<<<(V_ + 15) / 16, 256>>>(emb);
    scan_kernel<<<NTOT_, 512>>>(wid, nhi, nhw, emb, b0, s0, b1, s1, wcls, xtv);
    scores_ce_kernel<<<NROWS / 16, 256, smem_ce>>>(wbias, bidx, dir, ptg, rwid, xtv);
    stop_kernel<<<NROWS / 4, 256>>>(wid, noi, now_, bidx, dir, rwid, roi, row_w,
                                    xtv, emb, ucls, ubias);
    finalize<<<1, 1>>>(out);
}

// round 13
// speedup vs baseline: 1.2406x; 1.0084x over previous
#include <cuda_runtime.h>
#include <math.h>

#define T_ 64
#define M_ 256
#define K_ 6
#define B_ 256
#define H_ 256
#define L_ 128
#define V_ 780
#define E_ 16384
#define DC_ 383          // wcls cols = H+L-1
#define DS_ 638          // ucls cols = 2H+L-2
#define NROWS (E_ + B_)  // msg rows + root rows
#define NB_ 128          // scan worker blocks (barrier count)
#define NH_ 20           // helper blocks -> total grid 148
#define NTOT_ (NB_ + NH_)

// ------------------------- device scratch --------------------------------
__device__ __align__(16) float  g_hbuf [(E_ + 1) * H_];
__device__ __align__(16) float  g_h1buf[(E_ + 1) * H_];
__device__ __align__(16) float  g_W1T  [512 * H_];      // for embW1 prep
__device__ __align__(16) float  g_W1P  [H_ * H_];       // packed: [(k>>2)*256+col]*4+(k&3)
__device__ __align__(16) float  g_W0P  [H_ * H_];       // packed W0^T
__device__ __align__(16) float  g_embW1[V_ * H_];       // emb_spatial @ W1^T_spatial
__device__ __align__(16) float  g_GtP  [256 * V_];      // packed rows 0..255
__device__ __align__(16) float  g_GtC  [128 * V_];      // packed ctx rows 256..383
__device__ __align__(16) float  g_ctxG [B_ * V_];       // ctx_spatial(b) . Gt[256..382]
__device__ double g_acc[6];
__device__ volatile int g_bar[T_];
__device__ volatile int g_hbar;

// ------------------------- helpers ---------------------------------------
__device__ __forceinline__ void ffma2(unsigned long long& d,
                                      unsigned long long a,
                                      unsigned long long b) {
    asm("fma.rn.f32x2 %0, %1, %2, %0;" : "+l"(d) : "l"(a), "l"(b));
}
__device__ __forceinline__ float unpack_sum(unsigned long long v) {
    float lo, hi;
    asm("mov.b64 {%0,%1}, %2;" : "=f"(lo), "=f"(hi) : "l"(v));
    return lo + hi;
}

__device__ __forceinline__ float blockReduceSum(float v, float* sh) {
    __syncthreads();
    #pragma unroll
    for (int o = 16; o > 0; o >>= 1) v += __shfl_down_sync(0xffffffffu, v, o);
    int tid = threadIdx.x;
    if ((tid & 31) == 0) sh[tid >> 5] = v;
    __syncthreads();
    if (tid < 32) {
        int nw = (blockDim.x + 31) >> 5;
        v = (tid < nw) ? sh[tid] : 0.f;
        #pragma unroll
        for (int o = 16; o > 0; o >>= 1) v += __shfl_down_sync(0xffffffffu, v, o);
        if (tid == 0) sh[0] = v;
    }
    __syncthreads();
    return sh[0];
}

__device__ __forceinline__ float gt_val(int i, int v, const float* wcls) {
    if (i == 0)  return -wcls[v * DC_];
    if (i < DC_) return wcls[v * DC_ + i];
    return 0.f;
}

// ------------------------- prep (weights only) -----------------------------
__global__ void prep_misc(const float* __restrict__ W0,
                          const float* __restrict__ W1) {
    if (blockIdx.x == 0) {
        if (threadIdx.x < T_) g_bar[threadIdx.x] = 0;
        if (threadIdx.x == 0) g_hbar = 0;
    }
    const int n1 = 512 * H_;        // W1T
    const int n2 = H_ * H_;         // W1P
    const int n3 = H_ * H_;         // W0P
    for (int idx = blockIdx.x * blockDim.x + threadIdx.x;
         idx < n1 + n2 + n3; idx += gridDim.x * blockDim.x) {
        if (idx < n1) {
            int i = idx >> 8, j = idx & 255;
            g_W1T[idx] = (i < 511) ? W1[j * 511 + i] : 0.f;
        } else if (idx < n1 + n2) {
            int k = idx - n1;
            int i = k >> 8, j = k & 255;
            float val = (i == 0) ? W1[j * 511] : W1[j * 511 + 255 + i];
            g_W1P[((i >> 2) << 10) + (j << 2) + (i & 3)] = val;
        } else {
            int k = idx - n1 - n2;
            int i = k >> 8, j = k & 255;
            g_W0P[((i >> 2) << 10) + (j << 2) + (i & 3)] = W0[j * H_ + i];
        }
    }
}

__global__ void prep_pad(const float* __restrict__ W0,
                         const float* __restrict__ b0,
                         const float* __restrict__ s0p) {
    __shared__ float red[32];
    __shared__ float ybc;
    int tid = threadIdx.x;
    if (tid < 6) g_acc[tid] = 0.0;
    g_hbuf[E_ * H_ + tid] = (tid == 0) ? 1.f : 0.f;
    float y = W0[tid * H_] + b0[tid];
    if (tid == 0) ybc = y;
    float ss = blockReduceSum((tid == 0) ? 0.f : y * y, red);
    float time = expf(s0p[0]) / (1.f + expf(-ybc)) + 1.1f;
    float sc = sqrtf((time * time - 1.f) / fmaxf(ss, 1e-8f));
    g_h1buf[E_ * H_ + tid] = (tid == 0) ? time : y * sc;
}

// embW1[v][j] = sum_{i=1..255} emb[v][i] * W1T[i][j]
__global__ void prep_embW1(const float* __restrict__ emb) {
    __shared__ float es[16][256];
    int v0 = blockIdx.x * 16, tid = threadIdx.x;
    for (int i = tid; i < 16 * 256; i += 256) {
        int r = i >> 8, c = i & 255;
        es[r][c] = (v0 + r < V_) ? emb[(v0 + r) * H_ + c] : 0.f;
    }
    __syncthreads();
    float acc[16];
    #pragma unroll
    for (int r = 0; r < 16; r++) acc[r] = 0.f;
    for (int i = 1; i < 256; i++) {
        float w = g_W1T[i * H_ + tid];
        #pragma unroll
        for (int r = 0; r < 16; r++) acc[r] += es[r][i] * w;
    }
    #pragma unroll
    for (int r = 0; r < 16; r++)
        if (v0 + r < V_) g_embW1[(v0 + r) * H_ + tid] = acc[r];
}

// ------------- helper-block work (runs concurrently with the scan) ---------
__device__ void helper_work(const float* __restrict__ wcls,
                            const float* __restrict__ xtv,
                            int hb, float* cs) {
    int tid = threadIdx.x;   // 512 threads
    for (int idx = hb * 512 + tid; idx < 128 * V_; idx += NH_ * 512) {
        int j = idx / V_, v = idx - j * V_;
        g_GtC[(((j >> 2) * V_ + v) << 2) + (j & 3)] = gt_val(256 + j, v, wcls);
    }
    __threadfence();
    __syncthreads();
    if (tid == 0) {
        atomicAdd((int*)&g_hbar, 1);
        while (g_hbar < NH_) __nanosleep(128);
    }
    __syncthreads();
    const float4* gc = (const float4*)g_GtC;
    for (int b = hb; b < B_; b += NH_) {
        if (tid < 128) cs[tid] = (tid < 127) ? xtv[b * L_ + 1 + tid] : 0.f;
        __syncthreads();
        const float4* cv = (const float4*)cs;
        for (int v = tid; v < V_; v += 512) {
            float acc = 0.f;
            #pragma unroll 8
            for (int j4 = 0; j4 < 32; j4++) {
                float4 g = gc[j4 * V_ + v];
                float4 c = cv[j4];
                acc += g.x * c.x + g.y * c.y + g.z * c.z + g.w * c.w;
            }
            g_ctxG[b * V_ + v] = acc;
        }
        __syncthreads();
    }
    for (int idx = hb * 512 + tid; idx < 256 * V_; idx += NH_ * 512) {
        int i = idx / V_, v = idx - i * V_;
        g_GtP[(((i >> 2) * V_ + v) << 2) + (i & 3)] = gt_val(i, v, wcls);
    }
}

// ------------------------- persistent scan kernel -------------------------
// grid = 148: blocks 0..127 scan (2 rows each, K split across halves, FFMA2,
// scale-deferred epilogues); blocks 128..147 run helper prep concurrently.
__global__ void __launch_bounds__(512, 1) scan_kernel(
    const int*   __restrict__ wid,
    const int*   __restrict__ nhi,
    const float* __restrict__ nhw,
    const float* __restrict__ emb,
    const float* __restrict__ b0,
    const float* __restrict__ s0p,
    const float* __restrict__ b1,
    const float* __restrict__ s1p,
    const float* __restrict__ wcls,
    const float* __restrict__ xtv) {
    __shared__ __align__(16) float svec[2][256];
    __shared__ __align__(16) float shv [2][256];
    __shared__ float part[2][512];
    __shared__ float redA[2][8];
    __shared__ float redB[2][8];
    __shared__ float a0sh[2];
    __shared__ float ybcP[2];
    __shared__ float ybcQ[2];

    if (blockIdx.x >= NB_) {
        helper_work(wcls, xtv, blockIdx.x - NB_, &svec[0][0]);
        return;
    }

    int tid  = threadIdx.x;
    int col  = tid & 255;
    int half = tid >> 8;
    int wq   = (tid >> 5) & 7;
    int lane = tid & 31;
    int bx   = blockIdx.x;
    float e_s0 = expf(s0p[0]);
    float e_s1 = expf(s1p[0]);
    float bias1 = b1[col];
    float bias0 = b0[col];
    float w1r0 = g_W1P[col << 2];   // W1 row k=0, this col
    float w0r0 = g_W0P[col << 2];   // W0 row k=0, this col

    const ulonglong2* w1p = (const ulonglong2*)g_W1P + half * 32 * 256 + col;
    const ulonglong2* w0p = (const ulonglong2*)g_W0P + half * 32 * 256 + col;

    // prefetch step-0 indices
    int   pid[K_]; float pw[K_]; int pwid;
    {
        int e0 = bx * 2 + half;
        #pragma unroll
        for (int k = 0; k < K_; k++) { pid[k] = nhi[e0 * K_ + k]; pw[k] = nhw[e0 * K_ + k]; }
        pwid = wid[e0];
    }

    for (int t = 0; t < T_; t++) {
        int e = t * M_ + bx * 2 + half;   // this half's row

        // barrier-independent loads
        float embv = g_embW1[pwid * H_ + col];
        float cx0  = emb[pwid * H_];

        // ---- phase 1: gathered midpoint (UNSCALED), one sync --------------
        {
            float wsum = 0.f, a = 0.f;
            #pragma unroll
            for (int k = 0; k < K_; k++) {
                wsum += pw[k];
                a += pw[k] * g_h1buf[pid[k] * H_ + col];
            }
            a /= fmaxf(wsum, 1e-8f);
            float v = (col == 0) ? a * a : -a * a;
            #pragma unroll
            for (int o = 16; o > 0; o >>= 1) v += __shfl_down_sync(0xffffffffu, v, o);
            if (lane == 0) redA[half][wq] = v;
            if (col == 0) { a0sh[half] = a; svec[half][0] = 0.f; }
            else          svec[half][col] = a;
        }
        __syncthreads();

        // ---- phase 2 GEMM on unscaled svec (FFMA2) -------------------------
        unsigned long long acc0 = 0ull, acc1 = 0ull;
        {
            const ulonglong2* s0v = (const ulonglong2*)&svec[0][half * 128];
            const ulonglong2* s1v = (const ulonglong2*)&svec[1][half * 128];
            #pragma unroll 8
            for (int i4 = 0; i4 < 32; i4++) {
                ulonglong2 w = w1p[i4 * 256];
                ulonglong2 x0 = s0v[i4], x1 = s1v[i4];
                ffma2(acc0, w.x, x0.x); ffma2(acc0, w.y, x0.y);
                ffma2(acc1, w.x, x1.x); ffma2(acc1, w.y, x1.y);
            }
        }
        part[0][tid] = unpack_sum(acc0);
        part[1][tid] = unpack_sum(acc1);
        __syncthreads();

        // ---- epi2: apply deferred midpoint scale, produce unscaled y2 ------
        float y2;
        {
            float inn = 0.f;
            #pragma unroll
            for (int w8 = 0; w8 < 8; w8++) inn += redA[half][w8];
            float s = 1.0f / sqrtf(fmaxf(inn, 1e-8f));
            float a0 = a0sh[half];
            float h1m0 = a0 * s;
            float x0t = sqrtf(fmaxf(cx0 * cx0 + h1m0 * h1m0 - 1.0f, 1e-8f));
            float psum = part[half][col] + part[half][256 + col];
            y2 = s * psum + w1r0 * x0t + bias1 + embv;
            float v = (col == 0) ? 0.f : y2 * y2;
            #pragma unroll
            for (int o = 16; o > 0; o >>= 1) v += __shfl_down_sync(0xffffffffu, v, o);
            if (lane == 0) redB[half][wq] = v;
            if (col == 0) { ybcP[half] = y2; shv[half][0] = 0.f; }
            else          shv[half][col] = y2;
        }
        __syncthreads();

        // ---- phase 3 GEMM on unscaled y (FFMA2) ----------------------------
        unsigned long long acc2 = 0ull, acc3 = 0ull;
        {
            const ulonglong2* s0v = (const ulonglong2*)&shv[0][half * 128];
            const ulonglong2* s1v = (const ulonglong2*)&shv[1][half * 128];
            #pragma unroll 8
            for (int i4 = 0; i4 < 32; i4++) {
                ulonglong2 w = w0p[i4 * 256];
                ulonglong2 x0 = s0v[i4], x1 = s1v[i4];
                ffma2(acc2, w.x, x0.x); ffma2(acc2, w.y, x0.y);
                ffma2(acc3, w.x, x1.x); ffma2(acc3, w.y, x1.y);
            }
        }
        part[0][tid] = unpack_sum(acc2);
        part[1][tid] = unpack_sum(acc3);
        __syncthreads();

        // ---- epi3: finish llinear(W1) (write hbuf) + llinear(W0) ----------
        float y3;
        {
            float ss2 = 0.f;
            #pragma unroll
            for (int w8 = 0; w8 < 8; w8++) ss2 += redB[half][w8];
            float time2 = e_s1 / (1.f + expf(-ybcP[half])) + 1.1f;
            float sc2 = sqrtf((time2 * time2 - 1.f) / fmaxf(ss2, 1e-8f));
            g_hbuf[e * H_ + col] = (col == 0) ? time2 : y2 * sc2;
            float psum = part[half][col] + part[half][256 + col];
            y3 = sc2 * psum + w0r0 * time2 + bias0;
            float v = (col == 0) ? 0.f : y3 * y3;
            #pragma unroll
            for (int o = 16; o > 0; o >>= 1) v += __shfl_down_sync(0xffffffffu, v, o);
            if (lane == 0) redA[half][wq] = v;
            if (col == 0) ybcQ[half] = y3;
        }
        __syncthreads();
        {
            float ss3 = 0.f;
            #pragma unroll
            for (int w8 = 0; w8 < 8; w8++) ss3 += redA[half][w8];
            float time3 = e_s0 / (1.f + expf(-ybcQ[half])) + 1.1f;
            float sc3 = sqrtf((time3 * time3 - 1.f) / fmaxf(ss3, 1e-8f));
            g_h1buf[e * H_ + col] = (col == 0) ? time3 : y3 * sc3;
        }

        // prefetch next step's indices (barrier-independent)
        if (t + 1 < T_) {
            int en = (t + 1) * M_ + bx * 2 + half;
            #pragma unroll
            for (int k = 0; k < K_; k++) { pid[k] = nhi[en * K_ + k]; pw[k] = nhw[en * K_ + k]; }
            pwid = wid[en];
        }

        // ---- grid barrier -------------------------------------------------
        __threadfence();
        __syncthreads();
        if (tid == 0) {
            atomicAdd((int*)&g_bar[t], 1);
            while (g_bar[t] < NB_) __nanosleep(64);
        }
        __syncthreads();
    }
}

// -------- fused X-build + centroid scores GEMM (K=256, FFMA2) + CE --------
__global__ void __launch_bounds__(256) scores_ce_kernel(
    const float* __restrict__ wbias,
    const int*   __restrict__ bidx,
    const int*   __restrict__ dir,
    const int*   __restrict__ ptg,
    const int*   __restrict__ rwid,
    const float* __restrict__ xtv) {
    extern __shared__ float dsm[];
    float* xs  = dsm;                // [16][256]
    float* scr = dsm + 16 * 256;     // [16][788]
    __shared__ int sbid[16];
    __shared__ float sh_loss, sh_hit, sh_mask;
    int rb = blockIdx.x * 16, tid = threadIdx.x;
    if (tid == 0) { sh_loss = 0.f; sh_hit = 0.f; sh_mask = 0.f; }
    for (int idx = tid; idx < 16 * 256; idx += 256) {
        int row = rb + (idx >> 8);
        xs[idx] = (row < E_) ? g_hbuf[row * H_ + (idx & 255)] : 0.f;
    }
    if (tid < 16) {
        int row = rb + tid;
        sbid[tid] = (row < E_) ? bidx[row] : (row - E_);
    }
    __syncthreads();
    if (tid < 16) {   // fix col 0 (concat time component)
        int row = rb + tid;
        float c0 = xtv[sbid[tid] * L_];
        float n0 = (row < E_) ? xs[tid * 256] : 1.f;
        xs[tid * 256] = sqrtf(fmaxf(n0 * n0 + c0 * c0 - 1.f, 1e-8f));
    }
    __syncthreads();

    const ulonglong2* gp = (const ulonglong2*)g_GtP;
    for (int cc = 0; cc < 4; cc++) {
        int colv = cc * 256 + tid;
        if (colv < V_) {
            unsigned long long acc[16];
            #pragma unroll
            for (int r = 0; r < 16; r++) acc[r] = 0ull;
            #pragma unroll 4
            for (int i4 = 0; i4 < 64; i4++) {
                ulonglong2 g = gp[i4 * V_ + colv];
                #pragma unroll
                for (int r = 0; r < 16; r++) {
                    ulonglong2 xv = *(const ulonglong2*)&xs[r * 256 + i4 * 4];
                    ffma2(acc[r], g.x, xv.x);
                    ffma2(acc[r], g.y, xv.y);
                }
            }
            float bb = wbias[colv];
            #pragma unroll
            for (int r = 0; r < 16; r++) {
                float cg = g_ctxG[sbid[r] * V_ + colv];
                scr[r * 788 + colv] = 2.f + 2.f * (unpack_sum(acc[r]) + cg) + bb;
            }
        }
    }
    __syncthreads();

    int w = tid >> 5, lane = tid & 31;
    #pragma unroll
    for (int rr = 0; rr < 2; rr++) {
        int r = w * 2 + rr;
        int row = rb + r;
        const float* s = scr + r * 788;
        float mx = -1e30f; int mi = 0x7fffffff;
        for (int j = lane; j < V_; j += 32) {
            float v = s[j];
            if (v > mx) { mx = v; mi = j; }
        }
        #pragma unroll
        for (int o = 16; o > 0; o >>= 1) {
            float om = __shfl_down_sync(0xffffffffu, mx, o);
            int   oi = __shfl_down_sync(0xffffffffu, mi, o);
            if (om > mx || (om == mx && oi < mi)) { mx = om; mi = oi; }
        }
        mx = __shfl_sync(0xffffffffu, mx, 0);
        mi = __shfl_sync(0xffffffffu, mi, 0);
        float p = 0.f;
        for (int j = lane; j < V_; j += 32) p += __expf(s[j] - mx);
        #pragma unroll
        for (int o = 16; o > 0; o >>= 1) p += __shfl_down_sync(0xffffffffu, p, o);
        if (lane == 0) {
            float lse = mx + logf(p);
            float pm_l = (row < E_) ? (float)dir[row] : 1.f;
            float pm_m = (row < E_) ? pm_l : 0.f;
            int tgt = (row < E_) ? ptg[row] : rwid[row - E_];
            float ce = lse - s[tgt];
            atomicAdd(&sh_loss, pm_l * ce);
            atomicAdd(&sh_hit,  pm_l * ((mi == tgt) ? 1.f : 0.f));
            atomicAdd(&sh_mask, pm_m);
        }
    }
    __syncthreads();
    if (tid == 0) {
        atomicAdd(&g_acc[0], (double)sh_loss);
        atomicAdd(&g_acc[1], (double)sh_hit);
        atomicAdd(&g_acc[2], (double)sh_mask);
    }
}

// ------------------------- stop head (4 rows/block) ------------------------
__global__ void stop_kernel(const int*   __restrict__ wid,
                            const int*   __restrict__ noi,
                            const float* __restrict__ now,
                            const int*   __restrict__ bidx,
                            const int*   __restrict__ dir,
                            const int*   __restrict__ rwid,
                            const int*   __restrict__ roi,
                            const float* __restrict__ row_w,
                            const float* __restrict__ xtv,
                            const float* __restrict__ emb,
                            const float* __restrict__ ucls,
                            const float* __restrict__ ubias) {
    __shared__ float red[32];
    __shared__ float s_ce, s_hit;
    int tid = threadIdx.x;
    if (tid == 0) { s_ce = 0.f; s_hit = 0.f; }
    float u0a = ucls[tid];
    float u0b = ucls[255 + tid];
    float u1a = ucls[DS_ + tid];
    float u1b = ucls[DS_ + 255 + tid];
    float u0c = (tid > 0 && tid < L_) ? ucls[510 + tid] : 0.f;
    float u1c = (tid > 0 && tid < L_) ? ucls[DS_ + 510 + tid] : 0.f;
    float ub0 = ubias[0], ub1 = ubias[1];

    for (int rr = 0; rr < 4; rr++) {
        int row = blockIdx.x * 4 + rr;
        int widx, tgt;
        const int* oidx; const float* ow; const float* ctx;
        if (row < E_) {
            widx = wid[row]; tgt = dir[row];
            oidx = noi + row * K_; ow = now + row * K_;
            ctx = xtv + bidx[row] * L_;
        } else {
            int b = row - E_;
            widx = rwid[b]; tgt = 0;
            oidx = roi + b * K_; ow = row_w + b * K_;
            ctx = xtv + b * L_;
        }
        float wsum = 0.f, a = 0.f;
        #pragma unroll
        for (int k = 0; k < K_; k++) {
            int id = oidx[k]; float w = ow[k];
            wsum += w;
            a += w * g_hbuf[id * H_ + tid];
        }
        a /= fmaxf(wsum, 1e-8f);
        float inner = blockReduceSum((tid == 0) ? -a * a : a * a, red);
        float co = a / sqrtf(fmaxf(-inner, 1e-8f));
        float cx = emb[widx * H_ + tid];
        float d0, d1;
        if (tid == 0) {
            float t2s = fmaxf(cx * cx + co * co - 1.f, 1e-8f);
            float c0 = ctx[0];
            float x0 = sqrtf(fmaxf(t2s + c0 * c0 - 1.f, 1e-8f));
            d0 = -x0 * u0a;
            d1 = -x0 * u1a;
        } else {
            d0 = cx * u0a + co * u0b;
            d1 = cx * u1a + co * u1b;
            if (tid < L_) {
                float cv = ctx[tid];
                d0 += cv * u0c;
                d1 += cv * u1c;
            }
        }
        float sc0 = blockReduceSum(d0, red);
        float sc1 = blockReduceSum(d1, red);
        if (tid == 0) {
            sc0 = 2.f + 2.f * sc0 + ub0;
            sc1 = 2.f + 2.f * sc1 + ub1;
            float mxv = fmaxf(sc0, sc1);
            float lse = mxv + logf(expf(sc0 - mxv) + expf(sc1 - mxv));
            s_ce += lse - ((tgt == 0) ? sc0 : sc1);
            int am = (sc1 > sc0) ? 1 : 0;
            s_hit += (am == tgt) ? 1.f : 0.f;
        }
    }
    __syncthreads();
    if (tid == 0) {
        atomicAdd(&g_acc[3], (double)s_ce);
        atomicAdd(&g_acc[4], (double)s_hit);
    }
}

// ------------------------- finalize ---------------------------------------
__global__ void finalize(float* __restrict__ out) {
    out[0] = (float)(g_acc[0] / (double)B_);
    out[1] = (float)(g_acc[3] / (double)B_);
    out[2] = (float)(g_acc[1] / ((double)B_ + g_acc[2]));
    out[3] = (float)(g_acc[4] / (double)(E_ + B_));
}

// ------------------------- launch ------------------------------------------
extern "C" void kernel_launch(void* const* d_in, const int* in_sizes, int n_in,
                              void* d_out, int out_size) {
    const int*   wid   = (const int*)  d_in[0];
    const int*   nhi   = (const int*)  d_in[1];
    const float* nhw   = (const float*)d_in[2];
    const int*   noi   = (const int*)  d_in[3];
    const float* now_  = (const float*)d_in[4];
    const int*   bidx  = (const int*)  d_in[5];
    const int*   dir   = (const int*)  d_in[6];
    const int*   ptg   = (const int*)  d_in[7];
    const int*   rwid  = (const int*)  d_in[8];
    const int*   roi   = (const int*)  d_in[9];
    const float* row_w = (const float*)d_in[10];
    const float* xtv   = (const float*)d_in[11];
    const float* emb   = (const float*)d_in[12];
    const float* W0    = (const float*)d_in[13];
    const float* b0    = (const float*)d_in[14];
    const float* s0    = (const float*)d_in[15];
    const float* W1    = (const float*)d_in[16];
    const float* b1    = (const float*)d_in[17];
    const float* s1    = (const float*)d_in[18];
    const float* wcls  = (const float*)d_in[19];
    const float* wbias = (const float*)d_in[20];
    const float* ucls  = (const float*)d_in[21];
    const float* ubias = (const float*)d_in[22];
    float* out = (float*)d_out;

    const int smem_ce = (16 * 256 + 16 * 788) * sizeof(float);  // ~66 KB
    cudaFuncSetAttribute(scores_ce_kernel,
                         cudaFuncAttributeMaxDynamicSharedMemorySize, smem_ce);

    prep_misc<<<512, 256>>>(W0, W1);
    prep_pad<<<1, 256>>>(W0, b0, s0);
    prep_embW1<<<(V_ + 15) / 16, 256>>>(emb);
    scan_kernel<<<NTOT_, 512>>>(wid, nhi, nhw, emb, b0, s0, b1, s1, wcls, xtv);
    scores_ce_kernel<<<NROWS / 16, 256, smem_ce>>>(wbias, bidx, dir, ptg, rwid, xtv);
    stop_kernel<<<NROWS / 4, 256>>>(wid, noi, now_, bidx, dir, rwid, roi, row_w,
                                    xtv, emb, ucls, ubias);
    finalize<<<1, 1>>>(out);
}

// round 14
// speedup vs baseline: 1.2672x; 1.0214x over previous
#include <cuda_runtime.h>
#include <math.h>

#define T_ 64
#define M_ 256
#define K_ 6
#define B_ 256
#define H_ 256
#define L_ 128
#define V_ 780
#define E_ 16384
#define DC_ 383          // wcls cols = H+L-1
#define DS_ 638          // ucls cols = 2H+L-2
#define NROWS (E_ + B_)  // msg rows + root rows
#define NB_ 128          // scan worker blocks (barrier count)
#define NH_ 20           // helper blocks -> total grid 148
#define NTOT_ (NB_ + NH_)

// ------------------------- device scratch --------------------------------
__device__ __align__(16) float  g_hbuf [(E_ + 1) * H_];
__device__ __align__(16) float  g_h1buf[(E_ + 1) * H_];
__device__ __align__(16) float  g_W1T  [512 * H_];      // for embW1 prep
__device__ __align__(16) float  g_W1P  [H_ * H_];       // packed: [(k>>2)*256+col]*4+(k&3)
__device__ __align__(16) float  g_W0P  [H_ * H_];       // packed W0^T
__device__ __align__(16) float  g_embW1[V_ * H_];       // emb_spatial @ W1^T_spatial
__device__ __align__(16) float  g_GtP  [256 * V_];      // packed rows 0..255
__device__ __align__(16) float  g_GtC  [128 * V_];      // packed ctx rows 256..383
__device__ __align__(16) float  g_ctxG [B_ * V_];       // ctx_spatial(b) . Gt[256..382]
__device__ double g_acc[6];
__device__ volatile int g_bar[T_];
__device__ volatile int g_hbar;

// ------------------------- helpers ---------------------------------------
__device__ __forceinline__ void ffma2(unsigned long long& d,
                                      unsigned long long a,
                                      unsigned long long b) {
    asm("fma.rn.f32x2 %0, %1, %2, %0;" : "+l"(d) : "l"(a), "l"(b));
}
__device__ __forceinline__ float unpack_sum(unsigned long long v) {
    float lo, hi;
    asm("mov.b64 {%0,%1}, %2;" : "=f"(lo), "=f"(hi) : "l"(v));
    return lo + hi;
}

__device__ __forceinline__ float blockReduceSum(float v, float* sh) {
    __syncthreads();
    #pragma unroll
    for (int o = 16; o > 0; o >>= 1) v += __shfl_down_sync(0xffffffffu, v, o);
    int tid = threadIdx.x;
    if ((tid & 31) == 0) sh[tid >> 5] = v;
    __syncthreads();
    if (tid < 32) {
        int nw = (blockDim.x + 31) >> 5;
        v = (tid < nw) ? sh[tid] : 0.f;
        #pragma unroll
        for (int o = 16; o > 0; o >>= 1) v += __shfl_down_sync(0xffffffffu, v, o);
        if (tid == 0) sh[0] = v;
    }
    __syncthreads();
    return sh[0];
}

__device__ __forceinline__ float gt_val(int i, int v, const float* wcls) {
    if (i == 0)  return -wcls[v * DC_];
    if (i < DC_) return wcls[v * DC_ + i];
    return 0.f;
}

// ------------------------- prep (weights only) -----------------------------
__global__ void prep_misc(const float* __restrict__ W0,
                          const float* __restrict__ W1) {
    if (blockIdx.x == 0) {
        if (threadIdx.x < T_) g_bar[threadIdx.x] = 0;
        if (threadIdx.x == 0) g_hbar = 0;
    }
    const int n1 = 512 * H_;        // W1T
    const int n2 = H_ * H_;         // W1P
    const int n3 = H_ * H_;         // W0P
    for (int idx = blockIdx.x * blockDim.x + threadIdx.x;
         idx < n1 + n2 + n3; idx += gridDim.x * blockDim.x) {
        if (idx < n1) {
            int i = idx >> 8, j = idx & 255;
            g_W1T[idx] = (i < 511) ? W1[j * 511 + i] : 0.f;
        } else if (idx < n1 + n2) {
            int k = idx - n1;
            int i = k >> 8, j = k & 255;
            float val = (i == 0) ? W1[j * 511] : W1[j * 511 + 255 + i];
            g_W1P[((i >> 2) << 10) + (j << 2) + (i & 3)] = val;
        } else {
            int k = idx - n1 - n2;
            int i = k >> 8, j = k & 255;
            g_W0P[((i >> 2) << 10) + (j << 2) + (i & 3)] = W0[j * H_ + i];
        }
    }
}

__global__ void prep_pad(const float* __restrict__ W0,
                         const float* __restrict__ b0,
                         const float* __restrict__ s0p) {
    __shared__ float red[32];
    __shared__ float ybc;
    int tid = threadIdx.x;
    if (tid < 6) g_acc[tid] = 0.0;
    g_hbuf[E_ * H_ + tid] = (tid == 0) ? 1.f : 0.f;
    float y = W0[tid * H_] + b0[tid];
    if (tid == 0) ybc = y;
    float ss = blockReduceSum((tid == 0) ? 0.f : y * y, red);
    float time = expf(s0p[0]) / (1.f + expf(-ybc)) + 1.1f;
    float sc = sqrtf((time * time - 1.f) / fmaxf(ss, 1e-8f));
    g_h1buf[E_ * H_ + tid] = (tid == 0) ? time : y * sc;
}

// embW1[v][j] = sum_{i=1..255} emb[v][i] * W1T[i][j]
__global__ void prep_embW1(const float* __restrict__ emb) {
    __shared__ float es[16][256];
    int v0 = blockIdx.x * 16, tid = threadIdx.x;
    for (int i = tid; i < 16 * 256; i += 256) {
        int r = i >> 8, c = i & 255;
        es[r][c] = (v0 + r < V_) ? emb[(v0 + r) * H_ + c] : 0.f;
    }
    __syncthreads();
    float acc[16];
    #pragma unroll
    for (int r = 0; r < 16; r++) acc[r] = 0.f;
    for (int i = 1; i < 256; i++) {
        float w = g_W1T[i * H_ + tid];
        #pragma unroll
        for (int r = 0; r < 16; r++) acc[r] += es[r][i] * w;
    }
    #pragma unroll
    for (int r = 0; r < 16; r++)
        if (v0 + r < V_) g_embW1[(v0 + r) * H_ + tid] = acc[r];
}

// ------------- helper-block work (runs concurrently with the scan) ---------
__device__ void helper_work(const float* __restrict__ wcls,
                            const float* __restrict__ xtv,
                            int hb, float* cs) {
    int tid = threadIdx.x;   // 512 threads
    for (int idx = hb * 512 + tid; idx < 128 * V_; idx += NH_ * 512) {
        int j = idx / V_, v = idx - j * V_;
        g_GtC[(((j >> 2) * V_ + v) << 2) + (j & 3)] = gt_val(256 + j, v, wcls);
    }
    __threadfence();
    __syncthreads();
    if (tid == 0) {
        atomicAdd((int*)&g_hbar, 1);
        while (g_hbar < NH_) __nanosleep(128);
    }
    __syncthreads();
    const float4* gc = (const float4*)g_GtC;
    for (int b = hb; b < B_; b += NH_) {
        if (tid < 128) cs[tid] = (tid < 127) ? xtv[b * L_ + 1 + tid] : 0.f;
        __syncthreads();
        const float4* cv = (const float4*)cs;
        for (int v = tid; v < V_; v += 512) {
            float acc = 0.f;
            #pragma unroll 8
            for (int j4 = 0; j4 < 32; j4++) {
                float4 g = gc[j4 * V_ + v];
                float4 c = cv[j4];
                acc += g.x * c.x + g.y * c.y + g.z * c.z + g.w * c.w;
            }
            g_ctxG[b * V_ + v] = acc;
        }
        __syncthreads();
    }
    for (int idx = hb * 512 + tid; idx < 256 * V_; idx += NH_ * 512) {
        int i = idx / V_, v = idx - i * V_;
        g_GtP[(((i >> 2) * V_ + v) << 2) + (i & 3)] = gt_val(i, v, wcls);
    }
}

// ------------------------- persistent scan kernel -------------------------
// grid = 148: blocks 0..127 scan; 128..147 helper prep.
// Weight feed split across LDS (smem-cached k-rows) and LDG pipes:
//   smem holds W1P k-rows 0..127 (128 KB) + W0P k-rows 0..63 (64 KB).
__global__ void __launch_bounds__(512, 1) scan_kernel(
    const int*   __restrict__ wid,
    const int*   __restrict__ nhi,
    const float* __restrict__ nhw,
    const float* __restrict__ emb,
    const float* __restrict__ b0,
    const float* __restrict__ s0p,
    const float* __restrict__ b1,
    const float* __restrict__ s1p,
    const float* __restrict__ wcls,
    const float* __restrict__ xtv) {
    extern __shared__ __align__(16) float dynsm[];
    float* sW1 = dynsm;               // 32768 floats (k 0..127 of W1P)
    float* sW0 = dynsm + 32768;       // 16384 floats (k 0..63 of W0P)

    __shared__ __align__(16) float svec[2][256];
    __shared__ __align__(16) float shv [2][256];
    __shared__ float part[2][512];
    __shared__ float redA[2][8];
    __shared__ float redB[2][8];
    __shared__ float a0sh[2];
    __shared__ float ybcP[2];
    __shared__ float ybcQ[2];

    if (blockIdx.x >= NB_) {
        helper_work(wcls, xtv, blockIdx.x - NB_, &svec[0][0]);
        return;
    }

    int tid  = threadIdx.x;
    int col  = tid & 255;
    int half = tid >> 8;
    int wq   = (tid >> 5) & 7;
    int lane = tid & 31;
    int bx   = blockIdx.x;
    float e_s0 = expf(s0p[0]);
    float e_s1 = expf(s1p[0]);
    float bias1 = b1[col];
    float bias0 = b0[col];
    float w1r0 = g_W1P[col << 2];
    float w0r0 = g_W0P[col << 2];

    // preload smem weight caches (coalesced float4)
    {
        const float4* w1g = (const float4*)g_W1P;
        const float4* w0g = (const float4*)g_W0P;
        float4* d1 = (float4*)sW1;
        float4* d0 = (float4*)sW0;
        for (int i = tid; i < 8192; i += 512) d1[i] = w1g[i];
        for (int i = tid; i < 4096; i += 512) d0[i] = w0g[i];
    }
    __syncthreads();

    // prefetch step-0 indices
    int   pid[K_]; float pw[K_]; int pwid;
    {
        int e0 = bx * 2 + half;
        #pragma unroll
        for (int k = 0; k < K_; k++) { pid[k] = nhi[e0 * K_ + k]; pw[k] = nhw[e0 * K_ + k]; }
        pwid = wid[e0];
    }

    for (int t = 0; t < T_; t++) {
        int e = t * M_ + bx * 2 + half;

        float embv = g_embW1[pwid * H_ + col];
        float cx0  = emb[pwid * H_];

        // ---- phase 1: gathered midpoint (unscaled), one sync --------------
        {
            float wsum = 0.f, a = 0.f;
            #pragma unroll
            for (int k = 0; k < K_; k++) {
                wsum += pw[k];
                a += pw[k] * g_h1buf[pid[k] * H_ + col];
            }
            a /= fmaxf(wsum, 1e-8f);
            float v = (col == 0) ? a * a : -a * a;
            #pragma unroll
            for (int o = 16; o > 0; o >>= 1) v += __shfl_down_sync(0xffffffffu, v, o);
            if (lane == 0) redA[half][wq] = v;
            if (col == 0) { a0sh[half] = a; svec[half][0] = 0.f; }
            else          svec[half][col] = a;
        }
        __syncthreads();

        // ---- phase 2 GEMM: half0 from smem (LDS), half1 from gmem (LDG) ---
        unsigned long long acc0 = 0ull, acc1 = 0ull;
        {
            const ulonglong2* s0v = (const ulonglong2*)&svec[0][half * 128];
            const ulonglong2* s1v = (const ulonglong2*)&svec[1][half * 128];
            if (half == 0) {
                const ulonglong2* w = (const ulonglong2*)sW1 + col;
                #pragma unroll 8
                for (int i4 = 0; i4 < 32; i4++) {
                    ulonglong2 wv = w[i4 * 256];
                    ulonglong2 x0 = s0v[i4], x1 = s1v[i4];
                    ffma2(acc0, wv.x, x0.x); ffma2(acc0, wv.y, x0.y);
                    ffma2(acc1, wv.x, x1.x); ffma2(acc1, wv.y, x1.y);
                }
            } else {
                const ulonglong2* w = (const ulonglong2*)g_W1P + 32 * 256 + col;
                #pragma unroll 8
                for (int i4 = 0; i4 < 32; i4++) {
                    ulonglong2 wv = w[i4 * 256];
                    ulonglong2 x0 = s0v[i4], x1 = s1v[i4];
                    ffma2(acc0, wv.x, x0.x); ffma2(acc0, wv.y, x0.y);
                    ffma2(acc1, wv.x, x1.x); ffma2(acc1, wv.y, x1.y);
                }
            }
        }
        part[0][tid] = unpack_sum(acc0);
        part[1][tid] = unpack_sum(acc1);
        __syncthreads();

        // ---- epi2: deferred midpoint scale, produce unscaled y2 ------------
        float y2;
        {
            float inn = 0.f;
            #pragma unroll
            for (int w8 = 0; w8 < 8; w8++) inn += redA[half][w8];
            float s = 1.0f / sqrtf(fmaxf(inn, 1e-8f));
            float a0 = a0sh[half];
            float h1m0 = a0 * s;
            float x0t = sqrtf(fmaxf(cx0 * cx0 + h1m0 * h1m0 - 1.0f, 1e-8f));
            float psum = part[half][col] + part[half][256 + col];
            y2 = s * psum + w1r0 * x0t + bias1 + embv;
            float v = (col == 0) ? 0.f : y2 * y2;
            #pragma unroll
            for (int o = 16; o > 0; o >>= 1) v += __shfl_down_sync(0xffffffffu, v, o);
            if (lane == 0) redB[half][wq] = v;
            if (col == 0) { ybcP[half] = y2; shv[half][0] = 0.f; }
            else          shv[half][col] = y2;
        }
        __syncthreads();

        // ---- phase 3 GEMM: half0 = smem(k<64)+gmem(k 64..127); half1 gmem --
        unsigned long long acc2 = 0ull, acc3 = 0ull;
        {
            const ulonglong2* s0v = (const ulonglong2*)&shv[0][half * 128];
            const ulonglong2* s1v = (const ulonglong2*)&shv[1][half * 128];
            if (half == 0) {
                const ulonglong2* ws = (const ulonglong2*)sW0 + col;
                #pragma unroll 8
                for (int i4 = 0; i4 < 16; i4++) {
                    ulonglong2 wv = ws[i4 * 256];
                    ulonglong2 x0 = s0v[i4], x1 = s1v[i4];
                    ffma2(acc2, wv.x, x0.x); ffma2(acc2, wv.y, x0.y);
                    ffma2(acc3, wv.x, x1.x); ffma2(acc3, wv.y, x1.y);
                }
                const ulonglong2* wg = (const ulonglong2*)g_W0P + 16 * 256 + col;
                #pragma unroll 8
                for (int i4 = 0; i4 < 16; i4++) {
                    ulonglong2 wv = wg[i4 * 256];
                    ulonglong2 x0 = s0v[16 + i4], x1 = s1v[16 + i4];
                    ffma2(acc2, wv.x, x0.x); ffma2(acc2, wv.y, x0.y);
                    ffma2(acc3, wv.x, x1.x); ffma2(acc3, wv.y, x1.y);
                }
            } else {
                const ulonglong2* wg = (const ulonglong2*)g_W0P + 32 * 256 + col;
                #pragma unroll 8
                for (int i4 = 0; i4 < 32; i4++) {
                    ulonglong2 wv = wg[i4 * 256];
                    ulonglong2 x0 = s0v[i4], x1 = s1v[i4];
                    ffma2(acc2, wv.x, x0.x); ffma2(acc2, wv.y, x0.y);
                    ffma2(acc3, wv.x, x1.x); ffma2(acc3, wv.y, x1.y);
                }
            }
        }
        part[0][tid] = unpack_sum(acc2);
        part[1][tid] = unpack_sum(acc3);
        __syncthreads();

        // ---- epi3: finish llinear(W1) (write hbuf) + llinear(W0) ----------
        float y3;
        {
            float ss2 = 0.f;
            #pragma unroll
            for (int w8 = 0; w8 < 8; w8++) ss2 += redB[half][w8];
            float time2 = e_s1 / (1.f + expf(-ybcP[half])) + 1.1f;
            float sc2 = sqrtf((time2 * time2 - 1.f) / fmaxf(ss2, 1e-8f));
            g_hbuf[e * H_ + col] = (col == 0) ? time2 : y2 * sc2;
            float psum = part[half][col] + part[half][256 + col];
            y3 = sc2 * psum + w0r0 * time2 + bias0;
            float v = (col == 0) ? 0.f : y3 * y3;
            #pragma unroll
            for (int o = 16; o > 0; o >>= 1) v += __shfl_down_sync(0xffffffffu, v, o);
            if (lane == 0) redA[half][wq] = v;
            if (col == 0) ybcQ[half] = y3;
        }
        __syncthreads();
        {
            float ss3 = 0.f;
            #pragma unroll
            for (int w8 = 0; w8 < 8; w8++) ss3 += redA[half][w8];
            float time3 = e_s0 / (1.f + expf(-ybcQ[half])) + 1.1f;
            float sc3 = sqrtf((time3 * time3 - 1.f) / fmaxf(ss3, 1e-8f));
            g_h1buf[e * H_ + col] = (col == 0) ? time3 : y3 * sc3;
        }

        // prefetch next step's indices
        if (t + 1 < T_) {
            int en = (t + 1) * M_ + bx * 2 + half;
            #pragma unroll
            for (int k = 0; k < K_; k++) { pid[k] = nhi[en * K_ + k]; pw[k] = nhw[en * K_ + k]; }
            pwid = wid[en];
        }

        // ---- grid barrier -------------------------------------------------
        __threadfence();
        __syncthreads();
        if (tid == 0) {
            atomicAdd((int*)&g_bar[t], 1);
            while (g_bar[t] < NB_) __nanosleep(64);
        }
        __syncthreads();
    }
}

// -------- fused X-build + centroid scores GEMM (K=256, FFMA2) + CE --------
__global__ void __launch_bounds__(256) scores_ce_kernel(
    const float* __restrict__ wbias,
    const int*   __restrict__ bidx,
    const int*   __restrict__ dir,
    const int*   __restrict__ ptg,
    const int*   __restrict__ rwid,
    const float* __restrict__ xtv) {
    extern __shared__ float dsm[];
    float* xs  = dsm;                // [16][256]
    float* scr = dsm + 16 * 256;     // [16][788]
    __shared__ int sbid[16];
    __shared__ float sh_loss, sh_hit, sh_mask;
    int rb = blockIdx.x * 16, tid = threadIdx.x;
    if (tid == 0) { sh_loss = 0.f; sh_hit = 0.f; sh_mask = 0.f; }
    for (int idx = tid; idx < 16 * 256; idx += 256) {
        int row = rb + (idx >> 8);
        xs[idx] = (row < E_) ? g_hbuf[row * H_ + (idx & 255)] : 0.f;
    }
    if (tid < 16) {
        int row = rb + tid;
        sbid[tid] = (row < E_) ? bidx[row] : (row - E_);
    }
    __syncthreads();
    if (tid < 16) {   // fix col 0 (concat time component)
        int row = rb + tid;
        float c0 = xtv[sbid[tid] * L_];
        float n0 = (row < E_) ? xs[tid * 256] : 1.f;
        xs[tid * 256] = sqrtf(fmaxf(n0 * n0 + c0 * c0 - 1.f, 1e-8f));
    }
    __syncthreads();

    const ulonglong2* gp = (const ulonglong2*)g_GtP;
    for (int cc = 0; cc < 4; cc++) {
        int colv = cc * 256 + tid;
        if (colv < V_) {
            unsigned long long acc[16];
            #pragma unroll
            for (int r = 0; r < 16; r++) acc[r] = 0ull;
            #pragma unroll 4
            for (int i4 = 0; i4 < 64; i4++) {
                ulonglong2 g = gp[i4 * V_ + colv];
                #pragma unroll
                for (int r = 0; r < 16; r++) {
                    ulonglong2 xv = *(const ulonglong2*)&xs[r * 256 + i4 * 4];
                    ffma2(acc[r], g.x, xv.x);
                    ffma2(acc[r], g.y, xv.y);
                }
            }
            float bb = wbias[colv];
            #pragma unroll
            for (int r = 0; r < 16; r++) {
                float cg = g_ctxG[sbid[r] * V_ + colv];
                scr[r * 788 + colv] = 2.f + 2.f * (unpack_sum(acc[r]) + cg) + bb;
            }
        }
    }
    __syncthreads();

    int w = tid >> 5, lane = tid & 31;
    #pragma unroll
    for (int rr = 0; rr < 2; rr++) {
        int r = w * 2 + rr;
        int row = rb + r;
        const float* s = scr + r * 788;
        float mx = -1e30f; int mi = 0x7fffffff;
        for (int j = lane; j < V_; j += 32) {
            float v = s[j];
            if (v > mx) { mx = v; mi = j; }
        }
        #pragma unroll
        for (int o = 16; o > 0; o >>= 1) {
            float om = __shfl_down_sync(0xffffffffu, mx, o);
            int   oi = __shfl_down_sync(0xffffffffu, mi, o);
            if (om > mx || (om == mx && oi < mi)) { mx = om; mi = oi; }
        }
        mx = __shfl_sync(0xffffffffu, mx, 0);
        mi = __shfl_sync(0xffffffffu, mi, 0);
        float p = 0.f;
        for (int j = lane; j < V_; j += 32) p += __expf(s[j] - mx);
        #pragma unroll
        for (int o = 16; o > 0; o >>= 1) p += __shfl_down_sync(0xffffffffu, p, o);
        if (lane == 0) {
            float lse = mx + logf(p);
            float pm_l = (row < E_) ? (float)dir[row] : 1.f;
            float pm_m = (row < E_) ? pm_l : 0.f;
            int tgt = (row < E_) ? ptg[row] : rwid[row - E_];
            float ce = lse - s[tgt];
            atomicAdd(&sh_loss, pm_l * ce);
            atomicAdd(&sh_hit,  pm_l * ((mi == tgt) ? 1.f : 0.f));
            atomicAdd(&sh_mask, pm_m);
        }
    }
    __syncthreads();
    if (tid == 0) {
        atomicAdd(&g_acc[0], (double)sh_loss);
        atomicAdd(&g_acc[1], (double)sh_hit);
        atomicAdd(&g_acc[2], (double)sh_mask);
    }
}

// ------------------------- stop head (4 rows/block) ------------------------
__global__ void stop_kernel(const int*   __restrict__ wid,
                            const int*   __restrict__ noi,
                            const float* __restrict__ now,
                            const int*   __restrict__ bidx,
                            const int*   __restrict__ dir,
                            const int*   __restrict__ rwid,
                            const int*   __restrict__ roi,
                            const float* __restrict__ row_w,
                            const float* __restrict__ xtv,
                            const float* __restrict__ emb,
                            const float* __restrict__ ucls,
                            const float* __restrict__ ubias) {
    __shared__ float red[32];
    __shared__ float s_ce, s_hit;
    int tid = threadIdx.x;
    if (tid == 0) { s_ce = 0.f; s_hit = 0.f; }
    float u0a = ucls[tid];
    float u0b = ucls[255 + tid];
    float u1a = ucls[DS_ + tid];
    float u1b = ucls[DS_ + 255 + tid];
    float u0c = (tid > 0 && tid < L_) ? ucls[510 + tid] : 0.f;
    float u1c = (tid > 0 && tid < L_) ? ucls[DS_ + 510 + tid] : 0.f;
    float ub0 = ubias[0], ub1 = ubias[1];

    for (int rr = 0; rr < 4; rr++) {
        int row = blockIdx.x * 4 + rr;
        int widx, tgt;
        const int* oidx; const float* ow; const float* ctx;
        if (row < E_) {
            widx = wid[row]; tgt = dir[row];
            oidx = noi + row * K_; ow = now + row * K_;
            ctx = xtv + bidx[row] * L_;
        } else {
            int b = row - E_;
            widx = rwid[b]; tgt = 0;
            oidx = roi + b * K_; ow = row_w + b * K_;
            ctx = xtv + b * L_;
        }
        float wsum = 0.f, a = 0.f;
        #pragma unroll
        for (int k = 0; k < K_; k++) {
            int id = oidx[k]; float w = ow[k];
            wsum += w;
            a += w * g_hbuf[id * H_ + tid];
        }
        a /= fmaxf(wsum, 1e-8f);
        float inner = blockReduceSum((tid == 0) ? -a * a : a * a, red);
        float co = a / sqrtf(fmaxf(-inner, 1e-8f));
        float cx = emb[widx * H_ + tid];
        float d0, d1;
        if (tid == 0) {
            float t2s = fmaxf(cx * cx + co * co - 1.f, 1e-8f);
            float c0 = ctx[0];
            float x0 = sqrtf(fmaxf(t2s + c0 * c0 - 1.f, 1e-8f));
            d0 = -x0 * u0a;
            d1 = -x0 * u1a;
        } else {
            d0 = cx * u0a + co * u0b;
            d1 = cx * u1a + co * u1b;
            if (tid < L_) {
                float cv = ctx[tid];
                d0 += cv * u0c;
                d1 += cv * u1c;
            }
        }
        float sc0 = blockReduceSum(d0, red);
        float sc1 = blockReduceSum(d1, red);
        if (tid == 0) {
            sc0 = 2.f + 2.f * sc0 + ub0;
            sc1 = 2.f + 2.f * sc1 + ub1;
            float mxv = fmaxf(sc0, sc1);
            float lse = mxv + logf(expf(sc0 - mxv) + expf(sc1 - mxv));
            s_ce += lse - ((tgt == 0) ? sc0 : sc1);
            int am = (sc1 > sc0) ? 1 : 0;
            s_hit += (am == tgt) ? 1.f : 0.f;
        }
    }
    __syncthreads();
    if (tid == 0) {
        atomicAdd(&g_acc[3], (double)s_ce);
        atomicAdd(&g_acc[4], (double)s_hit);
    }
}

// ------------------------- finalize ---------------------------------------
__global__ void finalize(float* __restrict__ out) {
    out[0] = (float)(g_acc[0] / (double)B_);
    out[1] = (float)(g_acc[3] / (double)B_);
    out[2] = (float)(g_acc[1] / ((double)B_ + g_acc[2]));
    out[3] = (float)(g_acc[4] / (double)(E_ + B_));
}

// ------------------------- launch ------------------------------------------
extern "C" void kernel_launch(void* const* d_in, const int* in_sizes, int n_in,
                              void* d_out, int out_size) {
    const int*   wid   = (const int*)  d_in[0];
    const int*   nhi   = (const int*)  d_in[1];
    const float* nhw   = (const float*)d_in[2];
    const int*   noi   = (const int*)  d_in[3];
    const float* now_  = (const float*)d_in[4];
    const int*   bidx  = (const int*)  d_in[5];
    const int*   dir   = (const int*)  d_in[6];
    const int*   ptg   = (const int*)  d_in[7];
    const int*   rwid  = (const int*)  d_in[8];
    const int*   roi   = (const int*)  d_in[9];
    const float* row_w = (const float*)d_in[10];
    const float* xtv   = (const float*)d_in[11];
    const float* emb   = (const float*)d_in[12];
    const float* W0    = (const float*)d_in[13];
    const float* b0    = (const float*)d_in[14];
    const float* s0    = (const float*)d_in[15];
    const float* W1    = (const float*)d_in[16];
    const float* b1    = (const float*)d_in[17];
    const float* s1    = (const float*)d_in[18];
    const float* wcls  = (const float*)d_in[19];
    const float* wbias = (const float*)d_in[20];
    const float* ucls  = (const float*)d_in[21];
    const float* ubias = (const float*)d_in[22];
    float* out = (float*)d_out;

    const int smem_ce   = (16 * 256 + 16 * 788) * sizeof(float);  // ~66 KB
    const int smem_scan = (32768 + 16384) * sizeof(float);        // 192 KB
    cudaFuncSetAttribute(scores_ce_kernel,
                         cudaFuncAttributeMaxDynamicSharedMemorySize, smem_ce);
    cudaFuncSetAttribute(scan_kernel,
                         cudaFuncAttributeMaxDynamicSharedMemorySize, smem_scan);

    prep_misc<<<512, 256>>>(W0, W1);
    prep_pad<<<1, 256>>>(W0, b0, s0);
    prep_embW1<<<(V_ + 15) / 16, 256>>>(emb);
    scan_kernel<<<NTOT_, 512, smem_scan>>>(wid, nhi, nhw, emb, b0, s0, b1, s1,
                                           wcls, xtv);
    scores_ce_kernel<<<NROWS / 16, 256, smem_ce>>>(wbias, bidx, dir, ptg, rwid, xtv);
    stop_kernel<<<NROWS / 4, 256>>>(wid, noi, now_, bidx, dir, rwid, roi, row_w,
                                    xtv, emb, ucls, ubias);
    finalize<<<1, 1>>>(out);
}

// round 15
// speedup vs baseline: 1.5202x; 1.1996x over previous
#include <cuda_runtime.h>
#include <math.h>

#define T_ 64
#define M_ 256
#define K_ 6
#define B_ 256
#define H_ 256
#define L_ 128
#define V_ 780
#define E_ 16384
#define DC_ 383          // wcls cols = H+L-1
#define DS_ 638          // ucls cols = 2H+L-2
#define NROWS (E_ + B_)  // msg rows + root rows
#define NB_ 128          // scan worker blocks (barrier count)
#define NH_ 20           // helper blocks -> total grid 148
#define NTOT_ (NB_ + NH_)

// ------------------------- device scratch --------------------------------
__device__ __align__(16) float  g_hbuf [(E_ + 1) * H_];
__device__ __align__(16) float  g_h1buf[(E_ + 1) * H_];
__device__ __align__(16) float  g_W1T  [512 * H_];      // for embW1 prep
__device__ __align__(16) float  g_W1P  [H_ * H_];       // packed: [(k>>2)*256+col]*4+(k&3)
__device__ __align__(16) float  g_W0P  [H_ * H_];       // packed W0^T
__device__ __align__(16) float  g_embW1[V_ * H_];       // emb_spatial @ W1^T_spatial
__device__ __align__(16) float  g_GtP  [256 * V_];      // packed rows 0..255
__device__ __align__(16) float  g_GtC  [128 * V_];      // packed ctx rows 256..383
__device__ __align__(16) float  g_ctxG [B_ * V_];       // ctx_spatial(b) . Gt[256..382]
__device__ int    g_rowlist[NROWS];
__device__ int    g_rowcnt;
__device__ double g_acc[6];
__device__ volatile int g_bar[T_];
__device__ volatile int g_hbar;

// ------------------------- helpers ---------------------------------------
__device__ __forceinline__ void ffma2(unsigned long long& d,
                                      unsigned long long a,
                                      unsigned long long b) {
    asm("fma.rn.f32x2 %0, %1, %2, %0;" : "+l"(d) : "l"(a), "l"(b));
}
__device__ __forceinline__ float unpack_sum(unsigned long long v) {
    float lo, hi;
    asm("mov.b64 {%0,%1}, %2;" : "=f"(lo), "=f"(hi) : "l"(v));
    return lo + hi;
}

__device__ __forceinline__ float blockReduceSum(float v, float* sh) {
    __syncthreads();
    #pragma unroll
    for (int o = 16; o > 0; o >>= 1) v += __shfl_down_sync(0xffffffffu, v, o);
    int tid = threadIdx.x;
    if ((tid & 31) == 0) sh[tid >> 5] = v;
    __syncthreads();
    if (tid < 32) {
        int nw = (blockDim.x + 31) >> 5;
        v = (tid < nw) ? sh[tid] : 0.f;
        #pragma unroll
        for (int o = 16; o > 0; o >>= 1) v += __shfl_down_sync(0xffffffffu, v, o);
        if (tid == 0) sh[0] = v;
    }
    __syncthreads();
    return sh[0];
}

__device__ __forceinline__ float gt_val(int i, int v, const float* wcls) {
    if (i == 0)  return -wcls[v * DC_];
    if (i < DC_) return wcls[v * DC_ + i];
    return 0.f;
}

// ------------------------- prep (weights only) -----------------------------
__global__ void prep_misc(const float* __restrict__ W0,
                          const float* __restrict__ W1) {
    if (blockIdx.x == 0) {
        if (threadIdx.x < T_) g_bar[threadIdx.x] = 0;
        if (threadIdx.x == 0) { g_hbar = 0; g_rowcnt = 0; }
    }
    const int n1 = 512 * H_;        // W1T
    const int n2 = H_ * H_;         // W1P
    const int n3 = H_ * H_;         // W0P
    for (int idx = blockIdx.x * blockDim.x + threadIdx.x;
         idx < n1 + n2 + n3; idx += gridDim.x * blockDim.x) {
        if (idx < n1) {
            int i = idx >> 8, j = idx & 255;
            g_W1T[idx] = (i < 511) ? W1[j * 511 + i] : 0.f;
        } else if (idx < n1 + n2) {
            int k = idx - n1;
            int i = k >> 8, j = k & 255;
            float val = (i == 0) ? W1[j * 511] : W1[j * 511 + 255 + i];
            g_W1P[((i >> 2) << 10) + (j << 2) + (i & 3)] = val;
        } else {
            int k = idx - n1 - n2;
            int i = k >> 8, j = k & 255;
            g_W0P[((i >> 2) << 10) + (j << 2) + (i & 3)] = W0[j * H_ + i];
        }
    }
}

// ---- row compaction: keep msg rows with dir==1 and all root rows ----------
__global__ void compact_rows(const int* __restrict__ dir) {
    int i = blockIdx.x * blockDim.x + threadIdx.x;
    bool keep = false;
    if (i < NROWS) keep = (i >= E_) || (dir[i] != 0);
    unsigned m = __ballot_sync(0xffffffffu, keep);
    int lane = threadIdx.x & 31;
    int base = 0;
    if (lane == 0) base = atomicAdd(&g_rowcnt, __popc(m));
    base = __shfl_sync(0xffffffffu, base, 0);
    if (keep) {
        int off = __popc(m & ((1u << lane) - 1u));
        g_rowlist[base + off] = i;
    }
}

__global__ void prep_pad(const float* __restrict__ W0,
                         const float* __restrict__ b0,
                         const float* __restrict__ s0p) {
    __shared__ float red[32];
    __shared__ float ybc;
    int tid = threadIdx.x;
    if (tid < 6) g_acc[tid] = 0.0;
    g_hbuf[E_ * H_ + tid] = (tid == 0) ? 1.f : 0.f;
    float y = W0[tid * H_] + b0[tid];
    if (tid == 0) ybc = y;
    float ss = blockReduceSum((tid == 0) ? 0.f : y * y, red);
    float time = expf(s0p[0]) / (1.f + expf(-ybc)) + 1.1f;
    float sc = sqrtf((time * time - 1.f) / fmaxf(ss, 1e-8f));
    g_h1buf[E_ * H_ + tid] = (tid == 0) ? time : y * sc;
}

// embW1[v][j] = sum_{i=1..255} emb[v][i] * W1T[i][j]
__global__ void prep_embW1(const float* __restrict__ emb) {
    __shared__ float es[16][256];
    int v0 = blockIdx.x * 16, tid = threadIdx.x;
    for (int i = tid; i < 16 * 256; i += 256) {
        int r = i >> 8, c = i & 255;
        es[r][c] = (v0 + r < V_) ? emb[(v0 + r) * H_ + c] : 0.f;
    }
    __syncthreads();
    float acc[16];
    #pragma unroll
    for (int r = 0; r < 16; r++) acc[r] = 0.f;
    for (int i = 1; i < 256; i++) {
        float w = g_W1T[i * H_ + tid];
        #pragma unroll
        for (int r = 0; r < 16; r++) acc[r] += es[r][i] * w;
    }
    #pragma unroll
    for (int r = 0; r < 16; r++)
        if (v0 + r < V_) g_embW1[(v0 + r) * H_ + tid] = acc[r];
}

// ------------- helper-block work (runs concurrently with the scan) ---------
__device__ void helper_work(const float* __restrict__ wcls,
                            const float* __restrict__ xtv,
                            int hb, float* cs) {
    int tid = threadIdx.x;   // 512 threads
    for (int idx = hb * 512 + tid; idx < 128 * V_; idx += NH_ * 512) {
        int j = idx / V_, v = idx - j * V_;
        g_GtC[(((j >> 2) * V_ + v) << 2) + (j & 3)] = gt_val(256 + j, v, wcls);
    }
    __threadfence();
    __syncthreads();
    if (tid == 0) {
        atomicAdd((int*)&g_hbar, 1);
        while (g_hbar < NH_) __nanosleep(128);
    }
    __syncthreads();
    const float4* gc = (const float4*)g_GtC;
    for (int b = hb; b < B_; b += NH_) {
        if (tid < 128) cs[tid] = (tid < 127) ? xtv[b * L_ + 1 + tid] : 0.f;
        __syncthreads();
        const float4* cv = (const float4*)cs;
        for (int v = tid; v < V_; v += 512) {
            float acc = 0.f;
            #pragma unroll 8
            for (int j4 = 0; j4 < 32; j4++) {
                float4 g = gc[j4 * V_ + v];
                float4 c = cv[j4];
                acc += g.x * c.x + g.y * c.y + g.z * c.z + g.w * c.w;
            }
            g_ctxG[b * V_ + v] = acc;
        }
        __syncthreads();
    }
    for (int idx = hb * 512 + tid; idx < 256 * V_; idx += NH_ * 512) {
        int i = idx / V_, v = idx - i * V_;
        g_GtP[(((i >> 2) * V_ + v) << 2) + (i & 3)] = gt_val(i, v, wcls);
    }
}

// ------------------------- persistent scan kernel -------------------------
// grid = 148: blocks 0..127 scan; 128..147 helper prep.
__global__ void __launch_bounds__(512, 1) scan_kernel(
    const int*   __restrict__ wid,
    const int*   __restrict__ nhi,
    const float* __restrict__ nhw,
    const float* __restrict__ emb,
    const float* __restrict__ b0,
    const float* __restrict__ s0p,
    const float* __restrict__ b1,
    const float* __restrict__ s1p,
    const float* __restrict__ wcls,
    const float* __restrict__ xtv) {
    extern __shared__ __align__(16) float dynsm[];
    float* sW1 = dynsm;               // 32768 floats (k 0..127 of W1P)
    float* sW0 = dynsm + 32768;       // 16384 floats (k 0..63 of W0P)

    __shared__ __align__(16) float svec[2][256];
    __shared__ __align__(16) float shv [2][256];
    __shared__ float part[2][512];
    __shared__ float redA[2][8];
    __shared__ float redB[2][8];
    __shared__ float a0sh[2];
    __shared__ float ybcP[2];
    __shared__ float ybcQ[2];

    if (blockIdx.x >= NB_) {
        helper_work(wcls, xtv, blockIdx.x - NB_, &svec[0][0]);
        return;
    }

    int tid  = threadIdx.x;
    int col  = tid & 255;
    int half = tid >> 8;
    int wq   = (tid >> 5) & 7;
    int lane = tid & 31;
    int bx   = blockIdx.x;
    float e_s0 = expf(s0p[0]);
    float e_s1 = expf(s1p[0]);
    float bias1 = b1[col];
    float bias0 = b0[col];
    float w1r0 = g_W1P[col << 2];
    float w0r0 = g_W0P[col << 2];

    {
        const float4* w1g = (const float4*)g_W1P;
        const float4* w0g = (const float4*)g_W0P;
        float4* d1 = (float4*)sW1;
        float4* d0 = (float4*)sW0;
        for (int i = tid; i < 8192; i += 512) d1[i] = w1g[i];
        for (int i = tid; i < 4096; i += 512) d0[i] = w0g[i];
    }
    __syncthreads();

    int   pid[K_]; float pw[K_]; int pwid;
    {
        int e0 = bx * 2 + half;
        #pragma unroll
        for (int k = 0; k < K_; k++) { pid[k] = nhi[e0 * K_ + k]; pw[k] = nhw[e0 * K_ + k]; }
        pwid = wid[e0];
    }

    for (int t = 0; t < T_; t++) {
        int e = t * M_ + bx * 2 + half;

        float embv = g_embW1[pwid * H_ + col];
        float cx0  = emb[pwid * H_];

        // ---- phase 1: gathered midpoint (unscaled), one sync --------------
        {
            float wsum = 0.f, a = 0.f;
            #pragma unroll
            for (int k = 0; k < K_; k++) {
                wsum += pw[k];
                a += pw[k] * g_h1buf[pid[k] * H_ + col];
            }
            a /= fmaxf(wsum, 1e-8f);
            float v = (col == 0) ? a * a : -a * a;
            #pragma unroll
            for (int o = 16; o > 0; o >>= 1) v += __shfl_down_sync(0xffffffffu, v, o);
            if (lane == 0) redA[half][wq] = v;
            if (col == 0) { a0sh[half] = a; svec[half][0] = 0.f; }
            else          svec[half][col] = a;
        }
        __syncthreads();

        // ---- phase 2 GEMM: half0 smem, half1 gmem (FFMA2) ------------------
        unsigned long long acc0 = 0ull, acc1 = 0ull;
        {
            const ulonglong2* s0v = (const ulonglong2*)&svec[0][half * 128];
            const ulonglong2* s1v = (const ulonglong2*)&svec[1][half * 128];
            if (half == 0) {
                const ulonglong2* w = (const ulonglong2*)sW1 + col;
                #pragma unroll 8
                for (int i4 = 0; i4 < 32; i4++) {
                    ulonglong2 wv = w[i4 * 256];
                    ulonglong2 x0 = s0v[i4], x1 = s1v[i4];
                    ffma2(acc0, wv.x, x0.x); ffma2(acc0, wv.y, x0.y);
                    ffma2(acc1, wv.x, x1.x); ffma2(acc1, wv.y, x1.y);
                }
            } else {
                const ulonglong2* w = (const ulonglong2*)g_W1P + 32 * 256 + col;
                #pragma unroll 8
                for (int i4 = 0; i4 < 32; i4++) {
                    ulonglong2 wv = w[i4 * 256];
                    ulonglong2 x0 = s0v[i4], x1 = s1v[i4];
                    ffma2(acc0, wv.x, x0.x); ffma2(acc0, wv.y, x0.y);
                    ffma2(acc1, wv.x, x1.x); ffma2(acc1, wv.y, x1.y);
                }
            }
        }
        part[0][tid] = unpack_sum(acc0);
        part[1][tid] = unpack_sum(acc1);
        __syncthreads();

        // ---- epi2 ----------------------------------------------------------
        float y2;
        {
            float inn = 0.f;
            #pragma unroll
            for (int w8 = 0; w8 < 8; w8++) inn += redA[half][w8];
            float s = 1.0f / sqrtf(fmaxf(inn, 1e-8f));
            float a0 = a0sh[half];
            float h1m0 = a0 * s;
            float x0t = sqrtf(fmaxf(cx0 * cx0 + h1m0 * h1m0 - 1.0f, 1e-8f));
            float psum = part[half][col] + part[half][256 + col];
            y2 = s * psum + w1r0 * x0t + bias1 + embv;
            float v = (col == 0) ? 0.f : y2 * y2;
            #pragma unroll
            for (int o = 16; o > 0; o >>= 1) v += __shfl_down_sync(0xffffffffu, v, o);
            if (lane == 0) redB[half][wq] = v;
            if (col == 0) { ybcP[half] = y2; shv[half][0] = 0.f; }
            else          shv[half][col] = y2;
        }
        __syncthreads();

        // ---- phase 3 GEMM --------------------------------------------------
        unsigned long long acc2 = 0ull, acc3 = 0ull;
        {
            const ulonglong2* s0v = (const ulonglong2*)&shv[0][half * 128];
            const ulonglong2* s1v = (const ulonglong2*)&shv[1][half * 128];
            if (half == 0) {
                const ulonglong2* ws = (const ulonglong2*)sW0 + col;
                #pragma unroll 8
                for (int i4 = 0; i4 < 16; i4++) {
                    ulonglong2 wv = ws[i4 * 256];
                    ulonglong2 x0 = s0v[i4], x1 = s1v[i4];
                    ffma2(acc2, wv.x, x0.x); ffma2(acc2, wv.y, x0.y);
                    ffma2(acc3, wv.x, x1.x); ffma2(acc3, wv.y, x1.y);
                }
                const ulonglong2* wg = (const ulonglong2*)g_W0P + 16 * 256 + col;
                #pragma unroll 8
                for (int i4 = 0; i4 < 16; i4++) {
                    ulonglong2 wv = wg[i4 * 256];
                    ulonglong2 x0 = s0v[16 + i4], x1 = s1v[16 + i4];
                    ffma2(acc2, wv.x, x0.x); ffma2(acc2, wv.y, x0.y);
                    ffma2(acc3, wv.x, x1.x); ffma2(acc3, wv.y, x1.y);
                }
            } else {
                const ulonglong2* wg = (const ulonglong2*)g_W0P + 32 * 256 + col;
                #pragma unroll 8
                for (int i4 = 0; i4 < 32; i4++) {
                    ulonglong2 wv = wg[i4 * 256];
                    ulonglong2 x0 = s0v[i4], x1 = s1v[i4];
                    ffma2(acc2, wv.x, x0.x); ffma2(acc2, wv.y, x0.y);
                    ffma2(acc3, wv.x, x1.x); ffma2(acc3, wv.y, x1.y);
                }
            }
        }
        part[0][tid] = unpack_sum(acc2);
        part[1][tid] = unpack_sum(acc3);
        __syncthreads();

        // ---- epi3 ----------------------------------------------------------
        float y3;
        {
            float ss2 = 0.f;
            #pragma unroll
            for (int w8 = 0; w8 < 8; w8++) ss2 += redB[half][w8];
            float time2 = e_s1 / (1.f + expf(-ybcP[half])) + 1.1f;
            float sc2 = sqrtf((time2 * time2 - 1.f) / fmaxf(ss2, 1e-8f));
            g_hbuf[e * H_ + col] = (col == 0) ? time2 : y2 * sc2;
            float psum = part[half][col] + part[half][256 + col];
            y3 = sc2 * psum + w0r0 * time2 + bias0;
            float v = (col == 0) ? 0.f : y3 * y3;
            #pragma unroll
            for (int o = 16; o > 0; o >>= 1) v += __shfl_down_sync(0xffffffffu, v, o);
            if (lane == 0) redA[half][wq] = v;
            if (col == 0) ybcQ[half] = y3;
        }
        __syncthreads();
        {
            float ss3 = 0.f;
            #pragma unroll
            for (int w8 = 0; w8 < 8; w8++) ss3 += redA[half][w8];
            float time3 = e_s0 / (1.f + expf(-ybcQ[half])) + 1.1f;
            float sc3 = sqrtf((time3 * time3 - 1.f) / fmaxf(ss3, 1e-8f));
            g_h1buf[e * H_ + col] = (col == 0) ? time3 : y3 * sc3;
        }

        if (t + 1 < T_) {
            int en = (t + 1) * M_ + bx * 2 + half;
            #pragma unroll
            for (int k = 0; k < K_; k++) { pid[k] = nhi[en * K_ + k]; pw[k] = nhw[en * K_ + k]; }
            pwid = wid[en];
        }

        __threadfence();
        __syncthreads();
        if (tid == 0) {
            atomicAdd((int*)&g_bar[t], 1);
            while (g_bar[t] < NB_) __nanosleep(64);
        }
        __syncthreads();
    }
}

// -------- fused X-build + centroid scores GEMM + CE (compacted rows) -------
__global__ void __launch_bounds__(256) scores_ce_kernel(
    const float* __restrict__ wbias,
    const int*   __restrict__ bidx,
    const int*   __restrict__ ptg,
    const int*   __restrict__ rwid,
    const float* __restrict__ xtv) {
    extern __shared__ float dsm[];
    float* xs  = dsm;                // [16][256]
    float* scr = dsm + 16 * 256;     // [16][788]
    __shared__ int srow[16];
    __shared__ int sbid[16];
    __shared__ float sh_loss, sh_hit, sh_mask;
    int rb = blockIdx.x * 16, tid = threadIdx.x;
    int cnt = g_rowcnt;
    if (rb >= cnt) return;
    if (tid == 0) { sh_loss = 0.f; sh_hit = 0.f; sh_mask = 0.f; }
    if (tid < 16) {
        int row = (rb + tid < cnt) ? g_rowlist[rb + tid] : -1;
        srow[tid] = row;
        sbid[tid] = (row < 0) ? 0 : ((row < E_) ? bidx[row] : (row - E_));
    }
    __syncthreads();
    for (int idx = tid; idx < 16 * 256; idx += 256) {
        int row = srow[idx >> 8];
        xs[idx] = (row >= 0 && row < E_) ? g_hbuf[row * H_ + (idx & 255)] : 0.f;
    }
    __syncthreads();
    if (tid < 16) {   // fix col 0 (concat time component)
        int row = srow[tid];
        if (row >= 0) {
            float c0 = xtv[sbid[tid] * L_];
            float n0 = (row < E_) ? xs[tid * 256] : 1.f;
            xs[tid * 256] = sqrtf(fmaxf(n0 * n0 + c0 * c0 - 1.f, 1e-8f));
        }
    }
    __syncthreads();

    const ulonglong2* gp = (const ulonglong2*)g_GtP;
    for (int cc = 0; cc < 4; cc++) {
        int colv = cc * 256 + tid;
        if (colv < V_) {
            unsigned long long acc[16];
            #pragma unroll
            for (int r = 0; r < 16; r++) acc[r] = 0ull;
            #pragma unroll 4
            for (int i4 = 0; i4 < 64; i4++) {
                ulonglong2 g = gp[i4 * V_ + colv];
                #pragma unroll
                for (int r = 0; r < 16; r++) {
                    ulonglong2 xv = *(const ulonglong2*)&xs[r * 256 + i4 * 4];
                    ffma2(acc[r], g.x, xv.x);
                    ffma2(acc[r], g.y, xv.y);
                }
            }
            float bb = wbias[colv];
            #pragma unroll
            for (int r = 0; r < 16; r++) {
                float cg = g_ctxG[sbid[r] * V_ + colv];
                scr[r * 788 + colv] = 2.f + 2.f * (unpack_sum(acc[r]) + cg) + bb;
            }
        }
    }
    __syncthreads();

    int w = tid >> 5, lane = tid & 31;
    #pragma unroll
    for (int rr = 0; rr < 2; rr++) {
        int r = w * 2 + rr;
        int row = srow[r];
        if (row < 0) continue;
        const float* s = scr + r * 788;
        float mx = -1e30f; int mi = 0x7fffffff;
        for (int j = lane; j < V_; j += 32) {
            float v = s[j];
            if (v > mx) { mx = v; mi = j; }
        }
        #pragma unroll
        for (int o = 16; o > 0; o >>= 1) {
            float om = __shfl_down_sync(0xffffffffu, mx, o);
            int   oi = __shfl_down_sync(0xffffffffu, mi, o);
            if (om > mx || (om == mx && oi < mi)) { mx = om; mi = oi; }
        }
        mx = __shfl_sync(0xffffffffu, mx, 0);
        mi = __shfl_sync(0xffffffffu, mi, 0);
        float p = 0.f;
        for (int j = lane; j < V_; j += 32) p += __expf(s[j] - mx);
        #pragma unroll
        for (int o = 16; o > 0; o >>= 1) p += __shfl_down_sync(0xffffffffu, p, o);
        if (lane == 0) {
            float lse = mx + logf(p);
            int tgt = (row < E_) ? ptg[row] : rwid[row - E_];
            float ce = lse - s[tgt];
            atomicAdd(&sh_loss, ce);
            atomicAdd(&sh_hit,  (mi == tgt) ? 1.f : 0.f);
            atomicAdd(&sh_mask, (row < E_) ? 1.f : 0.f);
        }
    }
    __syncthreads();
    if (tid == 0) {
        atomicAdd(&g_acc[0], (double)sh_loss);
        atomicAdd(&g_acc[1], (double)sh_hit);
        atomicAdd(&g_acc[2], (double)sh_mask);
    }
}

// ------------------------- stop head (4 rows/block) ------------------------
__global__ void stop_kernel(const int*   __restrict__ wid,
                            const int*   __restrict__ noi,
                            const float* __restrict__ now,
                            const int*   __restrict__ bidx,
                            const int*   __restrict__ dir,
                            const int*   __restrict__ rwid,
                            const int*   __restrict__ roi,
                            const float* __restrict__ row_w,
                            const float* __restrict__ xtv,
                            const float* __restrict__ emb,
                            const float* __restrict__ ucls,
                            const float* __restrict__ ubias) {
    __shared__ float red[32];
    __shared__ float s_ce, s_hit;
    int tid = threadIdx.x;
    if (tid == 0) { s_ce = 0.f; s_hit = 0.f; }
    float u0a = ucls[tid];
    float u0b = ucls[255 + tid];
    float u1a = ucls[DS_ + tid];
    float u1b = ucls[DS_ + 255 + tid];
    float u0c = (tid > 0 && tid < L_) ? ucls[510 + tid] : 0.f;
    float u1c = (tid > 0 && tid < L_) ? ucls[DS_ + 510 + tid] : 0.f;
    float ub0 = ubias[0], ub1 = ubias[1];

    for (int rr = 0; rr < 4; rr++) {
        int row = blockIdx.x * 4 + rr;
        int widx, tgt;
        const int* oidx; const float* ow; const float* ctx;
        if (row < E_) {
            widx = wid[row]; tgt = dir[row];
            oidx = noi + row * K_; ow = now + row * K_;
            ctx = xtv + bidx[row] * L_;
        } else {
            int b = row - E_;
            widx = rwid[b]; tgt = 0;
            oidx = roi + b * K_; ow = row_w + b * K_;
            ctx = xtv + b * L_;
        }
        float wsum = 0.f, a = 0.f;
        #pragma unroll
        for (int k = 0; k < K_; k++) {
            int id = oidx[k]; float w = ow[k];
            wsum += w;
            a += w * g_hbuf[id * H_ + tid];
        }
        a /= fmaxf(wsum, 1e-8f);
        float inner = blockReduceSum((tid == 0) ? -a * a : a * a, red);
        float co = a / sqrtf(fmaxf(-inner, 1e-8f));
        float cx = emb[widx * H_ + tid];
        float d0, d1;
        if (tid == 0) {
            float t2s = fmaxf(cx * cx + co * co - 1.f, 1e-8f);
            float c0 = ctx[0];
            float x0 = sqrtf(fmaxf(t2s + c0 * c0 - 1.f, 1e-8f));
            d0 = -x0 * u0a;
            d1 = -x0 * u1a;
        } else {
            d0 = cx * u0a + co * u0b;
            d1 = cx * u1a + co * u1b;
            if (tid < L_) {
                float cv = ctx[tid];
                d0 += cv * u0c;
                d1 += cv * u1c;
            }
        }
        float sc0 = blockReduceSum(d0, red);
        float sc1 = blockReduceSum(d1, red);
        if (tid == 0) {
            sc0 = 2.f + 2.f * sc0 + ub0;
            sc1 = 2.f + 2.f * sc1 + ub1;
            float mxv = fmaxf(sc0, sc1);
            float lse = mxv + logf(expf(sc0 - mxv) + expf(sc1 - mxv));
            s_ce += lse - ((tgt == 0) ? sc0 : sc1);
            int am = (sc1 > sc0) ? 1 : 0;
            s_hit += (am == tgt) ? 1.f : 0.f;
        }
    }
    __syncthreads();
    if (tid == 0) {
        atomicAdd(&g_acc[3], (double)s_ce);
        atomicAdd(&g_acc[4], (double)s_hit);
    }
}

// ------------------------- finalize ---------------------------------------
__global__ void finalize(float* __restrict__ out) {
    out[0] = (float)(g_acc[0] / (double)B_);
    out[1] = (float)(g_acc[3] / (double)B_);
    out[2] = (float)(g_acc[1] / ((double)B_ + g_acc[2]));
    out[3] = (float)(g_acc[4] / (double)(E_ + B_));
}

// ------------------------- launch ------------------------------------------
extern "C" void kernel_launch(void* const* d_in, const int* in_sizes, int n_in,
                              void* d_out, int out_size) {
    const int*   wid   = (const int*)  d_in[0];
    const int*   nhi   = (const int*)  d_in[1];
    const float* nhw   = (const float*)d_in[2];
    const int*   noi   = (const int*)  d_in[3];
    const float* now_  = (const float*)d_in[4];
    const int*   bidx  = (const int*)  d_in[5];
    const int*   dir   = (const int*)  d_in[6];
    const int*   ptg   = (const int*)  d_in[7];
    const int*   rwid  = (const int*)  d_in[8];
    const int*   roi   = (const int*)  d_in[9];
    const float* row_w = (const float*)d_in[10];
    const float* xtv   = (const float*)d_in[11];
    const float* emb   = (const float*)d_in[12];
    const float* W0    = (const float*)d_in[13];
    const float* b0    = (const float*)d_in[14];
    const float* s0    = (const float*)d_in[15];
    const float* W1    = (const float*)d_in[16];
    const float* b1    = (const float*)d_in[17];
    const float* s1    = (const float*)d_in[18];
    const float* wcls  = (const float*)d_in[19];
    const float* wbias = (const float*)d_in[20];
    const float* ucls  = (const float*)d_in[21];
    const float* ubias = (const float*)d_in[22];
    float* out = (float*)d_out;

    const int smem_ce   = (16 * 256 + 16 * 788) * sizeof(float);  // ~66 KB
    const int smem_scan = (32768 + 16384) * sizeof(float);        // 192 KB
    cudaFuncSetAttribute(scores_ce_kernel,
                         cudaFuncAttributeMaxDynamicSharedMemorySize, smem_ce);
    cudaFuncSetAttribute(scan_kernel,
                         cudaFuncAttributeMaxDynamicSharedMemorySize, smem_scan);

    prep_misc<<<512, 256>>>(W0, W1);
    compact_rows<<<(NROWS + 255) / 256, 256>>>(dir);
    prep_pad<<<1, 256>>>(W0, b0, s0);
    prep_embW1<<<(V_ + 15) / 16, 256>>>(emb);
    scan_kernel<<<NTOT_, 512, smem_scan>>>(wid, nhi, nhw, emb, b0, s0, b1, s1,
                                           wcls, xtv);
    scores_ce_kernel<<<(NROWS + 15) / 16, 256, smem_ce>>>(wbias, bidx, ptg,
                                                          rwid, xtv);
    stop_kernel<<<NROWS / 4, 256>>>(wid, noi, now_, bidx, dir, rwid, roi, row_w,
                                    xtv, emb, ucls, ubias);
    finalize<<<1, 1>>>(out);
}

// round 16
// speedup vs baseline: 1.6074x; 1.0574x over previous
#include <cuda_runtime.h>
#include <math.h>

#define T_ 64
#define M_ 256
#define K_ 6
#define B_ 256
#define H_ 256
#define L_ 128
#define V_ 780
#define E_ 16384
#define DC_ 383          // wcls cols = H+L-1
#define DS_ 638          // ucls cols = 2H+L-2
#define NROWS (E_ + B_)  // msg rows + root rows
#define NB_ 128          // scan worker blocks (barrier count)
#define NH_ 20           // helper blocks -> total grid 148
#define NTOT_ (NB_ + NH_)

// ------------------------- device scratch --------------------------------
__device__ __align__(16) float  g_hbuf [(E_ + 1) * H_];
__device__ __align__(16) float  g_h1buf[(E_ + 1) * H_];
__device__ __align__(16) float  g_W1T  [512 * H_];      // for embW1 prep
__device__ __align__(16) float  g_W1P  [H_ * H_];       // packed: [(k>>2)*256+col]*4+(k&3)
__device__ __align__(16) float  g_W0P  [H_ * H_];       // packed W0^T
__device__ __align__(16) float  g_embW1[V_ * H_];       // emb_spatial @ W1^T_spatial
__device__ __align__(16) float  g_GtP  [256 * V_];      // packed rows 0..255
__device__ __align__(16) float  g_GtC  [128 * V_];      // packed ctx rows 256..383
__device__ __align__(16) float  g_ctxG [B_ * V_];       // ctx_spatial(b) . Gt[256..382]
__device__ int    g_rowlist[NROWS];
__device__ int    g_rowcnt;
__device__ double g_acc[6];
__device__ volatile int g_bar[T_];
__device__ volatile int g_hbar;

// ------------------------- helpers ---------------------------------------
__device__ __forceinline__ void ffma2(unsigned long long& d,
                                      unsigned long long a,
                                      unsigned long long b) {
    asm("fma.rn.f32x2 %0, %1, %2, %0;" : "+l"(d) : "l"(a), "l"(b));
}
__device__ __forceinline__ float unpack_sum(unsigned long long v) {
    float lo, hi;
    asm("mov.b64 {%0,%1}, %2;" : "=f"(lo), "=f"(hi) : "l"(v));
    return lo + hi;
}

__device__ __forceinline__ float blockReduceSum(float v, float* sh) {
    __syncthreads();
    #pragma unroll
    for (int o = 16; o > 0; o >>= 1) v += __shfl_down_sync(0xffffffffu, v, o);
    int tid = threadIdx.x;
    if ((tid & 31) == 0) sh[tid >> 5] = v;
    __syncthreads();
    if (tid < 32) {
        int nw = (blockDim.x + 31) >> 5;
        v = (tid < nw) ? sh[tid] : 0.f;
        #pragma unroll
        for (int o = 16; o > 0; o >>= 1) v += __shfl_down_sync(0xffffffffu, v, o);
        if (tid == 0) sh[0] = v;
    }
    __syncthreads();
    return sh[0];
}

__device__ __forceinline__ float gt_val(int i, int v, const float* wcls) {
    if (i == 0)  return -wcls[v * DC_];
    if (i < DC_) return wcls[v * DC_ + i];
    return 0.f;
}

// ------------------------- prep (weights only) -----------------------------
__global__ void prep_misc(const float* __restrict__ W0,
                          const float* __restrict__ W1) {
    if (blockIdx.x == 0) {
        if (threadIdx.x < T_) g_bar[threadIdx.x] = 0;
        if (threadIdx.x == 0) { g_hbar = 0; g_rowcnt = 0; }
    }
    const int n1 = 512 * H_;        // W1T
    const int n2 = H_ * H_;         // W1P
    const int n3 = H_ * H_;         // W0P
    for (int idx = blockIdx.x * blockDim.x + threadIdx.x;
         idx < n1 + n2 + n3; idx += gridDim.x * blockDim.x) {
        if (idx < n1) {
            int i = idx >> 8, j = idx & 255;
            g_W1T[idx] = (i < 511) ? W1[j * 511 + i] : 0.f;
        } else if (idx < n1 + n2) {
            int k = idx - n1;
            int i = k >> 8, j = k & 255;
            float val = (i == 0) ? W1[j * 511] : W1[j * 511 + 255 + i];
            g_W1P[((i >> 2) << 10) + (j << 2) + (i & 3)] = val;
        } else {
            int k = idx - n1 - n2;
            int i = k >> 8, j = k & 255;
            g_W0P[((i >> 2) << 10) + (j << 2) + (i & 3)] = W0[j * H_ + i];
        }
    }
}

// ---- row compaction: keep msg rows with dir==1 and all root rows ----------
__global__ void compact_rows(const int* __restrict__ dir) {
    int i = blockIdx.x * blockDim.x + threadIdx.x;
    bool keep = false;
    if (i < NROWS) keep = (i >= E_) || (dir[i] != 0);
    unsigned m = __ballot_sync(0xffffffffu, keep);
    int lane = threadIdx.x & 31;
    int base = 0;
    if (lane == 0) base = atomicAdd(&g_rowcnt, __popc(m));
    base = __shfl_sync(0xffffffffu, base, 0);
    if (keep) {
        int off = __popc(m & ((1u << lane) - 1u));
        g_rowlist[base + off] = i;
    }
}

__global__ void prep_pad(const float* __restrict__ W0,
                         const float* __restrict__ b0,
                         const float* __restrict__ s0p) {
    __shared__ float red[32];
    __shared__ float ybc;
    int tid = threadIdx.x;
    if (tid < 6) g_acc[tid] = 0.0;
    g_hbuf[E_ * H_ + tid] = (tid == 0) ? 1.f : 0.f;
    float y = W0[tid * H_] + b0[tid];
    if (tid == 0) ybc = y;
    float ss = blockReduceSum((tid == 0) ? 0.f : y * y, red);
    float time = expf(s0p[0]) / (1.f + expf(-ybc)) + 1.1f;
    float sc = sqrtf((time * time - 1.f) / fmaxf(ss, 1e-8f));
    g_h1buf[E_ * H_ + tid] = (tid == 0) ? time : y * sc;
}

// embW1[v][j] = sum_{i=1..255} emb[v][i] * W1T[i][j]
// 8 v-rows/block (grid 98), k-loop unrolled 8-wide (MLP=8).
__global__ void __launch_bounds__(256) prep_embW1(const float* __restrict__ emb) {
    __shared__ float es[8][256];
    int v0 = blockIdx.x * 8, tid = threadIdx.x;
    for (int i = tid; i < 8 * 256; i += 256) {
        int r = i >> 8, c = i & 255;
        es[r][c] = (v0 + r < V_) ? emb[(v0 + r) * H_ + c] : 0.f;
    }
    __syncthreads();
    if (tid < 8) es[tid][0] = 0.f;   // kill k=0 term (time component)
    __syncthreads();
    float acc[8];
    #pragma unroll
    for (int r = 0; r < 8; r++) acc[r] = 0.f;
    for (int ib = 0; ib < 256; ib += 8) {
        float w[8];
        #pragma unroll
        for (int u = 0; u < 8; u++) w[u] = g_W1T[(ib + u) * H_ + tid];
        #pragma unroll
        for (int u = 0; u < 8; u++) {
            #pragma unroll
            for (int r = 0; r < 8; r++) acc[r] += es[r][ib + u] * w[u];
        }
    }
    #pragma unroll
    for (int r = 0; r < 8; r++)
        if (v0 + r < V_) g_embW1[(v0 + r) * H_ + tid] = acc[r];
}

// ------------- helper-block work (runs concurrently with the scan) ---------
__device__ void helper_work(const float* __restrict__ wcls,
                            const float* __restrict__ xtv,
                            int hb, float* cs) {
    int tid = threadIdx.x;   // 512 threads
    for (int idx = hb * 512 + tid; idx < 128 * V_; idx += NH_ * 512) {
        int j = idx / V_, v = idx - j * V_;
        g_GtC[(((j >> 2) * V_ + v) << 2) + (j & 3)] = gt_val(256 + j, v, wcls);
    }
    __threadfence();
    __syncthreads();
    if (tid == 0) {
        atomicAdd((int*)&g_hbar, 1);
        while (g_hbar < NH_) __nanosleep(128);
    }
    __syncthreads();
    const float4* gc = (const float4*)g_GtC;
    for (int b = hb; b < B_; b += NH_) {
        if (tid < 128) cs[tid] = (tid < 127) ? xtv[b * L_ + 1 + tid] : 0.f;
        __syncthreads();
        const float4* cv = (const float4*)cs;
        for (int v = tid; v < V_; v += 512) {
            float acc = 0.f;
            #pragma unroll 8
            for (int j4 = 0; j4 < 32; j4++) {
                float4 g = gc[j4 * V_ + v];
                float4 c = cv[j4];
                acc += g.x * c.x + g.y * c.y + g.z * c.z + g.w * c.w;
            }
            g_ctxG[b * V_ + v] = acc;
        }
        __syncthreads();
    }
    for (int idx = hb * 512 + tid; idx < 256 * V_; idx += NH_ * 512) {
        int i = idx / V_, v = idx - i * V_;
        g_GtP[(((i >> 2) * V_ + v) << 2) + (i & 3)] = gt_val(i, v, wcls);
    }
}

// ------------------------- persistent scan kernel -------------------------
// grid = 148: blocks 0..127 scan; 128..147 helper prep.
__global__ void __launch_bounds__(512, 1) scan_kernel(
    const int*   __restrict__ wid,
    const int*   __restrict__ nhi,
    const float* __restrict__ nhw,
    const float* __restrict__ emb,
    const float* __restrict__ b0,
    const float* __restrict__ s0p,
    const float* __restrict__ b1,
    const float* __restrict__ s1p,
    const float* __restrict__ wcls,
    const float* __restrict__ xtv) {
    extern __shared__ __align__(16) float dynsm[];
    float* sW1 = dynsm;               // 32768 floats (k 0..127 of W1P)
    float* sW0 = dynsm + 32768;       // 16384 floats (k 0..63 of W0P)

    __shared__ __align__(16) float svec[2][256];
    __shared__ __align__(16) float shv [2][256];
    __shared__ float part[2][512];
    __shared__ float redA[2][8];
    __shared__ float redB[2][8];
    __shared__ float a0sh[2];
    __shared__ float ybcP[2];
    __shared__ float ybcQ[2];

    if (blockIdx.x >= NB_) {
        helper_work(wcls, xtv, blockIdx.x - NB_, &svec[0][0]);
        return;
    }

    int tid  = threadIdx.x;
    int col  = tid & 255;
    int half = tid >> 8;
    int wq   = (tid >> 5) & 7;
    int lane = tid & 31;
    int bx   = blockIdx.x;
    float e_s0 = expf(s0p[0]);
    float e_s1 = expf(s1p[0]);
    float bias1 = b1[col];
    float bias0 = b0[col];
    float w1r0 = g_W1P[col << 2];
    float w0r0 = g_W0P[col << 2];

    {
        const float4* w1g = (const float4*)g_W1P;
        const float4* w0g = (const float4*)g_W0P;
        float4* d1 = (float4*)sW1;
        float4* d0 = (float4*)sW0;
        for (int i = tid; i < 8192; i += 512) d1[i] = w1g[i];
        for (int i = tid; i < 4096; i += 512) d0[i] = w0g[i];
    }
    __syncthreads();

    int   pid[K_]; float pw[K_]; int pwid;
    {
        int e0 = bx * 2 + half;
        #pragma unroll
        for (int k = 0; k < K_; k++) { pid[k] = nhi[e0 * K_ + k]; pw[k] = nhw[e0 * K_ + k]; }
        pwid = wid[e0];
    }

    for (int t = 0; t < T_; t++) {
        int e = t * M_ + bx * 2 + half;

        float embv = g_embW1[pwid * H_ + col];
        float cx0  = emb[pwid * H_];

        // ---- phase 1: gathered midpoint (unscaled), one sync --------------
        {
            float wsum = 0.f, a = 0.f;
            #pragma unroll
            for (int k = 0; k < K_; k++) {
                wsum += pw[k];
                a += pw[k] * g_h1buf[pid[k] * H_ + col];
            }
            a /= fmaxf(wsum, 1e-8f);
            float v = (col == 0) ? a * a : -a * a;
            #pragma unroll
            for (int o = 16; o > 0; o >>= 1) v += __shfl_down_sync(0xffffffffu, v, o);
            if (lane == 0) redA[half][wq] = v;
            if (col == 0) { a0sh[half] = a; svec[half][0] = 0.f; }
            else          svec[half][col] = a;
        }
        __syncthreads();

        // ---- phase 2 GEMM: half0 smem, half1 gmem (FFMA2) ------------------
        unsigned long long acc0 = 0ull, acc1 = 0ull;
        {
            const ulonglong2* s0v = (const ulonglong2*)&svec[0][half * 128];
            const ulonglong2* s1v = (const ulonglong2*)&svec[1][half * 128];
            if (half == 0) {
                const ulonglong2* w = (const ulonglong2*)sW1 + col;
                #pragma unroll 8
                for (int i4 = 0; i4 < 32; i4++) {
                    ulonglong2 wv = w[i4 * 256];
                    ulonglong2 x0 = s0v[i4], x1 = s1v[i4];
                    ffma2(acc0, wv.x, x0.x); ffma2(acc0, wv.y, x0.y);
                    ffma2(acc1, wv.x, x1.x); ffma2(acc1, wv.y, x1.y);
                }
            } else {
                const ulonglong2* w = (const ulonglong2*)g_W1P + 32 * 256 + col;
                #pragma unroll 8
                for (int i4 = 0; i4 < 32; i4++) {
                    ulonglong2 wv = w[i4 * 256];
                    ulonglong2 x0 = s0v[i4], x1 = s1v[i4];
                    ffma2(acc0, wv.x, x0.x); ffma2(acc0, wv.y, x0.y);
                    ffma2(acc1, wv.x, x1.x); ffma2(acc1, wv.y, x1.y);
                }
            }
        }
        part[0][tid] = unpack_sum(acc0);
        part[1][tid] = unpack_sum(acc1);
        __syncthreads();

        // ---- epi2 ----------------------------------------------------------
        float y2;
        {
            float inn = 0.f;
            #pragma unroll
            for (int w8 = 0; w8 < 8; w8++) inn += redA[half][w8];
            float s = 1.0f / sqrtf(fmaxf(inn, 1e-8f));
            float a0 = a0sh[half];
            float h1m0 = a0 * s;
            float x0t = sqrtf(fmaxf(cx0 * cx0 + h1m0 * h1m0 - 1.0f, 1e-8f));
            float psum = part[half][col] + part[half][256 + col];
            y2 = s * psum + w1r0 * x0t + bias1 + embv;
            float v = (col == 0) ? 0.f : y2 * y2;
            #pragma unroll
            for (int o = 16; o > 0; o >>= 1) v += __shfl_down_sync(0xffffffffu, v, o);
            if (lane == 0) redB[half][wq] = v;
            if (col == 0) { ybcP[half] = y2; shv[half][0] = 0.f; }
            else          shv[half][col] = y2;
        }
        __syncthreads();

        // ---- phase 3 GEMM --------------------------------------------------
        unsigned long long acc2 = 0ull, acc3 = 0ull;
        {
            const ulonglong2* s0v = (const ulonglong2*)&shv[0][half * 128];
            const ulonglong2* s1v = (const ulonglong2*)&shv[1][half * 128];
            if (half == 0) {
                const ulonglong2* ws = (const ulonglong2*)sW0 + col;
                #pragma unroll 8
                for (int i4 = 0; i4 < 16; i4++) {
                    ulonglong2 wv = ws[i4 * 256];
                    ulonglong2 x0 = s0v[i4], x1 = s1v[i4];
                    ffma2(acc2, wv.x, x0.x); ffma2(acc2, wv.y, x0.y);
                    ffma2(acc3, wv.x, x1.x); ffma2(acc3, wv.y, x1.y);
                }
                const ulonglong2* wg = (const ulonglong2*)g_W0P + 16 * 256 + col;
                #pragma unroll 8
                for (int i4 = 0; i4 < 16; i4++) {
                    ulonglong2 wv = wg[i4 * 256];
                    ulonglong2 x0 = s0v[16 + i4], x1 = s1v[16 + i4];
                    ffma2(acc2, wv.x, x0.x); ffma2(acc2, wv.y, x0.y);
                    ffma2(acc3, wv.x, x1.x); ffma2(acc3, wv.y, x1.y);
                }
            } else {
                const ulonglong2* wg = (const ulonglong2*)g_W0P + 32 * 256 + col;
                #pragma unroll 8
                for (int i4 = 0; i4 < 32; i4++) {
                    ulonglong2 wv = wg[i4 * 256];
                    ulonglong2 x0 = s0v[i4], x1 = s1v[i4];
                    ffma2(acc2, wv.x, x0.x); ffma2(acc2, wv.y, x0.y);
                    ffma2(acc3, wv.x, x1.x); ffma2(acc3, wv.y, x1.y);
                }
            }
        }
        part[0][tid] = unpack_sum(acc2);
        part[1][tid] = unpack_sum(acc3);
        __syncthreads();

        // ---- epi3 ----------------------------------------------------------
        float y3;
        {
            float ss2 = 0.f;
            #pragma unroll
            for (int w8 = 0; w8 < 8; w8++) ss2 += redB[half][w8];
            float time2 = e_s1 / (1.f + expf(-ybcP[half])) + 1.1f;
            float sc2 = sqrtf((time2 * time2 - 1.f) / fmaxf(ss2, 1e-8f));
            g_hbuf[e * H_ + col] = (col == 0) ? time2 : y2 * sc2;
            float psum = part[half][col] + part[half][256 + col];
            y3 = sc2 * psum + w0r0 * time2 + bias0;
            float v = (col == 0) ? 0.f : y3 * y3;
            #pragma unroll
            for (int o = 16; o > 0; o >>= 1) v += __shfl_down_sync(0xffffffffu, v, o);
            if (lane == 0) redA[half][wq] = v;
            if (col == 0) ybcQ[half] = y3;
        }
        __syncthreads();
        {
            float ss3 = 0.f;
            #pragma unroll
            for (int w8 = 0; w8 < 8; w8++) ss3 += redA[half][w8];
            float time3 = e_s0 / (1.f + expf(-ybcQ[half])) + 1.1f;
            float sc3 = sqrtf((time3 * time3 - 1.f) / fmaxf(ss3, 1e-8f));
            g_h1buf[e * H_ + col] = (col == 0) ? time3 : y3 * sc3;
        }

        if (t + 1 < T_) {
            int en = (t + 1) * M_ + bx * 2 + half;
            #pragma unroll
            for (int k = 0; k < K_; k++) { pid[k] = nhi[en * K_ + k]; pw[k] = nhw[en * K_ + k]; }
            pwid = wid[en];
        }

        __threadfence();
        __syncthreads();
        if (tid == 0) {
            atomicAdd((int*)&g_bar[t], 1);
            while (g_bar[t] < NB_) __nanosleep(64);
        }
        __syncthreads();
    }
}

// -------- fused X-build + centroid scores GEMM + CE (compacted rows) -------
__global__ void __launch_bounds__(256) scores_ce_kernel(
    const float* __restrict__ wbias,
    const int*   __restrict__ bidx,
    const int*   __restrict__ ptg,
    const int*   __restrict__ rwid,
    const float* __restrict__ xtv) {
    extern __shared__ float dsm[];
    float* xs  = dsm;                // [16][256]
    float* scr = dsm + 16 * 256;     // [16][788]
    __shared__ int srow[16];
    __shared__ int sbid[16];
    __shared__ float sh_loss, sh_hit, sh_mask;
    int rb = blockIdx.x * 16, tid = threadIdx.x;
    int cnt = g_rowcnt;
    if (rb >= cnt) return;
    if (tid == 0) { sh_loss = 0.f; sh_hit = 0.f; sh_mask = 0.f; }
    if (tid < 16) {
        int row = (rb + tid < cnt) ? g_rowlist[rb + tid] : -1;
        srow[tid] = row;
        sbid[tid] = (row < 0) ? 0 : ((row < E_) ? bidx[row] : (row - E_));
    }
    __syncthreads();
    for (int idx = tid; idx < 16 * 256; idx += 256) {
        int row = srow[idx >> 8];
        xs[idx] = (row >= 0 && row < E_) ? g_hbuf[row * H_ + (idx & 255)] : 0.f;
    }
    __syncthreads();
    if (tid < 16) {   // fix col 0 (concat time component)
        int row = srow[tid];
        if (row >= 0) {
            float c0 = xtv[sbid[tid] * L_];
            float n0 = (row < E_) ? xs[tid * 256] : 1.f;
            xs[tid * 256] = sqrtf(fmaxf(n0 * n0 + c0 * c0 - 1.f, 1e-8f));
        }
    }
    __syncthreads();

    const ulonglong2* gp = (const ulonglong2*)g_GtP;
    for (int cc = 0; cc < 4; cc++) {
        int colv = cc * 256 + tid;
        if (colv < V_) {
            unsigned long long acc[16];
            #pragma unroll
            for (int r = 0; r < 16; r++) acc[r] = 0ull;
            #pragma unroll 4
            for (int i4 = 0; i4 < 64; i4++) {
                ulonglong2 g = gp[i4 * V_ + colv];
                #pragma unroll
                for (int r = 0; r < 16; r++) {
                    ulonglong2 xv = *(const ulonglong2*)&xs[r * 256 + i4 * 4];
                    ffma2(acc[r], g.x, xv.x);
                    ffma2(acc[r], g.y, xv.y);
                }
            }
            float bb = wbias[colv];
            #pragma unroll
            for (int r = 0; r < 16; r++) {
                float cg = g_ctxG[sbid[r] * V_ + colv];
                scr[r * 788 + colv] = 2.f + 2.f * (unpack_sum(acc[r]) + cg) + bb;
            }
        }
    }
    __syncthreads();

    int w = tid >> 5, lane = tid & 31;
    #pragma unroll
    for (int rr = 0; rr < 2; rr++) {
        int r = w * 2 + rr;
        int row = srow[r];
        if (row < 0) continue;
        const float* s = scr + r * 788;
        float mx = -1e30f; int mi = 0x7fffffff;
        for (int j = lane; j < V_; j += 32) {
            float v = s[j];
            if (v > mx) { mx = v; mi = j; }
        }
        #pragma unroll
        for (int o = 16; o > 0; o >>= 1) {
            float om = __shfl_down_sync(0xffffffffu, mx, o);
            int   oi = __shfl_down_sync(0xffffffffu, mi, o);
            if (om > mx || (om == mx && oi < mi)) { mx = om; mi = oi; }
        }
        mx = __shfl_sync(0xffffffffu, mx, 0);
        mi = __shfl_sync(0xffffffffu, mi, 0);
        float p = 0.f;
        for (int j = lane; j < V_; j += 32) p += __expf(s[j] - mx);
        #pragma unroll
        for (int o = 16; o > 0; o >>= 1) p += __shfl_down_sync(0xffffffffu, p, o);
        if (lane == 0) {
            float lse = mx + logf(p);
            int tgt = (row < E_) ? ptg[row] : rwid[row - E_];
            float ce = lse - s[tgt];
            atomicAdd(&sh_loss, ce);
            atomicAdd(&sh_hit,  (mi == tgt) ? 1.f : 0.f);
            atomicAdd(&sh_mask, (row < E_) ? 1.f : 0.f);
        }
    }
    __syncthreads();
    if (tid == 0) {
        atomicAdd(&g_acc[0], (double)sh_loss);
        atomicAdd(&g_acc[1], (double)sh_hit);
        atomicAdd(&g_acc[2], (double)sh_mask);
    }
}

// ------------------------- stop head (4 rows/block) ------------------------
__global__ void stop_kernel(const int*   __restrict__ wid,
                            const int*   __restrict__ noi,
                            const float* __restrict__ now,
                            const int*   __restrict__ bidx,
                            const int*   __restrict__ dir,
                            const int*   __restrict__ rwid,
                            const int*   __restrict__ roi,
                            const float* __restrict__ row_w,
                            const float* __restrict__ xtv,
                            const float* __restrict__ emb,
                            const float* __restrict__ ucls,
                            const float* __restrict__ ubias) {
    __shared__ float red[32];
    __shared__ float s_ce, s_hit;
    int tid = threadIdx.x;
    if (tid == 0) { s_ce = 0.f; s_hit = 0.f; }
    float u0a = ucls[tid];
    float u0b = ucls[255 + tid];
    float u1a = ucls[DS_ + tid];
    float u1b = ucls[DS_ + 255 + tid];
    float u0c = (tid > 0 && tid < L_) ? ucls[510 + tid] : 0.f;
    float u1c = (tid > 0 && tid < L_) ? ucls[DS_ + 510 + tid] : 0.f;
    float ub0 = ubias[0], ub1 = ubias[1];

    for (int rr = 0; rr < 4; rr++) {
        int row = blockIdx.x * 4 + rr;
        int widx, tgt;
        const int* oidx; const float* ow; const float* ctx;
        if (row < E_) {
            widx = wid[row]; tgt = dir[row];
            oidx = noi + row * K_; ow = now + row * K_;
            ctx = xtv + bidx[row] * L_;
        } else {
            int b = row - E_;
            widx = rwid[b]; tgt = 0;
            oidx = roi + b * K_; ow = row_w + b * K_;
            ctx = xtv + b * L_;
        }
        float wsum = 0.f, a = 0.f;
        #pragma unroll
        for (int k = 0; k < K_; k++) {
            int id = oidx[k]; float w = ow[k];
            wsum += w;
            a += w * g_hbuf[id * H_ + tid];
        }
        a /= fmaxf(wsum, 1e-8f);
        float inner = blockReduceSum((tid == 0) ? -a * a : a * a, red);
        float co = a / sqrtf(fmaxf(-inner, 1e-8f));
        float cx = emb[widx * H_ + tid];
        float d0, d1;
        if (tid == 0) {
            float t2s = fmaxf(cx * cx + co * co - 1.f, 1e-8f);
            float c0 = ctx[0];
            float x0 = sqrtf(fmaxf(t2s + c0 * c0 - 1.f, 1e-8f));
            d0 = -x0 * u0a;
            d1 = -x0 * u1a;
        } else {
            d0 = cx * u0a + co * u0b;
            d1 = cx * u1a + co * u1b;
            if (tid < L_) {
                float cv = ctx[tid];
                d0 += cv * u0c;
                d1 += cv * u1c;
            }
        }
        float sc0 = blockReduceSum(d0, red);
        float sc1 = blockReduceSum(d1, red);
        if (tid == 0) {
            sc0 = 2.f + 2.f * sc0 + ub0;
            sc1 = 2.f + 2.f * sc1 + ub1;
            float mxv = fmaxf(sc0, sc1);
            float lse = mxv + logf(expf(sc0 - mxv) + expf(sc1 - mxv));
            s_ce += lse - ((tgt == 0) ? sc0 : sc1);
            int am = (sc1 > sc0) ? 1 : 0;
            s_hit += (am == tgt) ? 1.f : 0.f;
        }
    }
    __syncthreads();
    if (tid == 0) {
        atomicAdd(&g_acc[3], (double)s_ce);
        atomicAdd(&g_acc[4], (double)s_hit);
    }
}

// ------------------------- finalize ---------------------------------------
__global__ void finalize(float* __restrict__ out) {
    out[0] = (float)(g_acc[0] / (double)B_);
    out[1] = (float)(g_acc[3] / (double)B_);
    out[2] = (float)(g_acc[1] / ((double)B_ + g_acc[2]));
    out[3] = (float)(g_acc[4] / (double)(E_ + B_));
}

// ------------------------- launch ------------------------------------------
extern "C" void kernel_launch(void* const* d_in, const int* in_sizes, int n_in,
                              void* d_out, int out_size) {
    const int*   wid   = (const int*)  d_in[0];
    const int*   nhi   = (const int*)  d_in[1];
    const float* nhw   = (const float*)d_in[2];
    const int*   noi   = (const int*)  d_in[3];
    const float* now_  = (const float*)d_in[4];
    const int*   bidx  = (const int*)  d_in[5];
    const int*   dir   = (const int*)  d_in[6];
    const int*   ptg   = (const int*)  d_in[7];
    const int*   rwid  = (const int*)  d_in[8];
    const int*   roi   = (const int*)  d_in[9];
    const float* row_w = (const float*)d_in[10];
    const float* xtv   = (const float*)d_in[11];
    const float* emb   = (const float*)d_in[12];
    const float* W0    = (const float*)d_in[13];
    const float* b0    = (const float*)d_in[14];
    const float* s0    = (const float*)d_in[15];
    const float* W1    = (const float*)d_in[16];
    const float* b1    = (const float*)d_in[17];
    const float* s1    = (const float*)d_in[18];
    const float* wcls  = (const float*)d_in[19];
    const float* wbias = (const float*)d_in[20];
    const float* ucls  = (const float*)d_in[21];
    const float* ubias = (const float*)d_in[22];
    float* out = (float*)d_out;

    const int smem_ce   = (16 * 256 + 16 * 788) * sizeof(float);  // ~66 KB
    const int smem_scan = (32768 + 16384) * sizeof(float);        // 192 KB
    cudaFuncSetAttribute(scores_ce_kernel,
                         cudaFuncAttributeMaxDynamicSharedMemorySize, smem_ce);
    cudaFuncSetAttribute(scan_kernel,
                         cudaFuncAttributeMaxDynamicSharedMemorySize, smem_scan);

    prep_misc<<<512, 256>>>(W0, W1);
    compact_rows<<<(NROWS + 255) / 256, 256>>>(dir);
    prep_pad<<<1, 256>>>(W0, b0, s0);
    prep_embW1<<<(V_ + 7) / 8, 256>>>(emb);
    scan_kernel<<<NTOT_, 512, smem_scan>>>(wid, nhi, nhw, emb, b0, s0, b1, s1,
                                           wcls, xtv);
    scores_ce_kernel<<<(NROWS + 15) / 16, 256, smem_ce>>>(wbias, bidx, ptg,
                                                          rwid, xtv);
    stop_kernel<<<NROWS / 4, 256>>>(wid, noi, now_, bidx, dir, rwid, roi, row_w,
                                    xtv, emb, ucls, ubias);
    finalize<<<1, 1>>>(out);
}

// round 17
// speedup vs baseline: 1.6344x; 1.0168x over previous
#include <cuda_runtime.h>
#include <math.h>

#define T_ 64
#define M_ 256
#define K_ 6
#define B_ 256
#define H_ 256
#define L_ 128
#define V_ 780
#define E_ 16384
#define DC_ 383          // wcls cols = H+L-1
#define DS_ 638          // ucls cols = 2H+L-2
#define NROWS (E_ + B_)  // msg rows + root rows
#define NB_ 128          // scan worker blocks (barrier count)
#define NH_ 20           // helper blocks -> total grid 148
#define NTOT_ (NB_ + NH_)

// ------------------------- device scratch --------------------------------
__device__ __align__(16) float  g_hbuf [(E_ + 1) * H_];
__device__ __align__(16) float  g_h1buf[(E_ + 1) * H_];
__device__ __align__(16) float  g_W1T  [512 * H_];      // for embW1 prep
__device__ __align__(16) float  g_W1P  [H_ * H_];       // packed: [(k>>2)*256+col]*4+(k&3)
__device__ __align__(16) float  g_W0P  [H_ * H_];       // packed W0^T
__device__ __align__(16) float  g_embW1[V_ * H_];       // emb_spatial @ W1^T_spatial
__device__ __align__(16) float  g_GtP  [256 * V_];      // packed rows 0..255
__device__ __align__(16) float  g_GtC  [128 * V_];      // packed ctx rows 256..383
__device__ __align__(16) float  g_ctxG [B_ * V_];       // ctx_spatial(b) . Gt[256..382]
__device__ int    g_rowlist[NROWS];
__device__ int    g_rowcnt;            // zero-init; reset by finalize
__device__ double g_acc[6];            // zero-init; reset by finalize
__device__ volatile int g_bar[T_];     // zero-init; reset by finalize
__device__ volatile int g_hbar;        // zero-init; reset by finalize

// ------------------------- helpers ---------------------------------------
__device__ __forceinline__ void ffma2(unsigned long long& d,
                                      unsigned long long a,
                                      unsigned long long b) {
    asm("fma.rn.f32x2 %0, %1, %2, %0;" : "+l"(d) : "l"(a), "l"(b));
}
__device__ __forceinline__ float unpack_sum(unsigned long long v) {
    float lo, hi;
    asm("mov.b64 {%0,%1}, %2;" : "=f"(lo), "=f"(hi) : "l"(v));
    return lo + hi;
}

// 256-thread reductions returning the sum to ALL threads (2 syncs each).
__device__ __forceinline__ float reduce1_256(float a, float* sh) {
    int tid = threadIdx.x, lane = tid & 31, w = tid >> 5;
    #pragma unroll
    for (int o = 16; o > 0; o >>= 1) a += __shfl_down_sync(0xffffffffu, a, o);
    __syncthreads();
    if (lane == 0) sh[w] = a;
    __syncthreads();
    float s = 0.f;
    #pragma unroll
    for (int i = 0; i < 8; i++) s += sh[i];
    return s;
}
__device__ __forceinline__ void reduce2_256(float& a, float& b,
                                            float* shA, float* shB) {
    int tid = threadIdx.x, lane = tid & 31, w = tid >> 5;
    #pragma unroll
    for (int o = 16; o > 0; o >>= 1) {
        a += __shfl_down_sync(0xffffffffu, a, o);
        b += __shfl_down_sync(0xffffffffu, b, o);
    }
    __syncthreads();
    if (lane == 0) { shA[w] = a; shB[w] = b; }
    __syncthreads();
    float sa = 0.f, sb = 0.f;
    #pragma unroll
    for (int i = 0; i < 8; i++) { sa += shA[i]; sb += shB[i]; }
    a = sa; b = sb;
}

__device__ __forceinline__ float gt_val(int i, int v, const float* wcls) {
    if (i == 0)  return -wcls[v * DC_];
    if (i < DC_) return wcls[v * DC_ + i];
    return 0.f;
}

// ------------- prep: weight tables + row compaction (fused) ----------------
__global__ void prep_misc(const float* __restrict__ W0,
                          const float* __restrict__ W1,
                          const int*   __restrict__ dir) {
    // row compaction (NROWS = 16640 is a multiple of 32; whole warps active)
    {
        int gid = blockIdx.x * blockDim.x + threadIdx.x;
        if (gid < NROWS) {
            bool keep = (gid >= E_) || (dir[gid] != 0);
            unsigned m = __ballot_sync(0xffffffffu, keep);
            int lane = threadIdx.x & 31;
            int base = 0;
            if (lane == 0) base = atomicAdd(&g_rowcnt, __popc(m));
            base = __shfl_sync(0xffffffffu, base, 0);
            if (keep) {
                int off = __popc(m & ((1u << lane) - 1u));
                g_rowlist[base + off] = gid;
            }
        }
    }
    const int n1 = 512 * H_;        // W1T
    const int n2 = H_ * H_;         // W1P
    const int n3 = H_ * H_;         // W0P
    for (int idx = blockIdx.x * blockDim.x + threadIdx.x;
         idx < n1 + n2 + n3; idx += gridDim.x * blockDim.x) {
        if (idx < n1) {
            int i = idx >> 8, j = idx & 255;
            g_W1T[idx] = (i < 511) ? W1[j * 511 + i] : 0.f;
        } else if (idx < n1 + n2) {
            int k = idx - n1;
            int i = k >> 8, j = k & 255;
            float val = (i == 0) ? W1[j * 511] : W1[j * 511 + 255 + i];
            g_W1P[((i >> 2) << 10) + (j << 2) + (i & 3)] = val;
        } else {
            int k = idx - n1 - n2;
            int i = k >> 8, j = k & 255;
            g_W0P[((i >> 2) << 10) + (j << 2) + (i & 3)] = W0[j * H_ + i];
        }
    }
}

__global__ void prep_pad(const float* __restrict__ W0,
                         const float* __restrict__ b0,
                         const float* __restrict__ s0p) {
    __shared__ float red[8];
    __shared__ float ybc;
    int tid = threadIdx.x;
    g_hbuf[E_ * H_ + tid] = (tid == 0) ? 1.f : 0.f;
    float y = W0[tid * H_] + b0[tid];
    if (tid == 0) ybc = y;
    float ss = reduce1_256((tid == 0) ? 0.f : y * y, red);
    __syncthreads();
    float time = expf(s0p[0]) / (1.f + expf(-ybc)) + 1.1f;
    float sc = sqrtf((time * time - 1.f) / fmaxf(ss, 1e-8f));
    g_h1buf[E_ * H_ + tid] = (tid == 0) ? time : y * sc;
}

// embW1[v][j] = sum_{i=1..255} emb[v][i] * W1T[i][j]
// 8 v-rows/block, 512 threads, k split across halves (MLP=8 each).
__global__ void __launch_bounds__(512) prep_embW1(const float* __restrict__ emb) {
    __shared__ float es[8][256];
    __shared__ float pp[8][512];
    int tid = threadIdx.x, col = tid & 255, half = tid >> 8;
    int v0 = blockIdx.x * 8;
    for (int i = tid; i < 8 * 256; i += 512) {
        int r = i >> 8, c = i & 255;
        es[r][c] = (v0 + r < V_) ? emb[(v0 + r) * H_ + c] : 0.f;
    }
    __syncthreads();
    if (tid < 8) es[tid][0] = 0.f;   // kill k=0 term
    __syncthreads();
    float acc[8];
    #pragma unroll
    for (int r = 0; r < 8; r++) acc[r] = 0.f;
    int kb = half * 128;
    for (int ib = 0; ib < 128; ib += 8) {
        float w[8];
        #pragma unroll
        for (int u = 0; u < 8; u++) w[u] = g_W1T[(kb + ib + u) * H_ + col];
        #pragma unroll
        for (int u = 0; u < 8; u++) {
            #pragma unroll
            for (int r = 0; r < 8; r++) acc[r] += es[r][kb + ib + u] * w[u];
        }
    }
    #pragma unroll
    for (int r = 0; r < 8; r++) pp[r][tid] = acc[r];
    __syncthreads();
    if (half == 0) {
        #pragma unroll
        for (int r = 0; r < 8; r++)
            if (v0 + r < V_)
                g_embW1[(v0 + r) * H_ + col] = pp[r][col] + pp[r][256 + col];
    }
}

// ------------- helper-block work (runs concurrently with the scan) ---------
__device__ void helper_work(const float* __restrict__ wcls,
                            const float* __restrict__ xtv,
                            int hb, float* cs) {
    int tid = threadIdx.x;   // 512 threads
    for (int idx = hb * 512 + tid; idx < 128 * V_; idx += NH_ * 512) {
        int j = idx / V_, v = idx - j * V_;
        g_GtC[(((j >> 2) * V_ + v) << 2) + (j & 3)] = gt_val(256 + j, v, wcls);
    }
    __threadfence();
    __syncthreads();
    if (tid == 0) {
        atomicAdd((int*)&g_hbar, 1);
        while (g_hbar < NH_) __nanosleep(128);
    }
    __syncthreads();
    const float4* gc = (const float4*)g_GtC;
    for (int b = hb; b < B_; b += NH_) {
        if (tid < 128) cs[tid] = (tid < 127) ? xtv[b * L_ + 1 + tid] : 0.f;
        __syncthreads();
        const float4* cv = (const float4*)cs;
        for (int v = tid; v < V_; v += 512) {
            float acc = 0.f;
            #pragma unroll 8
            for (int j4 = 0; j4 < 32; j4++) {
                float4 g = gc[j4 * V_ + v];
                float4 c = cv[j4];
                acc += g.x * c.x + g.y * c.y + g.z * c.z + g.w * c.w;
            }
            g_ctxG[b * V_ + v] = acc;
        }
        __syncthreads();
    }
    for (int idx = hb * 512 + tid; idx < 256 * V_; idx += NH_ * 512) {
        int i = idx / V_, v = idx - i * V_;
        g_GtP[(((i >> 2) * V_ + v) << 2) + (i & 3)] = gt_val(i, v, wcls);
    }
}

// ------------------------- persistent scan kernel -------------------------
// grid = 148: blocks 0..127 scan; 128..147 helper prep.
__global__ void __launch_bounds__(512, 1) scan_kernel(
    const int*   __restrict__ wid,
    const int*   __restrict__ nhi,
    const float* __restrict__ nhw,
    const float* __restrict__ emb,
    const float* __restrict__ b0,
    const float* __restrict__ s0p,
    const float* __restrict__ b1,
    const float* __restrict__ s1p,
    const float* __restrict__ wcls,
    const float* __restrict__ xtv) {
    extern __shared__ __align__(16) float dynsm[];
    float* sW1 = dynsm;               // 32768 floats (k 0..127 of W1P)
    float* sW0 = dynsm + 32768;       // 16384 floats (k 0..63 of W0P)

    __shared__ __align__(16) float svec[2][256];
    __shared__ __align__(16) float shv [2][256];
    __shared__ float part[2][512];
    __shared__ float redA[2][8];
    __shared__ float redB[2][8];
    __shared__ float a0sh[2];
    __shared__ float ybcP[2];
    __shared__ float ybcQ[2];

    if (blockIdx.x >= NB_) {
        helper_work(wcls, xtv, blockIdx.x - NB_, &svec[0][0]);
        return;
    }

    int tid  = threadIdx.x;
    int col  = tid & 255;
    int half = tid >> 8;
    int wq   = (tid >> 5) & 7;
    int lane = tid & 31;
    int bx   = blockIdx.x;
    float e_s0 = expf(s0p[0]);
    float e_s1 = expf(s1p[0]);
    float bias1 = b1[col];
    float bias0 = b0[col];
    float w1r0 = g_W1P[col << 2];
    float w0r0 = g_W0P[col << 2];

    {
        const float4* w1g = (const float4*)g_W1P;
        const float4* w0g = (const float4*)g_W0P;
        float4* d1 = (float4*)sW1;
        float4* d0 = (float4*)sW0;
        for (int i = tid; i < 8192; i += 512) d1[i] = w1g[i];
        for (int i = tid; i < 4096; i += 512) d0[i] = w0g[i];
    }
    __syncthreads();

    int   pid[K_]; float pw[K_]; int pwid;
    {
        int e0 = bx * 2 + half;
        #pragma unroll
        for (int k = 0; k < K_; k++) { pid[k] = nhi[e0 * K_ + k]; pw[k] = nhw[e0 * K_ + k]; }
        pwid = wid[e0];
    }

    for (int t = 0; t < T_; t++) {
        int e = t * M_ + bx * 2 + half;

        float embv = g_embW1[pwid * H_ + col];
        float cx0  = emb[pwid * H_];

        // ---- phase 1: gathered midpoint (unscaled), one sync --------------
        {
            float wsum = 0.f, a = 0.f;
            #pragma unroll
            for (int k = 0; k < K_; k++) {
                wsum += pw[k];
                a += pw[k] * g_h1buf[pid[k] * H_ + col];
            }
            a /= fmaxf(wsum, 1e-8f);
            float v = (col == 0) ? a * a : -a * a;
            #pragma unroll
            for (int o = 16; o > 0; o >>= 1) v += __shfl_down_sync(0xffffffffu, v, o);
            if (lane == 0) redA[half][wq] = v;
            if (col == 0) { a0sh[half] = a; svec[half][0] = 0.f; }
            else          svec[half][col] = a;
        }
        __syncthreads();

        // ---- phase 2 GEMM: half0 smem, half1 gmem (FFMA2) ------------------
        unsigned long long acc0 = 0ull, acc1 = 0ull;
        {
            const ulonglong2* s0v = (const ulonglong2*)&svec[0][half * 128];
            const ulonglong2* s1v = (const ulonglong2*)&svec[1][half * 128];
            if (half == 0) {
                const ulonglong2* w = (const ulonglong2*)sW1 + col;
                #pragma unroll 8
                for (int i4 = 0; i4 < 32; i4++) {
                    ulonglong2 wv = w[i4 * 256];
                    ulonglong2 x0 = s0v[i4], x1 = s1v[i4];
                    ffma2(acc0, wv.x, x0.x); ffma2(acc0, wv.y, x0.y);
                    ffma2(acc1, wv.x, x1.x); ffma2(acc1, wv.y, x1.y);
                }
            } else {
                const ulonglong2* w = (const ulonglong2*)g_W1P + 32 * 256 + col;
                #pragma unroll 8
                for (int i4 = 0; i4 < 32; i4++) {
                    ulonglong2 wv = w[i4 * 256];
                    ulonglong2 x0 = s0v[i4], x1 = s1v[i4];
                    ffma2(acc0, wv.x, x0.x); ffma2(acc0, wv.y, x0.y);
                    ffma2(acc1, wv.x, x1.x); ffma2(acc1, wv.y, x1.y);
                }
            }
        }
        part[0][tid] = unpack_sum(acc0);
        part[1][tid] = unpack_sum(acc1);
        __syncthreads();

        // ---- epi2 ----------------------------------------------------------
        float y2;
        {
            float inn = 0.f;
            #pragma unroll
            for (int w8 = 0; w8 < 8; w8++) inn += redA[half][w8];
            float s = 1.0f / sqrtf(fmaxf(inn, 1e-8f));
            float a0 = a0sh[half];
            float h1m0 = a0 * s;
            float x0t = sqrtf(fmaxf(cx0 * cx0 + h1m0 * h1m0 - 1.0f, 1e-8f));
            float psum = part[half][col] + part[half][256 + col];
            y2 = s * psum + w1r0 * x0t + bias1 + embv;
            float v = (col == 0) ? 0.f : y2 * y2;
            #pragma unroll
            for (int o = 16; o > 0; o >>= 1) v += __shfl_down_sync(0xffffffffu, v, o);
            if (lane == 0) redB[half][wq] = v;
            if (col == 0) { ybcP[half] = y2; shv[half][0] = 0.f; }
            else          shv[half][col] = y2;
        }
        __syncthreads();

        // ---- phase 3 GEMM --------------------------------------------------
        unsigned long long acc2 = 0ull, acc3 = 0ull;
        {
            const ulonglong2* s0v = (const ulonglong2*)&shv[0][half * 128];
            const ulonglong2* s1v = (const ulonglong2*)&shv[1][half * 128];
            if (half == 0) {
                const ulonglong2* ws = (const ulonglong2*)sW0 + col;
                #pragma unroll 8
                for (int i4 = 0; i4 < 16; i4++) {
                    ulonglong2 wv = ws[i4 * 256];
                    ulonglong2 x0 = s0v[i4], x1 = s1v[i4];
                    ffma2(acc2, wv.x, x0.x); ffma2(acc2, wv.y, x0.y);
                    ffma2(acc3, wv.x, x1.x); ffma2(acc3, wv.y, x1.y);
                }
                const ulonglong2* wg = (const ulonglong2*)g_W0P + 16 * 256 + col;
                #pragma unroll 8
                for (int i4 = 0; i4 < 16; i4++) {
                    ulonglong2 wv = wg[i4 * 256];
                    ulonglong2 x0 = s0v[16 + i4], x1 = s1v[16 + i4];
                    ffma2(acc2, wv.x, x0.x); ffma2(acc2, wv.y, x0.y);
                    ffma2(acc3, wv.x, x1.x); ffma2(acc3, wv.y, x1.y);
                }
            } else {
                const ulonglong2* wg = (const ulonglong2*)g_W0P + 32 * 256 + col;
                #pragma unroll 8
                for (int i4 = 0; i4 < 32; i4++) {
                    ulonglong2 wv = wg[i4 * 256];
                    ulonglong2 x0 = s0v[i4], x1 = s1v[i4];
                    ffma2(acc2, wv.x, x0.x); ffma2(acc2, wv.y, x0.y);
                    ffma2(acc3, wv.x, x1.x); ffma2(acc3, wv.y, x1.y);
                }
            }
        }
        part[0][tid] = unpack_sum(acc2);
        part[1][tid] = unpack_sum(acc3);
        __syncthreads();

        // ---- epi3 ----------------------------------------------------------
        float y3;
        {
            float ss2 = 0.f;
            #pragma unroll
            for (int w8 = 0; w8 < 8; w8++) ss2 += redB[half][w8];
            float time2 = e_s1 / (1.f + expf(-ybcP[half])) + 1.1f;
            float sc2 = sqrtf((time2 * time2 - 1.f) / fmaxf(ss2, 1e-8f));
            g_hbuf[e * H_ + col] = (col == 0) ? time2 : y2 * sc2;
            float psum = part[half][col] + part[half][256 + col];
            y3 = sc2 * psum + w0r0 * time2 + bias0;
            float v = (col == 0) ? 0.f : y3 * y3;
            #pragma unroll
            for (int o = 16; o > 0; o >>= 1) v += __shfl_down_sync(0xffffffffu, v, o);
            if (lane == 0) redA[half][wq] = v;
            if (col == 0) ybcQ[half] = y3;
        }
        __syncthreads();
        {
            float ss3 = 0.f;
            #pragma unroll
            for (int w8 = 0; w8 < 8; w8++) ss3 += redA[half][w8];
            float time3 = e_s0 / (1.f + expf(-ybcQ[half])) + 1.1f;
            float sc3 = sqrtf((time3 * time3 - 1.f) / fmaxf(ss3, 1e-8f));
            g_h1buf[e * H_ + col] = (col == 0) ? time3 : y3 * sc3;
        }

        if (t + 1 < T_) {
            int en = (t + 1) * M_ + bx * 2 + half;
            #pragma unroll
            for (int k = 0; k < K_; k++) { pid[k] = nhi[en * K_ + k]; pw[k] = nhw[en * K_ + k]; }
            pwid = wid[en];
        }

        __threadfence();
        __syncthreads();
        if (tid == 0) {
            atomicAdd((int*)&g_bar[t], 1);
            while (g_bar[t] < NB_) __nanosleep(64);
        }
        __syncthreads();
    }
}

// -------- fused X-build + centroid scores GEMM + CE (compacted rows) -------
__global__ void __launch_bounds__(256) scores_ce_kernel(
    const float* __restrict__ wbias,
    const int*   __restrict__ bidx,
    const int*   __restrict__ ptg,
    const int*   __restrict__ rwid,
    const float* __restrict__ xtv) {
    extern __shared__ float dsm[];
    float* xs  = dsm;                // [16][256]
    float* scr = dsm + 16 * 256;     // [16][788]
    __shared__ int srow[16];
    __shared__ int sbid[16];
    __shared__ float sh_loss, sh_hit, sh_mask;
    int rb = blockIdx.x * 16, tid = threadIdx.x;
    int cnt = g_rowcnt;
    if (rb >= cnt) return;
    if (tid == 0) { sh_loss = 0.f; sh_hit = 0.f; sh_mask = 0.f; }
    if (tid < 16) {
        int row = (rb + tid < cnt) ? g_rowlist[rb + tid] : -1;
        srow[tid] = row;
        sbid[tid] = (row < 0) ? 0 : ((row < E_) ? bidx[row] : (row - E_));
    }
    __syncthreads();
    for (int idx = tid; idx < 16 * 256; idx += 256) {
        int row = srow[idx >> 8];
        xs[idx] = (row >= 0 && row < E_) ? g_hbuf[row * H_ + (idx & 255)] : 0.f;
    }
    __syncthreads();
    if (tid < 16) {
        int row = srow[tid];
        if (row >= 0) {
            float c0 = xtv[sbid[tid] * L_];
            float n0 = (row < E_) ? xs[tid * 256] : 1.f;
            xs[tid * 256] = sqrtf(fmaxf(n0 * n0 + c0 * c0 - 1.f, 1e-8f));
        }
    }
    __syncthreads();

    const ulonglong2* gp = (const ulonglong2*)g_GtP;
    for (int cc = 0; cc < 4; cc++) {
        int colv = cc * 256 + tid;
        if (colv < V_) {
            unsigned long long acc[16];
            #pragma unroll
            for (int r = 0; r < 16; r++) acc[r] = 0ull;
            #pragma unroll 4
            for (int i4 = 0; i4 < 64; i4++) {
                ulonglong2 g = gp[i4 * V_ + colv];
                #pragma unroll
                for (int r = 0; r < 16; r++) {
                    ulonglong2 xv = *(const ulonglong2*)&xs[r * 256 + i4 * 4];
                    ffma2(acc[r], g.x, xv.x);
                    ffma2(acc[r], g.y, xv.y);
                }
            }
            float bb = wbias[colv];
            #pragma unroll
            for (int r = 0; r < 16; r++) {
                float cg = g_ctxG[sbid[r] * V_ + colv];
                scr[r * 788 + colv] = 2.f + 2.f * (unpack_sum(acc[r]) + cg) + bb;
            }
        }
    }
    __syncthreads();

    int w = tid >> 5, lane = tid & 31;
    #pragma unroll
    for (int rr = 0; rr < 2; rr++) {
        int r = w * 2 + rr;
        int row = srow[r];
        if (row < 0) continue;
        const float* s = scr + r * 788;
        float mx = -1e30f; int mi = 0x7fffffff;
        for (int j = lane; j < V_; j += 32) {
            float v = s[j];
            if (v > mx) { mx = v; mi = j; }
        }
        #pragma unroll
        for (int o = 16; o > 0; o >>= 1) {
            float om = __shfl_down_sync(0xffffffffu, mx, o);
            int   oi = __shfl_down_sync(0xffffffffu, mi, o);
            if (om > mx || (om == mx && oi < mi)) { mx = om; mi = oi; }
        }
        mx = __shfl_sync(0xffffffffu, mx, 0);
        mi = __shfl_sync(0xffffffffu, mi, 0);
        float p = 0.f;
        for (int j = lane; j < V_; j += 32) p += __expf(s[j] - mx);
        #pragma unroll
        for (int o = 16; o > 0; o >>= 1) p += __shfl_down_sync(0xffffffffu, p, o);
        if (lane == 0) {
            float lse = mx + logf(p);
            int tgt = (row < E_) ? ptg[row] : rwid[row - E_];
            float ce = lse - s[tgt];
            atomicAdd(&sh_loss, ce);
            atomicAdd(&sh_hit,  (mi == tgt) ? 1.f : 0.f);
            atomicAdd(&sh_mask, (row < E_) ? 1.f : 0.f);
        }
    }
    __syncthreads();
    if (tid == 0) {
        atomicAdd(&g_acc[0], (double)sh_loss);
        atomicAdd(&g_acc[1], (double)sh_hit);
        atomicAdd(&g_acc[2], (double)sh_mask);
    }
}

// ------------------------- stop head (8 rows/block) ------------------------
__global__ void __launch_bounds__(256) stop_kernel(
    const int*   __restrict__ wid,
    const int*   __restrict__ noi,
    const float* __restrict__ now,
    const int*   __restrict__ bidx,
    const int*   __restrict__ dir,
    const int*   __restrict__ rwid,
    const int*   __restrict__ roi,
    const float* __restrict__ row_w,
    const float* __restrict__ xtv,
    const float* __restrict__ emb,
    const float* __restrict__ ucls,
    const float* __restrict__ ubias) {
    __shared__ float redA[8];
    __shared__ float redB[8];
    int tid = threadIdx.x;
    float s_ce = 0.f, s_hit = 0.f;
    float u0a = ucls[tid];
    float u0b = ucls[255 + tid];
    float u1a = ucls[DS_ + tid];
    float u1b = ucls[DS_ + 255 + tid];
    float u0c = (tid > 0 && tid < L_) ? ucls[510 + tid] : 0.f;
    float u1c = (tid > 0 && tid < L_) ? ucls[DS_ + 510 + tid] : 0.f;
    float ub0 = ubias[0], ub1 = ubias[1];

    for (int rr = 0; rr < 8; rr++) {
        int row = blockIdx.x * 8 + rr;
        int widx, tgt;
        const int* oidx; const float* ow; const float* ctx;
        if (row < E_) {
            widx = wid[row]; tgt = dir[row];
            oidx = noi + row * K_; ow = now + row * K_;
            ctx = xtv + bidx[row] * L_;
        } else {
            int b = row - E_;
            widx = rwid[b]; tgt = 0;
            oidx = roi + b * K_; ow = row_w + b * K_;
            ctx = xtv + b * L_;
        }
        float wsum = 0.f, a = 0.f;
        #pragma unroll
        for (int k = 0; k < K_; k++) {
            int id = oidx[k]; float w = ow[k];
            wsum += w;
            a += w * g_hbuf[id * H_ + tid];
        }
        a /= fmaxf(wsum, 1e-8f);
        float inner = reduce1_256((tid == 0) ? -a * a : a * a, redA);
        float co = a / sqrtf(fmaxf(-inner, 1e-8f));
        float cx = emb[widx * H_ + tid];
        float d0, d1;
        if (tid == 0) {
            float t2s = fmaxf(cx * cx + co * co - 1.f, 1e-8f);
            float c0 = ctx[0];
            float x0 = sqrtf(fmaxf(t2s + c0 * c0 - 1.f, 1e-8f));
            d0 = -x0 * u0a;
            d1 = -x0 * u1a;
        } else {
            d0 = cx * u0a + co * u0b;
            d1 = cx * u1a + co * u1b;
            if (tid < L_) {
                float cv = ctx[tid];
                d0 += cv * u0c;
                d1 += cv * u1c;
            }
        }
        reduce2_256(d0, d1, redA, redB);
        if (tid == 0) {
            float sc0 = 2.f + 2.f * d0 + ub0;
            float sc1 = 2.f + 2.f * d1 + ub1;
            float mxv = fmaxf(sc0, sc1);
            float lse = mxv + logf(expf(sc0 - mxv) + expf(sc1 - mxv));
            s_ce += lse - ((tgt == 0) ? sc0 : sc1);
            int am = (sc1 > sc0) ? 1 : 0;
            s_hit += (am == tgt) ? 1.f : 0.f;
        }
    }
    if (tid == 0) {
        atomicAdd(&g_acc[3], (double)s_ce);
        atomicAdd(&g_acc[4], (double)s_hit);
    }
}

// ------------------------- finalize + state reset --------------------------
__global__ void finalize(float* __restrict__ out) {
    int tid = threadIdx.x;
    if (tid == 0) {
        out[0] = (float)(g_acc[0] / (double)B_);
        out[1] = (float)(g_acc[3] / (double)B_);
        out[2] = (float)(g_acc[1] / ((double)B_ + g_acc[2]));
        out[3] = (float)(g_acc[4] / (double)(E_ + B_));
        #pragma unroll
        for (int i = 0; i < 6; i++) g_acc[i] = 0.0;
        g_hbar = 0;
        g_rowcnt = 0;
    }
    if (tid < T_) g_bar[tid] = 0;
}

// ------------------------- launch ------------------------------------------
extern "C" void kernel_launch(void* const* d_in, const int* in_sizes, int n_in,
                              void* d_out, int out_size) {
    const int*   wid   = (const int*)  d_in[0];
    const int*   nhi   = (const int*)  d_in[1];
    const float* nhw   = (const float*)d_in[2];
    const int*   noi   = (const int*)  d_in[3];
    const float* now_  = (const float*)d_in[4];
    const int*   bidx  = (const int*)  d_in[5];
    const int*   dir   = (const int*)  d_in[6];
    const int*   ptg   = (const int*)  d_in[7];
    const int*   rwid  = (const int*)  d_in[8];
    const int*   roi   = (const int*)  d_in[9];
    const float* row_w = (const float*)d_in[10];
    const float* xtv   = (const float*)d_in[11];
    const float* emb   = (const float*)d_in[12];
    const float* W0    = (const float*)d_in[13];
    const float* b0    = (const float*)d_in[14];
    const float* s0    = (const float*)d_in[15];
    const float* W1    = (const float*)d_in[16];
    const float* b1    = (const float*)d_in[17];
    const float* s1    = (const float*)d_in[18];
    const float* wcls  = (const float*)d_in[19];
    const float* wbias = (const float*)d_in[20];
    const float* ucls  = (const float*)d_in[21];
    const float* ubias = (const float*)d_in[22];
    float* out = (float*)d_out;

    const int smem_ce   = (16 * 256 + 16 * 788) * sizeof(float);  // ~66 KB
    const int smem_scan = (32768 + 16384) * sizeof(float);        // 192 KB
    cudaFuncSetAttribute(scores_ce_kernel,
                         cudaFuncAttributeMaxDynamicSharedMemorySize, smem_ce);
    cudaFuncSetAttribute(scan_kernel,
                         cudaFuncAttributeMaxDynamicSharedMemorySize, smem_scan);

    prep_misc<<<512, 256>>>(W0, W1, dir);
    prep_pad<<<1, 256>>>(W0, b0, s0);
    prep_embW1<<<(V_ + 7) / 8, 512>>>(emb);
    scan_kernel<<<NTOT_, 512, smem_scan>>>(wid, nhi, nhw, emb, b0, s0, b1, s1,
                                           wcls, xtv);
    scores_ce_kernel<<<(NROWS + 15) / 16, 256, smem_ce>>>(wbias, bidx, ptg,
                                                          rwid, xtv);
    stop_kernel<<<NROWS / 8, 256>>>(wid, noi, now_, bidx, dir, rwid, roi, row_w,
                                    xtv, emb, ucls, ubias);
    finalize<<<1, 64>>>(out);
}